// round 1
// baseline (speedup 1.0000x reference)
#include <cuda_runtime.h>

#define Qn   64
#define LQ   20
#define DSET 12
#define DTn  24
#define LD   50
#define Hn   256
#define G3   768

// ---------------- device scratch (static, no allocation) ----------------
__device__ float g_gi_q[LQ * Qn * G3];   // [t][q][768]
__device__ float g_gi_c[LD * DTn * G3];  // [t][dt][768]
__device__ float g_gi_a[LD * DTn * G3];
__device__ float g_hq[2][Qn * Hn];
__device__ float g_hc[2][DTn * Hn];
__device__ float g_ha[2][DTn * Hn];
__device__ float g_attc[DTn * Hn];
__device__ float g_scores[Qn * DTn];
__device__ unsigned g_bar_t, g_bar_c, g_bar_a, g_bar_all;

// ---------------- helpers ----------------
__device__ __forceinline__ float sigm(float x) {
    return 1.0f / (1.0f + __expf(-x));
}

__device__ __forceinline__ float dot4(float4 a, float4 b, float acc) {
    acc = fmaf(a.x, b.x, acc);
    acc = fmaf(a.y, b.y, acc);
    acc = fmaf(a.z, b.z, acc);
    acc = fmaf(a.w, b.w, acc);
    return acc;
}

// Generation-counting spin barrier over a subset of blocks. Counter is
// monotonic: gen = old/n, wait for (gen+1)*n. Never reset -> safe across
// graph replays. Requires all participating blocks co-resident (grid<=148).
__device__ __forceinline__ void groupbar(unsigned* ctr, unsigned n) {
    __threadfence();          // make this thread's prior writes visible
    __syncthreads();          // all threads' writes ordered before arrive
    if (threadIdx.x == 0) {
        unsigned old = atomicAdd(ctr, 1u);
        unsigned target = (old / n + 1u) * n;
        while (*((volatile unsigned*)ctr) < target) { }
    }
    __syncthreads();
}

// ---------------- phase 0: gi = embed(tokens) @ Wih^T + bih ----------------
// mode 0: term rows r = t*64+q, tok = tokA[q*LQ+t]
// mode 1: doc  rows r = t*24+dt, tok = dt<12 ? tokA[dt*LD+t] : tokB[(dt-12)*LD+t]
__device__ void phase0_gemm(int gid, int R, int mode,
                            const int* __restrict__ tokA, const int* __restrict__ tokB,
                            const float* __restrict__ emb, const float* __restrict__ W,
                            const float* __restrict__ bias, float* __restrict__ gi,
                            float* xs)
{
    int tid = threadIdx.x;
    int rpb = (R + 31) >> 5;               // rows per block (32 blocks/group)
    int r0 = gid * rpb;
    int r1 = min(R, r0 + rpb);
    for (int rt = r0; rt < r1; rt += 8) {
        int nr = min(8, r1 - rt);
        __syncthreads();
        // stage x rows into smem
        for (int idx = tid; idx < (nr << 8); idx += 256) {
            int rl = idx >> 8, j = idx & 255;
            int r = rt + rl;
            int tok;
            if (mode == 0) {
                int t = r >> 6, q = r & 63;
                tok = tokA[q * LQ + t];
            } else {
                int t = r / DTn, dt = r - t * DTn;
                tok = (dt < DSET) ? tokA[dt * LD + t] : tokB[(dt - DSET) * LD + t];
            }
            xs[(rl << 8) + j] = __ldg(emb + (size_t)tok * Hn + j);
        }
        __syncthreads();
        for (int cc = 0; cc < 3; cc++) {
            int k = tid + (cc << 8);       // output column 0..767
            float acc[8];
            #pragma unroll
            for (int rl = 0; rl < 8; rl++) acc[rl] = 0.0f;
            const float4* wp = (const float4*)(W + (size_t)k * Hn);
            const float4* xp = (const float4*)xs;
            #pragma unroll 4
            for (int jj = 0; jj < 64; jj++) {
                float4 w4 = __ldg(wp + jj);
                #pragma unroll
                for (int rl = 0; rl < 8; rl++) {
                    float4 x4 = xp[(rl << 6) + jj];
                    acc[rl] = dot4(w4, x4, acc[rl]);
                }
            }
            float b = __ldg(bias + k);
            for (int rl = 0; rl < nr; rl++)
                gi[(size_t)(rt + rl) * G3 + k] = acc[rl] + b;
        }
    }
}

// ---------------- doc recurrence: 50 steps, 32 blocks per GRU ----------------
__device__ void run_doc(int cb, const float* __restrict__ Whh, const float* __restrict__ bhh,
                        const float* __restrict__ gi, float* hb0, float* hb1,
                        unsigned* bar, float* sm)
{
    int tid = threadIdx.x;
    float* ws = sm;            // [3][8][256]
    float* wb = sm + 6144;     // [24]
    int cbase = cb << 3;
    for (int idx = tid; idx < 6144; idx += 256) {
        int rloc = idx >> 8;                   // gate*8 + c
        int gate = rloc >> 3, cc = rloc & 7;
        ws[idx] = __ldg(Whh + (size_t)(gate * Hn + cbase + cc) * Hn + (idx & 255));
    }
    if (tid < 24)
        wb[tid] = __ldg(bhh + (tid >> 3) * Hn + cbase + (tid & 7));
    __syncthreads();

    int d = tid >> 3, c = tid & 7;
    bool act = (d < DTn);
    int jout = cbase + c;
    const float4* wrp = (const float4*)(ws + c * Hn);
    const float4* wzp = (const float4*)(ws + (8 + c) * Hn);
    const float4* wnp = (const float4*)(ws + (16 + c) * Hn);
    float br = wb[c], bz = wb[8 + c], bn = wb[16 + c];
    float* hb[2] = { hb0, hb1 };

    for (int t = 0; t < LD; t++) {
        const float* hcur = hb[t & 1];
        float* hnext = hb[(t & 1) ^ 1];
        if (act) {
            float ar = br, az = bz, an = bn;
            const float4* hp = (const float4*)(hcur + (d << 8));
            #pragma unroll 4
            for (int jj = 0; jj < 64; jj++) {
                float4 hv = __ldcg(hp + jj);     // L2, never stale L1
                ar = dot4(wrp[jj], hv, ar);
                az = dot4(wzp[jj], hv, az);
                an = dot4(wnp[jj], hv, an);
            }
            const float* gib = gi + ((size_t)t * DTn + d) * G3;
            float r = sigm(__ldg(gib + jout) + ar);
            float z = sigm(__ldg(gib + Hn + jout) + az);
            float n = tanhf(__ldg(gib + 2 * Hn + jout) + r * an);
            float hold = __ldcg(hcur + (d << 8) + jout);
            hnext[(d << 8) + jout] = (1.0f - z) * n + z * hold;
        }
        groupbar(bar, 32);
    }
}

// ---------------- term recurrence: 20 steps, 32 blocks ----------------
__device__ void run_term(int cb, const float* __restrict__ Whh, const float* __restrict__ bhh,
                         float* sm)
{
    int tid = threadIdx.x;
    float* ws = sm;
    float* wb = sm + 6144;
    int cbase = cb << 3;
    for (int idx = tid; idx < 6144; idx += 256) {
        int rloc = idx >> 8;
        int gate = rloc >> 3, cc = rloc & 7;
        ws[idx] = __ldg(Whh + (size_t)(gate * Hn + cbase + cc) * Hn + (idx & 255));
    }
    if (tid < 24)
        wb[tid] = __ldg(bhh + (tid >> 3) * Hn + cbase + (tid & 7));
    __syncthreads();

    int qp = tid >> 3, c = tid & 7;
    int jout = cbase + c;
    const float4* wrp = (const float4*)(ws + c * Hn);
    const float4* wzp = (const float4*)(ws + (8 + c) * Hn);
    const float4* wnp = (const float4*)(ws + (16 + c) * Hn);
    float br = wb[c], bz = wb[8 + c], bn = wb[16 + c];

    for (int t = 0; t < LQ; t++) {
        const float* hcur = g_hq[t & 1];
        float* hnext = g_hq[(t & 1) ^ 1];
        const float4* h0p = (const float4*)(hcur + (qp << 8));
        const float4* h1p = (const float4*)(hcur + ((qp + 32) << 8));
        float ar0 = br, az0 = bz, an0 = bn;
        float ar1 = br, az1 = bz, an1 = bn;
        #pragma unroll 4
        for (int jj = 0; jj < 64; jj++) {
            float4 h0 = __ldcg(h0p + jj);
            float4 h1 = __ldcg(h1p + jj);
            float4 w4r = wrp[jj], w4z = wzp[jj], w4n = wnp[jj];
            ar0 = dot4(w4r, h0, ar0); az0 = dot4(w4z, h0, az0); an0 = dot4(w4n, h0, an0);
            ar1 = dot4(w4r, h1, ar1); az1 = dot4(w4z, h1, az1); an1 = dot4(w4n, h1, an1);
        }
        {
            int q = qp;
            const float* gib = g_gi_q + ((size_t)t * Qn + q) * G3;
            float r = sigm(__ldg(gib + jout) + ar0);
            float z = sigm(__ldg(gib + Hn + jout) + az0);
            float n = tanhf(__ldg(gib + 2 * Hn + jout) + r * an0);
            float hold = __ldcg(hcur + (q << 8) + jout);
            hnext[(q << 8) + jout] = (1.0f - z) * n + z * hold;
        }
        {
            int q = qp + 32;
            const float* gib = g_gi_q + ((size_t)t * Qn + q) * G3;
            float r = sigm(__ldg(gib + jout) + ar1);
            float z = sigm(__ldg(gib + Hn + jout) + az1);
            float n = tanhf(__ldg(gib + 2 * Hn + jout) + r * an1);
            float hold = __ldcg(hcur + (q << 8) + jout);
            hnext[(q << 8) + jout] = (1.0f - z) * n + z * hold;
        }
        groupbar(&g_bar_t, 32);
    }
}

// ---------------- persistent kernel ----------------
__global__ void __launch_bounds__(256, 1)
fmn_kernel(const int* __restrict__ q_tok, const int* __restrict__ p_tok, const int* __restrict__ n_tok,
           const float* __restrict__ term_emb, const float* __restrict__ term_Wih,
           const float* __restrict__ term_Whh, const float* __restrict__ term_bih,
           const float* __restrict__ term_bhh,
           const float* __restrict__ doc_emb,
           const float* __restrict__ dc_Wih, const float* __restrict__ dc_Whh,
           const float* __restrict__ dc_bih, const float* __restrict__ dc_bhh,
           const float* __restrict__ da_Wih, const float* __restrict__ da_Whh,
           const float* __restrict__ da_bih, const float* __restrict__ da_bhh,
           const float* __restrict__ pos_table, const float* __restrict__ posd_W,
           const float* __restrict__ posd_b,
           const float* __restrict__ qy_Wih, const float* __restrict__ qy_Whh,
           const float* __restrict__ qy_bih, const float* __restrict__ qy_bhh,
           float* __restrict__ out)
{
    __shared__ float sm[6144 + 64];
    int bid = blockIdx.x;
    int tid = threadIdx.x;

    // ---- phase 0 + sequential recurrences (3 independent groups) ----
    if (bid < 32) {                       // doc content GRU
        if (bid == 0)
            for (int i = tid; i < DTn * Hn; i += 256) g_hc[0][i] = 0.0f;
        phase0_gemm(bid, LD * DTn, 1, p_tok, n_tok, doc_emb, dc_Wih, dc_bih, g_gi_c, sm);
        groupbar(&g_bar_c, 32);
        run_doc(bid, dc_Whh, dc_bhh, g_gi_c, g_hc[0], g_hc[1], &g_bar_c, sm);
    } else if (bid < 64) {                // doc attention GRU
        int gid = bid - 32;
        if (gid == 0)
            for (int i = tid; i < DTn * Hn; i += 256) g_ha[0][i] = 0.0f;
        phase0_gemm(gid, LD * DTn, 1, p_tok, n_tok, doc_emb, da_Wih, da_bih, g_gi_a, sm);
        groupbar(&g_bar_a, 32);
        run_doc(gid, da_Whh, da_bhh, g_gi_a, g_ha[0], g_ha[1], &g_bar_a, sm);
    } else {                              // term GRU
        int gid = bid - 64;
        if (gid == 0)
            for (int i = tid; i < Qn * Hn; i += 256) g_hq[0][i] = 0.0f;
        phase0_gemm(gid, LQ * Qn, 0, q_tok, (const int*)0, term_emb, term_Wih, term_bih, g_gi_q, sm);
        groupbar(&g_bar_t, 32);
        run_term(gid, term_Whh, term_bhh, sm);
    }

    groupbar(&g_bar_all, 96);

    // ---- phase A: position dense on content vectors (blocks 0..23) ----
    if (bid < DTn) {
        float* hrow = sm;
        hrow[tid] = __ldcg(&g_hc[0][bid * Hn + tid]);
        __syncthreads();
        int dset = bid % DSET;
        float pe0 = __ldg(&pos_table[dset * 4 + 0]);
        float pe1 = __ldg(&pos_table[dset * 4 + 1]);
        float pe2 = __ldg(&pos_table[dset * 4 + 2]);
        float pe3 = __ldg(&pos_table[dset * 4 + 3]);
        int j = tid;
        const float* wrow = posd_W + (size_t)j * (Hn + 4);
        const float4* w4p = (const float4*)wrow;
        const float4* x4p = (const float4*)hrow;
        float acc = 0.0f;
        #pragma unroll 4
        for (int ii = 0; ii < 64; ii++)
            acc = dot4(__ldg(w4p + ii), x4p[ii], acc);
        acc = fmaf(pe0, __ldg(wrow + 256), acc);
        acc = fmaf(pe1, __ldg(wrow + 257), acc);
        acc = fmaf(pe2, __ldg(wrow + 258), acc);
        acc = fmaf(pe3, __ldg(wrow + 259), acc);
        acc += __ldg(&posd_b[j]);
        g_attc[bid * Hn + j] = acc;
    } else if (bid >= 32) {
        // ---- phase B: attention scores (blocks 32..95 -> q 0..63) ----
        int q = bid - 32;
        float* eq = sm;
        eq[tid] = __ldcg(&g_hq[0][q * Hn + tid]);
        __syncthreads();
        if (tid < DTn) {
            const float4* ap = (const float4*)(g_ha[0] + tid * Hn);
            const float4* e4 = (const float4*)eq;
            float acc = 0.0f;
            #pragma unroll 4
            for (int ii = 0; ii < 64; ii++)
                acc = dot4(__ldcg(ap + ii), e4[ii], acc);
            g_scores[q * DTn + tid] = acc;
        }
    }

    groupbar(&g_bar_all, 96);

    // ---- phase C: softmax + memory read + final GRU step (blocks 0..63) ----
    if (bid < Qn) {
        int q = bid;
        float* sv = sm;         // 24 scores
        float* wv = sm + 32;    // 24 weights
        float* qs = sm + 64;    // 256 q_pos_neg row
        if (tid < DTn) sv[tid] = __ldcg(&g_scores[q * DTn + tid]);
        __syncthreads();
        if (tid < 2) {          // tid 0: pos softmax, tid 1: neg softmax
            int off = tid * DSET;
            float mx = -1e30f;
            for (int d2 = 0; d2 < DSET; d2++) mx = fmaxf(mx, sv[off + d2]);
            float s = 0.0f;
            for (int d2 = 0; d2 < DSET; d2++) {
                float e = __expf(sv[off + d2] - mx);
                wv[off + d2] = e;
                s += e;
            }
            float inv = 1.0f / s;
            for (int d2 = 0; d2 < DSET; d2++) wv[off + d2] *= inv;
        }
        __syncthreads();
        int j = tid;
        float val = __ldcg(&g_hq[0][q * Hn + j]);
        #pragma unroll
        for (int d2 = 0; d2 < DSET; d2++)
            val = fmaf(wv[d2], __ldcg(&g_attc[d2 * Hn + j]), val);
        #pragma unroll
        for (int d2 = 0; d2 < DSET; d2++)
            val = fmaf(wv[DSET + d2], __ldcg(&g_attc[(DSET + d2) * Hn + j]), val);
        qs[j] = val;
        __syncthreads();
        // final GRU step with h = 0:  out = (1-z) * n
        float dr = 0.0f, dz = 0.0f, dn = 0.0f;
        const float4* qs4 = (const float4*)qs;
        const float4* wr = (const float4*)(qy_Wih + (size_t)j * Hn);
        const float4* wz = (const float4*)(qy_Wih + (size_t)(Hn + j) * Hn);
        const float4* wn = (const float4*)(qy_Wih + (size_t)(2 * Hn + j) * Hn);
        #pragma unroll 4
        for (int ii = 0; ii < 64; ii++) {
            float4 x4 = qs4[ii];
            dr = dot4(__ldg(wr + ii), x4, dr);
            dz = dot4(__ldg(wz + ii), x4, dz);
            dn = dot4(__ldg(wn + ii), x4, dn);
        }
        float r = sigm(dr + __ldg(&qy_bih[j]) + __ldg(&qy_bhh[j]));
        float z = sigm(dz + __ldg(&qy_bih[Hn + j]) + __ldg(&qy_bhh[Hn + j]));
        float n = tanhf(dn + __ldg(&qy_bih[2 * Hn + j]) + r * __ldg(&qy_bhh[2 * Hn + j]));
        out[q * Hn + j] = (1.0f - z) * n;
    }
}

extern "C" void kernel_launch(void* const* d_in, const int* in_sizes, int n_in,
                              void* d_out, int out_size) {
    const int*   q_tok    = (const int*)d_in[0];
    const int*   p_tok    = (const int*)d_in[1];
    const int*   n_tok    = (const int*)d_in[2];
    const float* term_emb = (const float*)d_in[3];
    const float* term_Wih = (const float*)d_in[4];
    const float* term_Whh = (const float*)d_in[5];
    const float* term_bih = (const float*)d_in[6];
    const float* term_bhh = (const float*)d_in[7];
    const float* doc_emb  = (const float*)d_in[8];
    const float* dc_Wih   = (const float*)d_in[9];
    const float* dc_Whh   = (const float*)d_in[10];
    const float* dc_bih   = (const float*)d_in[11];
    const float* dc_bhh   = (const float*)d_in[12];
    const float* da_Wih   = (const float*)d_in[13];
    const float* da_Whh   = (const float*)d_in[14];
    const float* da_bih   = (const float*)d_in[15];
    const float* da_bhh   = (const float*)d_in[16];
    const float* pos_tab  = (const float*)d_in[17];
    const float* posd_W   = (const float*)d_in[18];
    const float* posd_b   = (const float*)d_in[19];
    const float* qy_Wih   = (const float*)d_in[20];
    const float* qy_Whh   = (const float*)d_in[21];
    const float* qy_bih   = (const float*)d_in[22];
    const float* qy_bhh   = (const float*)d_in[23];
    float* out = (float*)d_out;

    fmn_kernel<<<96, 256>>>(q_tok, p_tok, n_tok,
                            term_emb, term_Wih, term_Whh, term_bih, term_bhh,
                            doc_emb, dc_Wih, dc_Whh, dc_bih, dc_bhh,
                            da_Wih, da_Whh, da_bih, da_bhh,
                            pos_tab, posd_W, posd_b,
                            qy_Wih, qy_Whh, qy_bih, qy_bhh,
                            out);
}

// round 2
// speedup vs baseline: 2.5443x; 2.5443x over previous
#include <cuda_runtime.h>

typedef unsigned long long u64;

#define Qn   64
#define LQ   20
#define DSET 12
#define DTn  24
#define LD   50
#define Hn   256
#define G3   768
#define WSTR 260   // weight row stride (floats): 260 % 32 == 4 -> 8 c-lanes conflict-free
#define HSTR 264   // h row stride (floats):     264 % 32 == 8 -> 4 row-lanes conflict-free

// ---------------- device scratch ----------------
__device__ float g_gi_q[LQ * Qn * G3];
__device__ float g_gi_c[LD * DTn * G3];
__device__ float g_gi_a[LD * DTn * G3];
__device__ float g_hq[2][Qn * Hn];
__device__ float g_hc[2][DTn * Hn];
__device__ float g_ha[2][DTn * Hn];
__device__ float g_attc[DTn * Hn];
__device__ float g_scores[Qn * DTn];
__device__ unsigned g_bar_t, g_bar_c, g_bar_a, g_bar_all;

// ---------------- helpers ----------------
__device__ __forceinline__ float sigm(float x) { return 1.0f / (1.0f + __expf(-x)); }

__device__ __forceinline__ u64 pk(float lo, float hi) {
    u64 r; asm("mov.b64 %0, {%1,%2};" : "=l"(r) : "f"(lo), "f"(hi)); return r;
}
__device__ __forceinline__ float uns(u64 v) {
    float lo, hi; asm("mov.b64 {%0,%1}, %2;" : "=f"(lo), "=f"(hi) : "l"(v));
    return lo + hi;
}
__device__ __forceinline__ void ffma2(u64& d, u64 a, u64 b) {
    asm("fma.rn.f32x2 %0, %1, %2, %0;" : "+l"(d) : "l"(a), "l"(b));
}
__device__ __forceinline__ unsigned sptr(const void* p) {
    return (unsigned)__cvta_generic_to_shared(p);
}
__device__ __forceinline__ void lds2(u64& a, u64& b, unsigned addr) {
    asm volatile("ld.shared.v2.u64 {%0,%1}, [%2];" : "=l"(a), "=l"(b) : "r"(addr));
}
__device__ __forceinline__ void ldg2(u64& a, u64& b, const float* p) {
    asm volatile("ld.global.nc.v2.u64 {%0,%1}, [%2];" : "=l"(a), "=l"(b) : "l"(p));
}

// Generation-counting barrier, release/acquire (no MEMBAR.GPU).
__device__ __forceinline__ void groupbar(unsigned* ctr, unsigned n) {
    __syncthreads();
    if (threadIdx.x == 0) {
        unsigned old;
        asm volatile("atom.release.gpu.global.add.u32 %0, [%1], 1;"
                     : "=r"(old) : "l"(ctr) : "memory");
        unsigned target = (old / n + 1u) * n;
        unsigned cur;
        do {
            asm volatile("ld.acquire.gpu.global.u32 %0, [%1];"
                         : "=r"(cur) : "l"(ctr) : "memory");
        } while (cur < target);
    }
    __syncthreads();
}

// ---------------- phase 0: gi = embed(tokens) @ Wih^T + bih ----------------
__device__ void phase0_gemm(int gid, int R, int mode,
                            const int* __restrict__ tokA, const int* __restrict__ tokB,
                            const float* __restrict__ emb, const float* __restrict__ W,
                            const float* __restrict__ bias, float* __restrict__ gi,
                            float* xs)
{
    int tid = threadIdx.x;
    int rpb = (R + 31) >> 5;
    int r0 = gid * rpb;
    int r1 = min(R, r0 + rpb);
    unsigned xsa = sptr(xs);
    for (int rt = r0; rt < r1; rt += 8) {
        int nr = min(8, r1 - rt);
        __syncthreads();
        for (int idx = tid; idx < (nr << 8); idx += 256) {
            int rl = idx >> 8, j = idx & 255;
            int r = rt + rl;
            int tok;
            if (mode == 0) {
                int t = r >> 6, q = r & 63;
                tok = tokA[q * LQ + t];
            } else {
                int t = r / DTn, dt = r - t * DTn;
                tok = (dt < DSET) ? tokA[dt * LD + t] : tokB[(dt - DSET) * LD + t];
            }
            xs[(rl << 8) + j] = __ldg(emb + (size_t)tok * Hn + j);
        }
        __syncthreads();
        for (int cc = 0; cc < 3; cc++) {
            int k = tid + (cc << 8);
            float b = __ldg(bias + k);
            u64 acc[8];
            #pragma unroll
            for (int rl = 0; rl < 8; rl++) acc[rl] = pk(b, 0.0f);
            const float* wrow = W + (size_t)k * Hn;
            #pragma unroll 4
            for (int jj = 0; jj < 64; jj++) {
                u64 w01, w23;
                ldg2(w01, w23, wrow + (jj << 2));
                unsigned xo = xsa + (jj << 4);
                #pragma unroll
                for (int rl = 0; rl < 8; rl++) {
                    u64 x01, x23;
                    lds2(x01, x23, xo + (rl << 10));
                    ffma2(acc[rl], w01, x01);
                    ffma2(acc[rl], w23, x23);
                }
            }
            for (int rl = 0; rl < nr; rl++)
                gi[(size_t)(rt + rl) * G3 + k] = uns(acc[rl]);
        }
    }
}

// ---------------- doc recurrence ----------------
__device__ void run_doc(int cb, const float* __restrict__ Whh, const float* __restrict__ bhh,
                        const float* __restrict__ gi, float* hb0, float* hb1,
                        unsigned* bar, float* ws, float* hst)
{
    int tid = threadIdx.x;
    int cbase = cb << 3;
    for (int idx = tid; idx < 6144; idx += 256) {
        int rl = idx >> 8, j = idx & 255;
        int gate = rl >> 3, cc = rl & 7;
        ws[rl * WSTR + j] = __ldg(Whh + (size_t)(gate * Hn + cbase + cc) * Hn + j);
    }
    int d = tid >> 3, c = tid & 7;
    bool act = (d < DTn);
    int jout = cbase + c;
    float br = __ldg(bhh + jout), bz = __ldg(bhh + Hn + jout), bn = __ldg(bhh + 2 * Hn + jout);
    unsigned wsa = sptr(ws);
    unsigned wrA = wsa + ((unsigned)(c) * WSTR << 2);
    unsigned wzA = wsa + ((unsigned)(8 + c) * WSTR << 2);
    unsigned wnA = wsa + ((unsigned)(16 + c) * WSTR << 2);
    unsigned hA  = sptr(hst) + ((unsigned)d * HSTR << 2);
    float* hb[2] = { hb0, hb1 };

    for (int t = 0; t < LD; t++) {
        const float4* hg = (const float4*)hb[t & 1];
        float* hn_ = hb[(t & 1) ^ 1];
        #pragma unroll
        for (int i = 0; i < 6; i++) {
            int idx = tid + (i << 8);          // < 1536
            int row = idx >> 6, col = idx & 63;
            *((float4*)(hst + row * HSTR) + col) = __ldcg(hg + idx);
        }
        __syncthreads();
        if (act) {
            u64 ar = pk(br, 0.0f), az = pk(bz, 0.0f), an = pk(bn, 0.0f);
            #pragma unroll 8
            for (int jj = 0; jj < 64; jj++) {
                unsigned off = jj << 4;
                u64 h01, h23, a01, a23;
                lds2(h01, h23, hA + off);
                lds2(a01, a23, wrA + off);
                ffma2(ar, a01, h01); ffma2(ar, a23, h23);
                lds2(a01, a23, wzA + off);
                ffma2(az, a01, h01); ffma2(az, a23, h23);
                lds2(a01, a23, wnA + off);
                ffma2(an, a01, h01); ffma2(an, a23, h23);
            }
            const float* gib = gi + ((size_t)t * DTn + d) * G3;
            float r = sigm(__ldg(gib + jout) + uns(ar));
            float z = sigm(__ldg(gib + Hn + jout) + uns(az));
            float n = tanhf(__ldg(gib + 2 * Hn + jout) + r * uns(an));
            float hold = hst[d * HSTR + jout];
            hn_[(d << 8) + jout] = (1.0f - z) * n + z * hold;
        }
        groupbar(bar, 32);
    }
}

// ---------------- term recurrence ----------------
__device__ void run_term(int cb, const float* __restrict__ Whh, const float* __restrict__ bhh,
                         float* ws, float* hst)
{
    int tid = threadIdx.x;
    int cbase = cb << 3;
    for (int idx = tid; idx < 6144; idx += 256) {
        int rl = idx >> 8, j = idx & 255;
        int gate = rl >> 3, cc = rl & 7;
        ws[rl * WSTR + j] = __ldg(Whh + (size_t)(gate * Hn + cbase + cc) * Hn + j);
    }
    int qp = tid >> 3, c = tid & 7;
    int jout = cbase + c;
    float br = __ldg(bhh + jout), bz = __ldg(bhh + Hn + jout), bn = __ldg(bhh + 2 * Hn + jout);
    unsigned wsa = sptr(ws);
    unsigned wrA = wsa + ((unsigned)(c) * WSTR << 2);
    unsigned wzA = wsa + ((unsigned)(8 + c) * WSTR << 2);
    unsigned wnA = wsa + ((unsigned)(16 + c) * WSTR << 2);
    unsigned h0A = sptr(hst) + ((unsigned)qp * HSTR << 2);
    unsigned h1A = sptr(hst) + ((unsigned)(qp + 32) * HSTR << 2);

    for (int t = 0; t < LQ; t++) {
        const float4* hg = (const float4*)g_hq[t & 1];
        float* hn_ = g_hq[(t & 1) ^ 1];
        #pragma unroll
        for (int i = 0; i < 16; i++) {
            int idx = tid + (i << 8);          // < 4096
            int row = idx >> 6, col = idx & 63;
            *((float4*)(hst + row * HSTR) + col) = __ldcg(hg + idx);
        }
        __syncthreads();
        u64 ar0 = pk(br, 0.0f), az0 = pk(bz, 0.0f), an0 = pk(bn, 0.0f);
        u64 ar1 = pk(br, 0.0f), az1 = pk(bz, 0.0f), an1 = pk(bn, 0.0f);
        #pragma unroll 4
        for (int jj = 0; jj < 64; jj++) {
            unsigned off = jj << 4;
            u64 h0a, h0b, h1a, h1b, w01, w23;
            lds2(h0a, h0b, h0A + off);
            lds2(h1a, h1b, h1A + off);
            lds2(w01, w23, wrA + off);
            ffma2(ar0, w01, h0a); ffma2(ar0, w23, h0b);
            ffma2(ar1, w01, h1a); ffma2(ar1, w23, h1b);
            lds2(w01, w23, wzA + off);
            ffma2(az0, w01, h0a); ffma2(az0, w23, h0b);
            ffma2(az1, w01, h1a); ffma2(az1, w23, h1b);
            lds2(w01, w23, wnA + off);
            ffma2(an0, w01, h0a); ffma2(an0, w23, h0b);
            ffma2(an1, w01, h1a); ffma2(an1, w23, h1b);
        }
        {
            int q = qp;
            const float* gib = g_gi_q + ((size_t)t * Qn + q) * G3;
            float r = sigm(__ldg(gib + jout) + uns(ar0));
            float z = sigm(__ldg(gib + Hn + jout) + uns(az0));
            float n = tanhf(__ldg(gib + 2 * Hn + jout) + r * uns(an0));
            float hold = hst[q * HSTR + jout];
            hn_[(q << 8) + jout] = (1.0f - z) * n + z * hold;
        }
        {
            int q = qp + 32;
            const float* gib = g_gi_q + ((size_t)t * Qn + q) * G3;
            float r = sigm(__ldg(gib + jout) + uns(ar1));
            float z = sigm(__ldg(gib + Hn + jout) + uns(az1));
            float n = tanhf(__ldg(gib + 2 * Hn + jout) + r * uns(an1));
            float hold = hst[q * HSTR + jout];
            hn_[(q << 8) + jout] = (1.0f - z) * n + z * hold;
        }
        groupbar(&g_bar_t, 32);
    }
}

// ---------------- persistent kernel ----------------
__global__ void __launch_bounds__(256, 1)
fmn_kernel(const int* __restrict__ q_tok, const int* __restrict__ p_tok, const int* __restrict__ n_tok,
           const float* __restrict__ term_emb, const float* __restrict__ term_Wih,
           const float* __restrict__ term_Whh, const float* __restrict__ term_bih,
           const float* __restrict__ term_bhh,
           const float* __restrict__ doc_emb,
           const float* __restrict__ dc_Wih, const float* __restrict__ dc_Whh,
           const float* __restrict__ dc_bih, const float* __restrict__ dc_bhh,
           const float* __restrict__ da_Wih, const float* __restrict__ da_Whh,
           const float* __restrict__ da_bih, const float* __restrict__ da_bhh,
           const float* __restrict__ pos_table, const float* __restrict__ posd_W,
           const float* __restrict__ posd_b,
           const float* __restrict__ qy_Wih, const float* __restrict__ qy_Whh,
           const float* __restrict__ qy_bih, const float* __restrict__ qy_bhh,
           float* __restrict__ out)
{
    __shared__ float ws[24 * WSTR];
    extern __shared__ float dyn[];
    int bid = blockIdx.x;
    int tid = threadIdx.x;

    if (bid < 32) {                       // doc content GRU
        if (bid == 0)
            for (int i = tid; i < DTn * Hn; i += 256) g_hc[0][i] = 0.0f;
        phase0_gemm(bid, LD * DTn, 1, p_tok, n_tok, doc_emb, dc_Wih, dc_bih, g_gi_c, dyn);
        groupbar(&g_bar_c, 32);
        run_doc(bid, dc_Whh, dc_bhh, g_gi_c, g_hc[0], g_hc[1], &g_bar_c, ws, dyn);
    } else if (bid < 64) {                // doc attention GRU
        int gid = bid - 32;
        if (gid == 0)
            for (int i = tid; i < DTn * Hn; i += 256) g_ha[0][i] = 0.0f;
        phase0_gemm(gid, LD * DTn, 1, p_tok, n_tok, doc_emb, da_Wih, da_bih, g_gi_a, dyn);
        groupbar(&g_bar_a, 32);
        run_doc(gid, da_Whh, da_bhh, g_gi_a, g_ha[0], g_ha[1], &g_bar_a, ws, dyn);
    } else {                              // term GRU
        int gid = bid - 64;
        if (gid == 0)
            for (int i = tid; i < Qn * Hn; i += 256) g_hq[0][i] = 0.0f;
        phase0_gemm(gid, LQ * Qn, 0, q_tok, (const int*)0, term_emb, term_Wih, term_bih, g_gi_q, dyn);
        groupbar(&g_bar_t, 32);
        run_term(gid, term_Whh, term_bhh, ws, dyn);
    }

    groupbar(&g_bar_all, 96);

    // ---- phase A: position dense on content vectors (blocks 0..23) ----
    if (bid < DTn) {
        float* hrow = ws;
        hrow[tid] = __ldcg(&g_hc[0][bid * Hn + tid]);
        __syncthreads();
        int dset = bid % DSET;
        float pe0 = __ldg(&pos_table[dset * 4 + 0]);
        float pe1 = __ldg(&pos_table[dset * 4 + 1]);
        float pe2 = __ldg(&pos_table[dset * 4 + 2]);
        float pe3 = __ldg(&pos_table[dset * 4 + 3]);
        int j = tid;
        const float* wrow = posd_W + (size_t)j * (Hn + 4);
        unsigned xsa = sptr(hrow);
        u64 acc = pk(0.0f, 0.0f);
        #pragma unroll 4
        for (int ii = 0; ii < 64; ii++) {
            u64 w01, w23, x01, x23;
            ldg2(w01, w23, wrow + (ii << 2));
            lds2(x01, x23, xsa + (ii << 4));
            ffma2(acc, w01, x01);
            ffma2(acc, w23, x23);
        }
        float a = uns(acc);
        a = fmaf(pe0, __ldg(wrow + 256), a);
        a = fmaf(pe1, __ldg(wrow + 257), a);
        a = fmaf(pe2, __ldg(wrow + 258), a);
        a = fmaf(pe3, __ldg(wrow + 259), a);
        a += __ldg(&posd_b[j]);
        g_attc[bid * Hn + j] = a;
    } else if (bid >= 32) {
        // ---- phase B: attention scores (blocks 32..95 -> q 0..63) ----
        int q = bid - 32;
        float* eq = ws;
        eq[tid] = __ldcg(&g_hq[0][q * Hn + tid]);
        __syncthreads();
        if (tid < DTn) {
            const float4* ap = (const float4*)(g_ha[0] + tid * Hn);
            const float4* e4 = (const float4*)eq;
            float acc = 0.0f;
            #pragma unroll 4
            for (int ii = 0; ii < 64; ii++) {
                float4 a4 = __ldcg(ap + ii);
                float4 x4 = e4[ii];
                acc = fmaf(a4.x, x4.x, acc);
                acc = fmaf(a4.y, x4.y, acc);
                acc = fmaf(a4.z, x4.z, acc);
                acc = fmaf(a4.w, x4.w, acc);
            }
            g_scores[q * DTn + tid] = acc;
        }
    }

    groupbar(&g_bar_all, 96);

    // ---- phase C: softmax + memory read + final GRU step (blocks 0..63) ----
    if (bid < Qn) {
        int q = bid;
        float* sv = ws;
        float* wv = ws + 32;
        float* qs = ws + 64;
        if (tid < DTn) sv[tid] = __ldcg(&g_scores[q * DTn + tid]);
        __syncthreads();
        if (tid < 2) {
            int off = tid * DSET;
            float mx = -1e30f;
            for (int d2 = 0; d2 < DSET; d2++) mx = fmaxf(mx, sv[off + d2]);
            float s = 0.0f;
            for (int d2 = 0; d2 < DSET; d2++) {
                float e = __expf(sv[off + d2] - mx);
                wv[off + d2] = e;
                s += e;
            }
            float inv = 1.0f / s;
            for (int d2 = 0; d2 < DSET; d2++) wv[off + d2] *= inv;
        }
        __syncthreads();
        int j = tid;
        float val = __ldcg(&g_hq[0][q * Hn + j]);
        #pragma unroll
        for (int d2 = 0; d2 < DSET; d2++)
            val = fmaf(wv[d2], __ldcg(&g_attc[d2 * Hn + j]), val);
        #pragma unroll
        for (int d2 = 0; d2 < DSET; d2++)
            val = fmaf(wv[DSET + d2], __ldcg(&g_attc[(DSET + d2) * Hn + j]), val);
        qs[j] = val;
        __syncthreads();
        u64 dr = pk(0.0f, 0.0f), dz = pk(0.0f, 0.0f), dn = pk(0.0f, 0.0f);
        unsigned qsa = sptr(qs);
        const float* wr = qy_Wih + (size_t)j * Hn;
        const float* wz = qy_Wih + (size_t)(Hn + j) * Hn;
        const float* wn = qy_Wih + (size_t)(2 * Hn + j) * Hn;
        #pragma unroll 4
        for (int ii = 0; ii < 64; ii++) {
            u64 x01, x23, w01, w23;
            lds2(x01, x23, qsa + (ii << 4));
            ldg2(w01, w23, wr + (ii << 2));
            ffma2(dr, w01, x01); ffma2(dr, w23, x23);
            ldg2(w01, w23, wz + (ii << 2));
            ffma2(dz, w01, x01); ffma2(dz, w23, x23);
            ldg2(w01, w23, wn + (ii << 2));
            ffma2(dn, w01, x01); ffma2(dn, w23, x23);
        }
        float r = sigm(uns(dr) + __ldg(&qy_bih[j]) + __ldg(&qy_bhh[j]));
        float z = sigm(uns(dz) + __ldg(&qy_bih[Hn + j]) + __ldg(&qy_bhh[Hn + j]));
        float n = tanhf(uns(dn) + __ldg(&qy_bih[2 * Hn + j]) + r * __ldg(&qy_bhh[2 * Hn + j]));
        out[q * Hn + j] = (1.0f - z) * n;
    }
}

extern "C" void kernel_launch(void* const* d_in, const int* in_sizes, int n_in,
                              void* d_out, int out_size) {
    const int*   q_tok    = (const int*)d_in[0];
    const int*   p_tok    = (const int*)d_in[1];
    const int*   n_tok    = (const int*)d_in[2];
    const float* term_emb = (const float*)d_in[3];
    const float* term_Wih = (const float*)d_in[4];
    const float* term_Whh = (const float*)d_in[5];
    const float* term_bih = (const float*)d_in[6];
    const float* term_bhh = (const float*)d_in[7];
    const float* doc_emb  = (const float*)d_in[8];
    const float* dc_Wih   = (const float*)d_in[9];
    const float* dc_Whh   = (const float*)d_in[10];
    const float* dc_bih   = (const float*)d_in[11];
    const float* dc_bhh   = (const float*)d_in[12];
    const float* da_Wih   = (const float*)d_in[13];
    const float* da_Whh   = (const float*)d_in[14];
    const float* da_bih   = (const float*)d_in[15];
    const float* da_bhh   = (const float*)d_in[16];
    const float* pos_tab  = (const float*)d_in[17];
    const float* posd_W   = (const float*)d_in[18];
    const float* posd_b   = (const float*)d_in[19];
    const float* qy_Wih   = (const float*)d_in[20];
    const float* qy_Whh   = (const float*)d_in[21];
    const float* qy_bih   = (const float*)d_in[22];
    const float* qy_bhh   = (const float*)d_in[23];
    float* out = (float*)d_out;

    const int dyn_bytes = 64 * HSTR * 4;   // 67584: term h stage (doc uses 24 rows of it)
    cudaFuncSetAttribute(fmn_kernel, cudaFuncAttributeMaxDynamicSharedMemorySize, dyn_bytes);
    fmn_kernel<<<96, 256, dyn_bytes>>>(q_tok, p_tok, n_tok,
                            term_emb, term_Wih, term_Whh, term_bih, term_bhh,
                            doc_emb, dc_Wih, dc_Whh, dc_bih, dc_bhh,
                            da_Wih, da_Whh, da_bih, da_bhh,
                            pos_tab, posd_W, posd_b,
                            qy_Wih, qy_Whh, qy_bih, qy_bhh,
                            out);
}

// round 3
// speedup vs baseline: 2.5464x; 1.0008x over previous
#include <cuda_runtime.h>

typedef unsigned long long u64;

#define Qn   64
#define LQ   20
#define DSET 12
#define DTn  24
#define LD   50
#define Hn   256
#define G3   768
#define WSTR 260   // weight row stride (floats): 260 % 32 == 4 -> 8 c-lanes conflict-free
#define HSTR 264   // h row stride (floats):     264 % 32 == 8 -> 4 row-lanes conflict-free

// ---------------- device scratch ----------------
__device__ float g_gi_q[LQ * Qn * G3];
__device__ float g_gi_c[LD * DTn * G3];
__device__ float g_gi_a[LD * DTn * G3];
__device__ float g_hq[2][Qn * Hn];
__device__ float g_hc[2][DTn * Hn];
__device__ float g_ha[2][DTn * Hn];
__device__ float g_attc[DTn * Hn];
__device__ float g_scores[Qn * DTn];
__device__ unsigned g_bar_t, g_bar_c, g_bar_a, g_bar_all;

// ---------------- helpers ----------------
__device__ __forceinline__ float sigm(float x) { return 1.0f / (1.0f + __expf(-x)); }

__device__ __forceinline__ u64 pk(float lo, float hi) {
    u64 r; asm("mov.b64 %0, {%1,%2};" : "=l"(r) : "f"(lo), "f"(hi)); return r;
}
__device__ __forceinline__ float uns(u64 v) {
    float lo, hi; asm("mov.b64 {%0,%1}, %2;" : "=f"(lo), "=f"(hi) : "l"(v));
    return lo + hi;
}
__device__ __forceinline__ void ffma2(u64& d, u64 a, u64 b) {
    asm("fma.rn.f32x2 %0, %1, %2, %0;" : "+l"(d) : "l"(a), "l"(b));
}
__device__ __forceinline__ unsigned sptr(const void* p) {
    return (unsigned)__cvta_generic_to_shared(p);
}
__device__ __forceinline__ void lds2(u64& a, u64& b, unsigned addr) {
    asm volatile("ld.shared.v2.u64 {%0,%1}, [%2];" : "=l"(a), "=l"(b) : "r"(addr));
}
__device__ __forceinline__ void ldg2(u64& a, u64& b, const float* p) {
    asm volatile("ld.global.nc.v2.u64 {%0,%1}, [%2];" : "=l"(a), "=l"(b) : "l"(p));
}

// Generation-counting barrier, release/acquire (no MEMBAR.GPU).
__device__ __forceinline__ void groupbar(unsigned* ctr, unsigned n) {
    __syncthreads();
    if (threadIdx.x == 0) {
        unsigned old;
        asm volatile("atom.release.gpu.global.add.u32 %0, [%1], 1;"
                     : "=r"(old) : "l"(ctr) : "memory");
        unsigned target = (old / n + 1u) * n;
        unsigned cur;
        do {
            asm volatile("ld.acquire.gpu.global.u32 %0, [%1];"
                         : "=r"(cur) : "l"(ctr) : "memory");
        } while (cur < target);
    }
    __syncthreads();
}

// ---------------- phase 0: gi = embed(tokens) @ Wih^T + bih ----------------
__device__ void phase0_gemm(int gid, int R, int mode,
                            const int* __restrict__ tokA, const int* __restrict__ tokB,
                            const float* __restrict__ emb, const float* __restrict__ W,
                            const float* __restrict__ bias, float* __restrict__ gi,
                            float* xs)
{
    int tid = threadIdx.x;
    int rpb = (R + 31) >> 5;
    int r0 = gid * rpb;
    int r1 = min(R, r0 + rpb);
    unsigned xsa = sptr(xs);
    for (int rt = r0; rt < r1; rt += 8) {
        int nr = min(8, r1 - rt);
        __syncthreads();
        for (int idx = tid; idx < (nr << 8); idx += 256) {
            int rl = idx >> 8, j = idx & 255;
            int r = rt + rl;
            int tok;
            if (mode == 0) {
                int t = r >> 6, q = r & 63;
                tok = tokA[q * LQ + t];
            } else {
                int t = r / DTn, dt = r - t * DTn;
                tok = (dt < DSET) ? tokA[dt * LD + t] : tokB[(dt - DSET) * LD + t];
            }
            xs[(rl << 8) + j] = __ldg(emb + (size_t)tok * Hn + j);
        }
        __syncthreads();
        for (int cc = 0; cc < 3; cc++) {
            int k = tid + (cc << 8);
            float b = __ldg(bias + k);
            u64 acc[8];
            #pragma unroll
            for (int rl = 0; rl < 8; rl++) acc[rl] = pk(b, 0.0f);
            const float* wrow = W + (size_t)k * Hn;
            #pragma unroll 4
            for (int jj = 0; jj < 64; jj++) {
                u64 w01, w23;
                ldg2(w01, w23, wrow + (jj << 2));
                unsigned xo = xsa + (jj << 4);
                #pragma unroll
                for (int rl = 0; rl < 8; rl++) {
                    u64 x01, x23;
                    lds2(x01, x23, xo + (rl << 10));
                    ffma2(acc[rl], w01, x01);
                    ffma2(acc[rl], w23, x23);
                }
            }
            for (int rl = 0; rl < nr; rl++)
                gi[(size_t)(rt + rl) * G3 + k] = uns(acc[rl]);
        }
    }
}

// ---------------- doc recurrence ----------------
__device__ void run_doc(int cb, const float* __restrict__ Whh, const float* __restrict__ bhh,
                        const float* __restrict__ gi, float* hb0, float* hb1,
                        unsigned* bar, float* ws, float* hst)
{
    int tid = threadIdx.x;
    int cbase = cb << 3;
    for (int idx = tid; idx < 6144; idx += 256) {
        int rl = idx >> 8, j = idx & 255;
        int gate = rl >> 3, cc = rl & 7;
        ws[rl * WSTR + j] = __ldg(Whh + (size_t)(gate * Hn + cbase + cc) * Hn + j);
    }
    int d = tid >> 3, c = tid & 7;
    bool act = (d < DTn);
    int jout = cbase + c;
    float br = __ldg(bhh + jout), bz = __ldg(bhh + Hn + jout), bn = __ldg(bhh + 2 * Hn + jout);
    unsigned wsa = sptr(ws);
    unsigned wrA = wsa + ((unsigned)(c) * WSTR << 2);
    unsigned wzA = wsa + ((unsigned)(8 + c) * WSTR << 2);
    unsigned wnA = wsa + ((unsigned)(16 + c) * WSTR << 2);
    unsigned hA  = sptr(hst) + ((unsigned)d * HSTR << 2);
    float* hb[2] = { hb0, hb1 };

    for (int t = 0; t < LD; t++) {
        const float4* hg = (const float4*)hb[t & 1];
        float* hn_ = hb[(t & 1) ^ 1];
        #pragma unroll
        for (int i = 0; i < 6; i++) {
            int idx = tid + (i << 8);          // < 1536
            int row = idx >> 6, col = idx & 63;
            *((float4*)(hst + row * HSTR) + col) = __ldcg(hg + idx);
        }
        __syncthreads();
        if (act) {
            u64 ar = pk(br, 0.0f), az = pk(bz, 0.0f), an = pk(bn, 0.0f);
            #pragma unroll 8
            for (int jj = 0; jj < 64; jj++) {
                unsigned off = jj << 4;
                u64 h01, h23, a01, a23;
                lds2(h01, h23, hA + off);
                lds2(a01, a23, wrA + off);
                ffma2(ar, a01, h01); ffma2(ar, a23, h23);
                lds2(a01, a23, wzA + off);
                ffma2(az, a01, h01); ffma2(az, a23, h23);
                lds2(a01, a23, wnA + off);
                ffma2(an, a01, h01); ffma2(an, a23, h23);
            }
            const float* gib = gi + ((size_t)t * DTn + d) * G3;
            float r = sigm(__ldg(gib + jout) + uns(ar));
            float z = sigm(__ldg(gib + Hn + jout) + uns(az));
            float n = tanhf(__ldg(gib + 2 * Hn + jout) + r * uns(an));
            float hold = hst[d * HSTR + jout];
            hn_[(d << 8) + jout] = (1.0f - z) * n + z * hold;
        }
        groupbar(bar, 32);
    }
}

// ---------------- term recurrence ----------------
__device__ void run_term(int cb, const float* __restrict__ Whh, const float* __restrict__ bhh,
                         float* ws, float* hst)
{
    int tid = threadIdx.x;
    int cbase = cb << 3;
    for (int idx = tid; idx < 6144; idx += 256) {
        int rl = idx >> 8, j = idx & 255;
        int gate = rl >> 3, cc = rl & 7;
        ws[rl * WSTR + j] = __ldg(Whh + (size_t)(gate * Hn + cbase + cc) * Hn + j);
    }
    int qp = tid >> 3, c = tid & 7;
    int jout = cbase + c;
    float br = __ldg(bhh + jout), bz = __ldg(bhh + Hn + jout), bn = __ldg(bhh + 2 * Hn + jout);
    unsigned wsa = sptr(ws);
    unsigned wrA = wsa + ((unsigned)(c) * WSTR << 2);
    unsigned wzA = wsa + ((unsigned)(8 + c) * WSTR << 2);
    unsigned wnA = wsa + ((unsigned)(16 + c) * WSTR << 2);
    unsigned h0A = sptr(hst) + ((unsigned)qp * HSTR << 2);
    unsigned h1A = sptr(hst) + ((unsigned)(qp + 32) * HSTR << 2);

    for (int t = 0; t < LQ; t++) {
        const float4* hg = (const float4*)g_hq[t & 1];
        float* hn_ = g_hq[(t & 1) ^ 1];
        #pragma unroll
        for (int i = 0; i < 16; i++) {
            int idx = tid + (i << 8);          // < 4096
            int row = idx >> 6, col = idx & 63;
            *((float4*)(hst + row * HSTR) + col) = __ldcg(hg + idx);
        }
        __syncthreads();
        u64 ar0 = pk(br, 0.0f), az0 = pk(bz, 0.0f), an0 = pk(bn, 0.0f);
        u64 ar1 = pk(br, 0.0f), az1 = pk(bz, 0.0f), an1 = pk(bn, 0.0f);
        #pragma unroll 4
        for (int jj = 0; jj < 64; jj++) {
            unsigned off = jj << 4;
            u64 h0a, h0b, h1a, h1b, w01, w23;
            lds2(h0a, h0b, h0A + off);
            lds2(h1a, h1b, h1A + off);
            lds2(w01, w23, wrA + off);
            ffma2(ar0, w01, h0a); ffma2(ar0, w23, h0b);
            ffma2(ar1, w01, h1a); ffma2(ar1, w23, h1b);
            lds2(w01, w23, wzA + off);
            ffma2(az0, w01, h0a); ffma2(az0, w23, h0b);
            ffma2(az1, w01, h1a); ffma2(az1, w23, h1b);
            lds2(w01, w23, wnA + off);
            ffma2(an0, w01, h0a); ffma2(an0, w23, h0b);
            ffma2(an1, w01, h1a); ffma2(an1, w23, h1b);
        }
        {
            int q = qp;
            const float* gib = g_gi_q + ((size_t)t * Qn + q) * G3;
            float r = sigm(__ldg(gib + jout) + uns(ar0));
            float z = sigm(__ldg(gib + Hn + jout) + uns(az0));
            float n = tanhf(__ldg(gib + 2 * Hn + jout) + r * uns(an0));
            float hold = hst[q * HSTR + jout];
            hn_[(q << 8) + jout] = (1.0f - z) * n + z * hold;
        }
        {
            int q = qp + 32;
            const float* gib = g_gi_q + ((size_t)t * Qn + q) * G3;
            float r = sigm(__ldg(gib + jout) + uns(ar1));
            float z = sigm(__ldg(gib + Hn + jout) + uns(az1));
            float n = tanhf(__ldg(gib + 2 * Hn + jout) + r * uns(an1));
            float hold = hst[q * HSTR + jout];
            hn_[(q << 8) + jout] = (1.0f - z) * n + z * hold;
        }
        groupbar(&g_bar_t, 32);
    }
}

// ---------------- persistent kernel ----------------
__global__ void __launch_bounds__(256, 1)
fmn_kernel(const int* __restrict__ q_tok, const int* __restrict__ p_tok, const int* __restrict__ n_tok,
           const float* __restrict__ term_emb, const float* __restrict__ term_Wih,
           const float* __restrict__ term_Whh, const float* __restrict__ term_bih,
           const float* __restrict__ term_bhh,
           const float* __restrict__ doc_emb,
           const float* __restrict__ dc_Wih, const float* __restrict__ dc_Whh,
           const float* __restrict__ dc_bih, const float* __restrict__ dc_bhh,
           const float* __restrict__ da_Wih, const float* __restrict__ da_Whh,
           const float* __restrict__ da_bih, const float* __restrict__ da_bhh,
           const float* __restrict__ pos_table, const float* __restrict__ posd_W,
           const float* __restrict__ posd_b,
           const float* __restrict__ qy_Wih, const float* __restrict__ qy_Whh,
           const float* __restrict__ qy_bih, const float* __restrict__ qy_bhh,
           float* __restrict__ out)
{
    __shared__ float ws[24 * WSTR];
    extern __shared__ float dyn[];
    int bid = blockIdx.x;
    int tid = threadIdx.x;

    if (bid < 32) {                       // doc content GRU
        if (bid == 0)
            for (int i = tid; i < DTn * Hn; i += 256) g_hc[0][i] = 0.0f;
        phase0_gemm(bid, LD * DTn, 1, p_tok, n_tok, doc_emb, dc_Wih, dc_bih, g_gi_c, dyn);
        groupbar(&g_bar_c, 32);
        run_doc(bid, dc_Whh, dc_bhh, g_gi_c, g_hc[0], g_hc[1], &g_bar_c, ws, dyn);
    } else if (bid < 64) {                // doc attention GRU
        int gid = bid - 32;
        if (gid == 0)
            for (int i = tid; i < DTn * Hn; i += 256) g_ha[0][i] = 0.0f;
        phase0_gemm(gid, LD * DTn, 1, p_tok, n_tok, doc_emb, da_Wih, da_bih, g_gi_a, dyn);
        groupbar(&g_bar_a, 32);
        run_doc(gid, da_Whh, da_bhh, g_gi_a, g_ha[0], g_ha[1], &g_bar_a, ws, dyn);
    } else {                              // term GRU
        int gid = bid - 64;
        if (gid == 0)
            for (int i = tid; i < Qn * Hn; i += 256) g_hq[0][i] = 0.0f;
        phase0_gemm(gid, LQ * Qn, 0, q_tok, (const int*)0, term_emb, term_Wih, term_bih, g_gi_q, dyn);
        groupbar(&g_bar_t, 32);
        run_term(gid, term_Whh, term_bhh, ws, dyn);
    }

    groupbar(&g_bar_all, 96);

    // ---- phase A: position dense on content vectors (blocks 0..23) ----
    if (bid < DTn) {
        float* hrow = ws;
        hrow[tid] = __ldcg(&g_hc[0][bid * Hn + tid]);
        __syncthreads();
        int dset = bid % DSET;
        float pe0 = __ldg(&pos_table[dset * 4 + 0]);
        float pe1 = __ldg(&pos_table[dset * 4 + 1]);
        float pe2 = __ldg(&pos_table[dset * 4 + 2]);
        float pe3 = __ldg(&pos_table[dset * 4 + 3]);
        int j = tid;
        const float* wrow = posd_W + (size_t)j * (Hn + 4);
        unsigned xsa = sptr(hrow);
        u64 acc = pk(0.0f, 0.0f);
        #pragma unroll 4
        for (int ii = 0; ii < 64; ii++) {
            u64 w01, w23, x01, x23;
            ldg2(w01, w23, wrow + (ii << 2));
            lds2(x01, x23, xsa + (ii << 4));
            ffma2(acc, w01, x01);
            ffma2(acc, w23, x23);
        }
        float a = uns(acc);
        a = fmaf(pe0, __ldg(wrow + 256), a);
        a = fmaf(pe1, __ldg(wrow + 257), a);
        a = fmaf(pe2, __ldg(wrow + 258), a);
        a = fmaf(pe3, __ldg(wrow + 259), a);
        a += __ldg(&posd_b[j]);
        g_attc[bid * Hn + j] = a;
    } else if (bid >= 32) {
        // ---- phase B: attention scores (blocks 32..95 -> q 0..63) ----
        int q = bid - 32;
        float* eq = ws;
        eq[tid] = __ldcg(&g_hq[0][q * Hn + tid]);
        __syncthreads();
        if (tid < DTn) {
            const float4* ap = (const float4*)(g_ha[0] + tid * Hn);
            const float4* e4 = (const float4*)eq;
            float acc = 0.0f;
            #pragma unroll 4
            for (int ii = 0; ii < 64; ii++) {
                float4 a4 = __ldcg(ap + ii);
                float4 x4 = e4[ii];
                acc = fmaf(a4.x, x4.x, acc);
                acc = fmaf(a4.y, x4.y, acc);
                acc = fmaf(a4.z, x4.z, acc);
                acc = fmaf(a4.w, x4.w, acc);
            }
            g_scores[q * DTn + tid] = acc;
        }
    }

    groupbar(&g_bar_all, 96);

    // ---- phase C: softmax + memory read + final GRU step (blocks 0..63) ----
    if (bid < Qn) {
        int q = bid;
        float* sv = ws;
        float* wv = ws + 32;
        float* qs = ws + 64;
        if (tid < DTn) sv[tid] = __ldcg(&g_scores[q * DTn + tid]);
        __syncthreads();
        if (tid < 2) {
            int off = tid * DSET;
            float mx = -1e30f;
            for (int d2 = 0; d2 < DSET; d2++) mx = fmaxf(mx, sv[off + d2]);
            float s = 0.0f;
            for (int d2 = 0; d2 < DSET; d2++) {
                float e = __expf(sv[off + d2] - mx);
                wv[off + d2] = e;
                s += e;
            }
            float inv = 1.0f / s;
            for (int d2 = 0; d2 < DSET; d2++) wv[off + d2] *= inv;
        }
        __syncthreads();
        int j = tid;
        float val = __ldcg(&g_hq[0][q * Hn + j]);
        #pragma unroll
        for (int d2 = 0; d2 < DSET; d2++)
            val = fmaf(wv[d2], __ldcg(&g_attc[d2 * Hn + j]), val);
        #pragma unroll
        for (int d2 = 0; d2 < DSET; d2++)
            val = fmaf(wv[DSET + d2], __ldcg(&g_attc[(DSET + d2) * Hn + j]), val);
        qs[j] = val;
        __syncthreads();
        u64 dr = pk(0.0f, 0.0f), dz = pk(0.0f, 0.0f), dn = pk(0.0f, 0.0f);
        unsigned qsa = sptr(qs);
        const float* wr = qy_Wih + (size_t)j * Hn;
        const float* wz = qy_Wih + (size_t)(Hn + j) * Hn;
        const float* wn = qy_Wih + (size_t)(2 * Hn + j) * Hn;
        #pragma unroll 4
        for (int ii = 0; ii < 64; ii++) {
            u64 x01, x23, w01, w23;
            lds2(x01, x23, qsa + (ii << 4));
            ldg2(w01, w23, wr + (ii << 2));
            ffma2(dr, w01, x01); ffma2(dr, w23, x23);
            ldg2(w01, w23, wz + (ii << 2));
            ffma2(dz, w01, x01); ffma2(dz, w23, x23);
            ldg2(w01, w23, wn + (ii << 2));
            ffma2(dn, w01, x01); ffma2(dn, w23, x23);
        }
        float r = sigm(uns(dr) + __ldg(&qy_bih[j]) + __ldg(&qy_bhh[j]));
        float z = sigm(uns(dz) + __ldg(&qy_bih[Hn + j]) + __ldg(&qy_bhh[Hn + j]));
        float n = tanhf(uns(dn) + __ldg(&qy_bih[2 * Hn + j]) + r * __ldg(&qy_bhh[2 * Hn + j]));
        out[q * Hn + j] = (1.0f - z) * n;
    }
}

extern "C" void kernel_launch(void* const* d_in, const int* in_sizes, int n_in,
                              void* d_out, int out_size) {
    const int*   q_tok    = (const int*)d_in[0];
    const int*   p_tok    = (const int*)d_in[1];
    const int*   n_tok    = (const int*)d_in[2];
    const float* term_emb = (const float*)d_in[3];
    const float* term_Wih = (const float*)d_in[4];
    const float* term_Whh = (const float*)d_in[5];
    const float* term_bih = (const float*)d_in[6];
    const float* term_bhh = (const float*)d_in[7];
    const float* doc_emb  = (const float*)d_in[8];
    const float* dc_Wih   = (const float*)d_in[9];
    const float* dc_Whh   = (const float*)d_in[10];
    const float* dc_bih   = (const float*)d_in[11];
    const float* dc_bhh   = (const float*)d_in[12];
    const float* da_Wih   = (const float*)d_in[13];
    const float* da_Whh   = (const float*)d_in[14];
    const float* da_bih   = (const float*)d_in[15];
    const float* da_bhh   = (const float*)d_in[16];
    const float* pos_tab  = (const float*)d_in[17];
    const float* posd_W   = (const float*)d_in[18];
    const float* posd_b   = (const float*)d_in[19];
    const float* qy_Wih   = (const float*)d_in[20];
    const float* qy_Whh   = (const float*)d_in[21];
    const float* qy_bih   = (const float*)d_in[22];
    const float* qy_bhh   = (const float*)d_in[23];
    float* out = (float*)d_out;

    const int dyn_bytes = 64 * HSTR * 4;   // 67584: term h stage (doc uses 24 rows of it)
    cudaFuncSetAttribute(fmn_kernel, cudaFuncAttributeMaxDynamicSharedMemorySize, dyn_bytes);
    fmn_kernel<<<96, 256, dyn_bytes>>>(q_tok, p_tok, n_tok,
                            term_emb, term_Wih, term_Whh, term_bih, term_bhh,
                            doc_emb, dc_Wih, dc_Whh, dc_bih, dc_bhh,
                            da_Wih, da_Whh, da_bih, da_bhh,
                            pos_tab, posd_W, posd_b,
                            qy_Wih, qy_Whh, qy_bih, qy_bhh,
                            out);
}

// round 5
// speedup vs baseline: 3.0046x; 1.1799x over previous
#include <cuda_runtime.h>

typedef unsigned long long u64;

#define Qn   64
#define LQ   20
#define DSET 12
#define DTn  24
#define LD   50
#define Hn   256
#define G3   768
#define HSTR 260   // h row stride (floats): 260 % 32 == 4 -> 3-wf (minimal) h reads

// ---------------- device scratch ----------------
__device__ float g_gi_q[LQ * Qn * G3];
__device__ float g_gi_c[LD * DTn * G3];
__device__ float g_gi_a[LD * DTn * G3];
__device__ float g_hq[2][Qn * Hn];
__device__ float g_hc[2][DTn * Hn];
__device__ float g_ha[2][DTn * Hn];
__device__ float g_attc[DTn * Hn];
__device__ float g_scores[Qn * DTn];
__device__ unsigned g_bar_t, g_bar_c, g_bar_a, g_bar_all;

// ---------------- helpers ----------------
__device__ __forceinline__ float sigm(float x) { return 1.0f / (1.0f + __expf(-x)); }
__device__ __forceinline__ u64 pk(float lo, float hi) {
    u64 r; asm("mov.b64 %0, {%1,%2};" : "=l"(r) : "f"(lo), "f"(hi)); return r;
}
__device__ __forceinline__ float uns(u64 v) {
    float lo, hi; asm("mov.b64 {%0,%1}, %2;" : "=f"(lo), "=f"(hi) : "l"(v));
    return lo + hi;
}
__device__ __forceinline__ void ffma2(u64& d, u64 a, u64 b) {
    asm("fma.rn.f32x2 %0, %1, %2, %0;" : "+l"(d) : "l"(a), "l"(b));
}
__device__ __forceinline__ unsigned sptr(const void* p) {
    return (unsigned)__cvta_generic_to_shared(p);
}
__device__ __forceinline__ void lds2(u64& a, u64& b, unsigned addr) {
    asm volatile("ld.shared.v2.u64 {%0,%1}, [%2];" : "=l"(a), "=l"(b) : "r"(addr));
}
__device__ __forceinline__ void ldg2(u64& a, u64& b, const float* p) {
    asm volatile("ld.global.nc.v2.u64 {%0,%1}, [%2];" : "=l"(a), "=l"(b) : "l"(p));
}

// Generation-counting barrier, release/acquire.
__device__ __forceinline__ void groupbar(unsigned* ctr, unsigned n) {
    __syncthreads();
    if (threadIdx.x == 0) {
        unsigned old;
        asm volatile("atom.release.gpu.global.add.u32 %0, [%1], 1;"
                     : "=r"(old) : "l"(ctr) : "memory");
        unsigned target = (old / n + 1u) * n;
        unsigned cur;
        do {
            asm volatile("ld.acquire.gpu.global.u32 %0, [%1];"
                         : "=r"(cur) : "l"(ctr) : "memory");
        } while (cur < target);
    }
    __syncthreads();
}

// ---------------- phase 0: gi = embed(tokens) @ Wih^T + bih ----------------
__device__ void phase0_gemm(int gid, int R, int mode,
                            const int* __restrict__ tokA, const int* __restrict__ tokB,
                            const float* __restrict__ emb, const float* __restrict__ W,
                            const float* __restrict__ bias, float* __restrict__ gi,
                            float* xs)
{
    int tid = threadIdx.x;
    int rpb = (R + 31) >> 5;
    int r0 = gid * rpb;
    int r1 = min(R, r0 + rpb);
    unsigned xsa = sptr(xs);
    const float* wrow0 = W + (size_t)tid * Hn;
    const float* wrow1 = W + (size_t)(tid + 256) * Hn;
    const float* wrow2 = W + (size_t)(tid + 512) * Hn;
    float b0 = __ldg(bias + tid), b1 = __ldg(bias + tid + 256), b2 = __ldg(bias + tid + 512);

    for (int rt = r0; rt < r1; rt += 8) {
        int nr = min(8, r1 - rt);
        __syncthreads();
        for (int idx = tid; idx < (nr << 8); idx += 256) {
            int rl = idx >> 8, j = idx & 255;
            int r = rt + rl;
            int tok;
            if (mode == 0) {
                int t = r >> 6, q = r & 63;
                tok = tokA[q * LQ + t];
            } else {
                int t = r / DTn, dt = r - t * DTn;
                tok = (dt < DSET) ? tokA[dt * LD + t] : tokB[(dt - DSET) * LD + t];
            }
            xs[(rl << 8) + j] = __ldg(emb + (size_t)tok * Hn + j);
        }
        __syncthreads();

        u64 acc[3][8];
        #pragma unroll
        for (int rl = 0; rl < 8; rl++) {
            acc[0][rl] = pk(b0, 0.0f);
            acc[1][rl] = pk(b1, 0.0f);
            acc[2][rl] = pk(b2, 0.0f);
        }
        #pragma unroll 2
        for (int jj = 0; jj < 64; jj++) {
            u64 w0a, w0b, w1a, w1b, w2a, w2b;
            ldg2(w0a, w0b, wrow0 + (jj << 2));
            ldg2(w1a, w1b, wrow1 + (jj << 2));
            ldg2(w2a, w2b, wrow2 + (jj << 2));
            unsigned xo = xsa + (jj << 4);
            #pragma unroll
            for (int rlb = 0; rlb < 2; rlb++) {
                u64 x01[4], x23[4];
                #pragma unroll
                for (int rl = 0; rl < 4; rl++)
                    lds2(x01[rl], x23[rl], xo + ((rlb * 4 + rl) << 10));
                #pragma unroll
                for (int rl = 0; rl < 4; rl++) {
                    int ri = rlb * 4 + rl;
                    ffma2(acc[0][ri], w0a, x01[rl]); ffma2(acc[0][ri], w0b, x23[rl]);
                    ffma2(acc[1][ri], w1a, x01[rl]); ffma2(acc[1][ri], w1b, x23[rl]);
                    ffma2(acc[2][ri], w2a, x01[rl]); ffma2(acc[2][ri], w2b, x23[rl]);
                }
            }
        }
        for (int rl = 0; rl < nr; rl++) {
            float* gr = gi + (size_t)(rt + rl) * G3 + tid;
            gr[0]   = uns(acc[0][rl]);
            gr[256] = uns(acc[1][rl]);
            gr[512] = uns(acc[2][rl]);
        }
    }
}

// ---------------- doc recurrence: warp = 2 cols, lane = doc ----------------
__device__ void run_doc(int cb, const float* __restrict__ Whh, const float* __restrict__ bhh,
                        const float* __restrict__ gi, float* hb0, float* hb1,
                        unsigned* bar, float* ws, float* hst)
{
    int tid = threadIdx.x;
    int cbase = cb << 3;
    // weights: ws[gate*8 + cloc][256], compact (broadcast reads only)
    for (int idx = tid; idx < 6144; idx += 256) {
        int rl = idx >> 8, j = idx & 255;
        int gate = rl >> 3, cc = rl & 7;
        ws[idx] = __ldg(Whh + (size_t)(gate * Hn + cbase + cc) * Hn + j);
    }
    int wid = tid >> 5, lane = tid & 31;
    bool act = (wid < 4) && (lane < DTn);
    int c0 = (wid & 3) * 2, c1 = c0 + 1;
    int j0 = cbase + c0, j1 = cbase + c1;
    float br0 = __ldg(bhh + j0), bz0 = __ldg(bhh + Hn + j0), bn0 = __ldg(bhh + 2 * Hn + j0);
    float br1 = __ldg(bhh + j1), bz1 = __ldg(bhh + Hn + j1), bn1 = __ldg(bhh + 2 * Hn + j1);
    unsigned wsa = sptr(ws);
    unsigned wA[6];
    #pragma unroll
    for (int g = 0; g < 3; g++) {
        wA[g * 2 + 0] = wsa + ((g * 8 + c0) << 10);
        wA[g * 2 + 1] = wsa + ((g * 8 + c1) << 10);
    }
    unsigned hA = sptr(hst) + (unsigned)lane * (HSTR * 4);
    float* hb[2] = { hb0, hb1 };

    for (int t = 0; t < LD; t++) {
        const float4* hg = (const float4*)hb[t & 1];
        float* hn_ = hb[(t & 1) ^ 1];
        // stage h (24 rows x 256 floats = 1536 float4) into smem
        #pragma unroll
        for (int i = 0; i < 6; i++) {
            int idx = tid + (i << 8);          // < 1536
            int row = idx >> 6, col = idx & 63;
            float4 v = __ldcg(hg + idx);
            *(float4*)(hst + row * HSTR + (col << 2)) = v;
        }
        __syncthreads();
        if (act) {
            const float* gib = gi + ((size_t)t * DTn + lane) * G3;
            float g_r0 = __ldg(gib + j0), g_z0 = __ldg(gib + Hn + j0), g_n0 = __ldg(gib + 2 * Hn + j0);
            float g_r1 = __ldg(gib + j1), g_z1 = __ldg(gib + Hn + j1), g_n1 = __ldg(gib + 2 * Hn + j1);
            u64 ar0 = pk(br0, 0.f), az0 = pk(bz0, 0.f), an0 = pk(bn0, 0.f);
            u64 ar1 = pk(br1, 0.f), az1 = pk(bz1, 0.f), an1 = pk(bn1, 0.f);
            #pragma unroll 4
            for (int jj = 0; jj < 64; jj++) {
                unsigned off = jj << 4;
                u64 h01, h23, w01, w23;
                lds2(h01, h23, hA + off);
                lds2(w01, w23, wA[0] + off);
                ffma2(ar0, w01, h01); ffma2(ar0, w23, h23);
                lds2(w01, w23, wA[1] + off);
                ffma2(ar1, w01, h01); ffma2(ar1, w23, h23);
                lds2(w01, w23, wA[2] + off);
                ffma2(az0, w01, h01); ffma2(az0, w23, h23);
                lds2(w01, w23, wA[3] + off);
                ffma2(az1, w01, h01); ffma2(az1, w23, h23);
                lds2(w01, w23, wA[4] + off);
                ffma2(an0, w01, h01); ffma2(an0, w23, h23);
                lds2(w01, w23, wA[5] + off);
                ffma2(an1, w01, h01); ffma2(an1, w23, h23);
            }
            float r0 = sigm(g_r0 + uns(ar0));
            float z0 = sigm(g_z0 + uns(az0));
            float n0 = tanhf(g_n0 + r0 * uns(an0));
            float r1 = sigm(g_r1 + uns(ar1));
            float z1 = sigm(g_z1 + uns(az1));
            float n1 = tanhf(g_n1 + r1 * uns(an1));
            float ho0 = hst[lane * HSTR + j0];
            float ho1 = hst[lane * HSTR + j1];
            hn_[(lane << 8) + j0] = (1.0f - z0) * n0 + z0 * ho0;
            hn_[(lane << 8) + j1] = (1.0f - z1) * n1 + z1 * ho1;
        }
        groupbar(bar, 32);
    }
}

// ---------------- term recurrence: warp = 2 cols, lane = query (2 halves) ----------------
__device__ void run_term(int cb, const float* __restrict__ Whh, const float* __restrict__ bhh,
                         float* ws, float* hst)
{
    int tid = threadIdx.x;
    int cbase = cb << 3;
    for (int idx = tid; idx < 6144; idx += 256) {
        int rl = idx >> 8, j = idx & 255;
        int gate = rl >> 3, cc = rl & 7;
        ws[idx] = __ldg(Whh + (size_t)(gate * Hn + cbase + cc) * Hn + j);
    }
    int wid = tid >> 5, lane = tid & 31;
    bool act = (wid < 4);
    int c0 = (wid & 3) * 2, c1 = c0 + 1;
    int j0 = cbase + c0, j1 = cbase + c1;
    float br0 = __ldg(bhh + j0), bz0 = __ldg(bhh + Hn + j0), bn0 = __ldg(bhh + 2 * Hn + j0);
    float br1 = __ldg(bhh + j1), bz1 = __ldg(bhh + Hn + j1), bn1 = __ldg(bhh + 2 * Hn + j1);
    unsigned wsa = sptr(ws);
    unsigned wA[6];
    #pragma unroll
    for (int g = 0; g < 3; g++) {
        wA[g * 2 + 0] = wsa + ((g * 8 + c0) << 10);
        wA[g * 2 + 1] = wsa + ((g * 8 + c1) << 10);
    }
    unsigned h0A = sptr(hst) + (unsigned)lane * (HSTR * 4);
    unsigned h1A = sptr(hst) + (unsigned)(lane + 32) * (HSTR * 4);

    for (int t = 0; t < LQ; t++) {
        const float4* hg = (const float4*)g_hq[t & 1];
        float* hn_ = g_hq[(t & 1) ^ 1];
        #pragma unroll
        for (int i = 0; i < 16; i++) {
            int idx = tid + (i << 8);          // < 4096 float4
            int row = idx >> 6, col = idx & 63;
            float4 v = __ldcg(hg + idx);
            *(float4*)(hst + row * HSTR + (col << 2)) = v;
        }
        __syncthreads();
        if (act) {
            int q0 = lane, q1 = lane + 32;
            const float* gA = g_gi_q + ((size_t)t * Qn + q0) * G3;
            const float* gB = g_gi_q + ((size_t)t * Qn + q1) * G3;
            float gr00 = __ldg(gA + j0), gz00 = __ldg(gA + Hn + j0), gn00 = __ldg(gA + 2 * Hn + j0);
            float gr01 = __ldg(gA + j1), gz01 = __ldg(gA + Hn + j1), gn01 = __ldg(gA + 2 * Hn + j1);
            float gr10 = __ldg(gB + j0), gz10 = __ldg(gB + Hn + j0), gn10 = __ldg(gB + 2 * Hn + j0);
            float gr11 = __ldg(gB + j1), gz11 = __ldg(gB + Hn + j1), gn11 = __ldg(gB + 2 * Hn + j1);
            u64 ar00 = pk(br0, 0.f), az00 = pk(bz0, 0.f), an00 = pk(bn0, 0.f);
            u64 ar01 = pk(br1, 0.f), az01 = pk(bz1, 0.f), an01 = pk(bn1, 0.f);
            u64 ar10 = pk(br0, 0.f), az10 = pk(bz0, 0.f), an10 = pk(bn0, 0.f);
            u64 ar11 = pk(br1, 0.f), az11 = pk(bz1, 0.f), an11 = pk(bn1, 0.f);
            #pragma unroll 2
            for (int jj = 0; jj < 64; jj++) {
                unsigned off = jj << 4;
                u64 h0a, h0b, h1a, h1b, w01, w23;
                lds2(h0a, h0b, h0A + off);
                lds2(h1a, h1b, h1A + off);
                lds2(w01, w23, wA[0] + off);
                ffma2(ar00, w01, h0a); ffma2(ar00, w23, h0b);
                ffma2(ar10, w01, h1a); ffma2(ar10, w23, h1b);
                lds2(w01, w23, wA[1] + off);
                ffma2(ar01, w01, h0a); ffma2(ar01, w23, h0b);
                ffma2(ar11, w01, h1a); ffma2(ar11, w23, h1b);
                lds2(w01, w23, wA[2] + off);
                ffma2(az00, w01, h0a); ffma2(az00, w23, h0b);
                ffma2(az10, w01, h1a); ffma2(az10, w23, h1b);
                lds2(w01, w23, wA[3] + off);
                ffma2(az01, w01, h0a); ffma2(az01, w23, h0b);
                ffma2(az11, w01, h1a); ffma2(az11, w23, h1b);
                lds2(w01, w23, wA[4] + off);
                ffma2(an00, w01, h0a); ffma2(an00, w23, h0b);
                ffma2(an10, w01, h1a); ffma2(an10, w23, h1b);
                lds2(w01, w23, wA[5] + off);
                ffma2(an01, w01, h0a); ffma2(an01, w23, h0b);
                ffma2(an11, w01, h1a); ffma2(an11, w23, h1b);
            }
            float r, z, n, ho;
            r = sigm(gr00 + uns(ar00)); z = sigm(gz00 + uns(az00));
            n = tanhf(gn00 + r * uns(an00)); ho = hst[q0 * HSTR + j0];
            hn_[(q0 << 8) + j0] = (1.0f - z) * n + z * ho;
            r = sigm(gr01 + uns(ar01)); z = sigm(gz01 + uns(az01));
            n = tanhf(gn01 + r * uns(an01)); ho = hst[q0 * HSTR + j1];
            hn_[(q0 << 8) + j1] = (1.0f - z) * n + z * ho;
            r = sigm(gr10 + uns(ar10)); z = sigm(gz10 + uns(az10));
            n = tanhf(gn10 + r * uns(an10)); ho = hst[q1 * HSTR + j0];
            hn_[(q1 << 8) + j0] = (1.0f - z) * n + z * ho;
            r = sigm(gr11 + uns(ar11)); z = sigm(gz11 + uns(az11));
            n = tanhf(gn11 + r * uns(an11)); ho = hst[q1 * HSTR + j1];
            hn_[(q1 << 8) + j1] = (1.0f - z) * n + z * ho;
        }
        groupbar(&g_bar_t, 32);
    }
}

// ---------------- persistent kernel ----------------
__global__ void __launch_bounds__(256, 1)
fmn_kernel(const int* __restrict__ q_tok, const int* __restrict__ p_tok, const int* __restrict__ n_tok,
           const float* __restrict__ term_emb, const float* __restrict__ term_Wih,
           const float* __restrict__ term_Whh, const float* __restrict__ term_bih,
           const float* __restrict__ term_bhh,
           const float* __restrict__ doc_emb,
           const float* __restrict__ dc_Wih, const float* __restrict__ dc_Whh,
           const float* __restrict__ dc_bih, const float* __restrict__ dc_bhh,
           const float* __restrict__ da_Wih, const float* __restrict__ da_Whh,
           const float* __restrict__ da_bih, const float* __restrict__ da_bhh,
           const float* __restrict__ pos_table, const float* __restrict__ posd_W,
           const float* __restrict__ posd_b,
           const float* __restrict__ qy_Wih, const float* __restrict__ qy_Whh,
           const float* __restrict__ qy_bih, const float* __restrict__ qy_bhh,
           float* __restrict__ out)
{
    __shared__ float ws[24 * 256];
    extern __shared__ float dyn[];
    int bid = blockIdx.x;
    int tid = threadIdx.x;

    if (bid < 32) {                       // doc content GRU
        if (bid == 0)
            for (int i = tid; i < DTn * Hn; i += 256) g_hc[0][i] = 0.0f;
        phase0_gemm(bid, LD * DTn, 1, p_tok, n_tok, doc_emb, dc_Wih, dc_bih, g_gi_c, dyn);
        groupbar(&g_bar_c, 32);
        run_doc(bid, dc_Whh, dc_bhh, g_gi_c, g_hc[0], g_hc[1], &g_bar_c, ws, dyn);
    } else if (bid < 64) {                // doc attention GRU
        int gid = bid - 32;
        if (gid == 0)
            for (int i = tid; i < DTn * Hn; i += 256) g_ha[0][i] = 0.0f;
        phase0_gemm(gid, LD * DTn, 1, p_tok, n_tok, doc_emb, da_Wih, da_bih, g_gi_a, dyn);
        groupbar(&g_bar_a, 32);
        run_doc(gid, da_Whh, da_bhh, g_gi_a, g_ha[0], g_ha[1], &g_bar_a, ws, dyn);
    } else {                              // term GRU
        int gid = bid - 64;
        if (gid == 0)
            for (int i = tid; i < Qn * Hn; i += 256) g_hq[0][i] = 0.0f;
        phase0_gemm(gid, LQ * Qn, 0, q_tok, (const int*)0, term_emb, term_Wih, term_bih, g_gi_q, dyn);
        groupbar(&g_bar_t, 32);
        run_term(gid, term_Whh, term_bhh, ws, dyn);
    }

    groupbar(&g_bar_all, 96);

    // ---- phase A: position dense on content vectors (blocks 0..23) ----
    if (bid < DTn) {
        float* hrow = ws;
        hrow[tid] = __ldcg(&g_hc[0][bid * Hn + tid]);
        __syncthreads();
        int dset = bid % DSET;
        float pe0 = __ldg(&pos_table[dset * 4 + 0]);
        float pe1 = __ldg(&pos_table[dset * 4 + 1]);
        float pe2 = __ldg(&pos_table[dset * 4 + 2]);
        float pe3 = __ldg(&pos_table[dset * 4 + 3]);
        int j = tid;
        const float* wrow = posd_W + (size_t)j * (Hn + 4);
        unsigned xsa = sptr(hrow);
        u64 acc = pk(0.0f, 0.0f);
        #pragma unroll 4
        for (int ii = 0; ii < 64; ii++) {
            u64 w01, w23, x01, x23;
            ldg2(w01, w23, wrow + (ii << 2));
            lds2(x01, x23, xsa + (ii << 4));
            ffma2(acc, w01, x01);
            ffma2(acc, w23, x23);
        }
        float a = uns(acc);
        a = fmaf(pe0, __ldg(wrow + 256), a);
        a = fmaf(pe1, __ldg(wrow + 257), a);
        a = fmaf(pe2, __ldg(wrow + 258), a);
        a = fmaf(pe3, __ldg(wrow + 259), a);
        a += __ldg(&posd_b[j]);
        g_attc[bid * Hn + j] = a;
    } else if (bid >= 32) {
        // ---- phase B: attention scores (blocks 32..95 -> q 0..63) ----
        int q = bid - 32;
        float* eq = ws;
        eq[tid] = __ldcg(&g_hq[0][q * Hn + tid]);
        __syncthreads();
        if (tid < DTn) {
            const float4* ap = (const float4*)(g_ha[0] + tid * Hn);
            const float4* e4 = (const float4*)eq;
            float acc = 0.0f;
            #pragma unroll 4
            for (int ii = 0; ii < 64; ii++) {
                float4 a4 = __ldcg(ap + ii);
                float4 x4 = e4[ii];
                acc = fmaf(a4.x, x4.x, acc);
                acc = fmaf(a4.y, x4.y, acc);
                acc = fmaf(a4.z, x4.z, acc);
                acc = fmaf(a4.w, x4.w, acc);
            }
            g_scores[q * DTn + tid] = acc;
        }
    }

    groupbar(&g_bar_all, 96);

    // ---- phase C: softmax + memory read + final GRU step (blocks 0..63) ----
    if (bid < Qn) {
        int q = bid;
        float* sv = ws;
        float* wv = ws + 32;
        float* qs = ws + 64;
        if (tid < DTn) sv[tid] = __ldcg(&g_scores[q * DTn + tid]);
        __syncthreads();
        if (tid < 2) {
            int off = tid * DSET;
            float mx = -1e30f;
            for (int d2 = 0; d2 < DSET; d2++) mx = fmaxf(mx, sv[off + d2]);
            float s = 0.0f;
            for (int d2 = 0; d2 < DSET; d2++) {
                float e = __expf(sv[off + d2] - mx);
                wv[off + d2] = e;
                s += e;
            }
            float inv = 1.0f / s;
            for (int d2 = 0; d2 < DSET; d2++) wv[off + d2] *= inv;
        }
        __syncthreads();
        int j = tid;
        float val = __ldcg(&g_hq[0][q * Hn + j]);
        #pragma unroll
        for (int d2 = 0; d2 < DSET; d2++)
            val = fmaf(wv[d2], __ldcg(&g_attc[d2 * Hn + j]), val);
        #pragma unroll
        for (int d2 = 0; d2 < DSET; d2++)
            val = fmaf(wv[DSET + d2], __ldcg(&g_attc[(DSET + d2) * Hn + j]), val);
        qs[j] = val;
        __syncthreads();
        u64 dr = pk(0.0f, 0.0f), dz = pk(0.0f, 0.0f), dn = pk(0.0f, 0.0f);
        unsigned qsa = sptr(qs);
        const float* wr = qy_Wih + (size_t)j * Hn;
        const float* wz = qy_Wih + (size_t)(Hn + j) * Hn;
        const float* wn = qy_Wih + (size_t)(2 * Hn + j) * Hn;
        #pragma unroll 4
        for (int ii = 0; ii < 64; ii++) {
            u64 x01, x23, w01, w23;
            lds2(x01, x23, qsa + (ii << 4));
            ldg2(w01, w23, wr + (ii << 2));
            ffma2(dr, w01, x01); ffma2(dr, w23, x23);
            ldg2(w01, w23, wz + (ii << 2));
            ffma2(dz, w01, x01); ffma2(dz, w23, x23);
            ldg2(w01, w23, wn + (ii << 2));
            ffma2(dn, w01, x01); ffma2(dn, w23, x23);
        }
        float r = sigm(uns(dr) + __ldg(&qy_bih[j]) + __ldg(&qy_bhh[j]));
        float z = sigm(uns(dz) + __ldg(&qy_bih[Hn + j]) + __ldg(&qy_bhh[Hn + j]));
        float n = tanhf(uns(dn) + __ldg(&qy_bih[2 * Hn + j]) + r * __ldg(&qy_bhh[2 * Hn + j]));
        out[q * Hn + j] = (1.0f - z) * n;
    }
}

extern "C" void kernel_launch(void* const* d_in, const int* in_sizes, int n_in,
                              void* d_out, int out_size) {
    const int*   q_tok    = (const int*)d_in[0];
    const int*   p_tok    = (const int*)d_in[1];
    const int*   n_tok    = (const int*)d_in[2];
    const float* term_emb = (const float*)d_in[3];
    const float* term_Wih = (const float*)d_in[4];
    const float* term_Whh = (const float*)d_in[5];
    const float* term_bih = (const float*)d_in[6];
    const float* term_bhh = (const float*)d_in[7];
    const float* doc_emb  = (const float*)d_in[8];
    const float* dc_Wih   = (const float*)d_in[9];
    const float* dc_Whh   = (const float*)d_in[10];
    const float* dc_bih   = (const float*)d_in[11];
    const float* dc_bhh   = (const float*)d_in[12];
    const float* da_Wih   = (const float*)d_in[13];
    const float* da_Whh   = (const float*)d_in[14];
    const float* da_bih   = (const float*)d_in[15];
    const float* da_bhh   = (const float*)d_in[16];
    const float* pos_tab  = (const float*)d_in[17];
    const float* posd_W   = (const float*)d_in[18];
    const float* posd_b   = (const float*)d_in[19];
    const float* qy_Wih   = (const float*)d_in[20];
    const float* qy_Whh   = (const float*)d_in[21];
    const float* qy_bih   = (const float*)d_in[22];
    const float* qy_bhh   = (const float*)d_in[23];
    float* out = (float*)d_out;

    const int dyn_bytes = 64 * HSTR * 4;   // 66560: term h stage (doc uses 24 rows; phase0 xs uses 2048 floats)
    cudaFuncSetAttribute(fmn_kernel, cudaFuncAttributeMaxDynamicSharedMemorySize, dyn_bytes);
    fmn_kernel<<<96, 256, dyn_bytes>>>(q_tok, p_tok, n_tok,
                            term_emb, term_Wih, term_Whh, term_bih, term_bhh,
                            doc_emb, dc_Wih, dc_Whh, dc_bih, dc_bhh,
                            da_Wih, da_Whh, da_bih, da_bhh,
                            pos_tab, posd_W, posd_b,
                            qy_Wih, qy_Whh, qy_bih, qy_bhh,
                            out);
}

// round 7
// speedup vs baseline: 3.0821x; 1.0258x over previous
#include <cuda_runtime.h>

typedef unsigned long long u64;

#define Qn   64
#define LQ   20
#define DSET 12
#define DTn  24
#define LD   50
#define Hn   256
#define G3   768
#define HSTR 260   // h row stride (floats): 260 % 32 == 4 -> 3-wf h reads for 24 lanes

// ---------------- device scratch ----------------
__device__ float g_gi_q[LQ * Qn * G3];
__device__ float g_gi_c[LD * DTn * G3];
__device__ float g_gi_a[LD * DTn * G3];
__device__ float g_hq[2][Qn * Hn];
__device__ float g_hc[2][DTn * Hn];
__device__ float g_ha[2][DTn * Hn];
__device__ float g_attc[DTn * Hn];
__device__ float g_scores[Qn * DTn];
__device__ unsigned g_bar_t, g_bar_c, g_bar_a, g_bar_all;

// ---------------- helpers ----------------
__device__ __forceinline__ float sigm(float x) { return 1.0f / (1.0f + __expf(-x)); }
__device__ __forceinline__ u64 pk(float lo, float hi) {
    u64 r; asm("mov.b64 %0, {%1,%2};" : "=l"(r) : "f"(lo), "f"(hi)); return r;
}
__device__ __forceinline__ float uns(u64 v) {
    float lo, hi; asm("mov.b64 {%0,%1}, %2;" : "=f"(lo), "=f"(hi) : "l"(v));
    return lo + hi;
}
__device__ __forceinline__ void ffma2(u64& d, u64 a, u64 b) {
    asm("fma.rn.f32x2 %0, %1, %2, %0;" : "+l"(d) : "l"(a), "l"(b));
}
__device__ __forceinline__ unsigned sptr(const void* p) {
    return (unsigned)__cvta_generic_to_shared(p);
}
__device__ __forceinline__ void lds2(u64& a, u64& b, unsigned addr) {
    asm volatile("ld.shared.v2.u64 {%0,%1}, [%2];" : "=l"(a), "=l"(b) : "r"(addr));
}
__device__ __forceinline__ void ldg2(u64& a, u64& b, const float* p) {
    asm volatile("ld.global.nc.v2.u64 {%0,%1}, [%2];" : "=l"(a), "=l"(b) : "l"(p));
}

// Generation-counting barrier, release/acquire.
__device__ __forceinline__ void groupbar(unsigned* ctr, unsigned n) {
    __syncthreads();
    if (threadIdx.x == 0) {
        unsigned old;
        asm volatile("atom.release.gpu.global.add.u32 %0, [%1], 1;"
                     : "=r"(old) : "l"(ctr) : "memory");
        unsigned target = (old / n + 1u) * n;
        unsigned cur;
        do {
            asm volatile("ld.acquire.gpu.global.u32 %0, [%1];"
                         : "=r"(cur) : "l"(ctr) : "memory");
        } while (cur < target);
    }
    __syncthreads();
}

// ---------------- phase 0: gi = embed(tokens) @ Wih^T + bih ----------------
__device__ void phase0_gemm(int gid, int R, int mode,
                            const int* __restrict__ tokA, const int* __restrict__ tokB,
                            const float* __restrict__ emb, const float* __restrict__ W,
                            const float* __restrict__ bias, float* __restrict__ gi,
                            float* xs)
{
    int tid = threadIdx.x;
    int rpb = (R + 31) >> 5;
    int r0 = gid * rpb;
    int r1 = min(R, r0 + rpb);
    unsigned xsa = sptr(xs);
    const float* wrow0 = W + (size_t)tid * Hn;
    const float* wrow1 = W + (size_t)(tid + 256) * Hn;
    const float* wrow2 = W + (size_t)(tid + 512) * Hn;
    float b0 = __ldg(bias + tid), b1 = __ldg(bias + tid + 256), b2 = __ldg(bias + tid + 512);

    for (int rt = r0; rt < r1; rt += 8) {
        int nr = min(8, r1 - rt);
        __syncthreads();
        for (int idx = tid; idx < (nr << 8); idx += 256) {
            int rl = idx >> 8, j = idx & 255;
            int r = rt + rl;
            int tok;
            if (mode == 0) {
                int t = r >> 6, q = r & 63;
                tok = tokA[q * LQ + t];
            } else {
                int t = r / DTn, dt = r - t * DTn;
                tok = (dt < DSET) ? tokA[dt * LD + t] : tokB[(dt - DSET) * LD + t];
            }
            xs[(rl << 8) + j] = __ldg(emb + (size_t)tok * Hn + j);
        }
        __syncthreads();

        u64 acc[3][8];
        #pragma unroll
        for (int rl = 0; rl < 8; rl++) {
            acc[0][rl] = pk(b0, 0.0f);
            acc[1][rl] = pk(b1, 0.0f);
            acc[2][rl] = pk(b2, 0.0f);
        }
        #pragma unroll 2
        for (int jj = 0; jj < 64; jj++) {
            u64 w0a, w0b, w1a, w1b, w2a, w2b;
            ldg2(w0a, w0b, wrow0 + (jj << 2));
            ldg2(w1a, w1b, wrow1 + (jj << 2));
            ldg2(w2a, w2b, wrow2 + (jj << 2));
            unsigned xo = xsa + (jj << 4);
            #pragma unroll
            for (int rlb = 0; rlb < 2; rlb++) {
                u64 x01[4], x23[4];
                #pragma unroll
                for (int rl = 0; rl < 4; rl++)
                    lds2(x01[rl], x23[rl], xo + ((rlb * 4 + rl) << 10));
                #pragma unroll
                for (int rl = 0; rl < 4; rl++) {
                    int ri = rlb * 4 + rl;
                    ffma2(acc[0][ri], w0a, x01[rl]); ffma2(acc[0][ri], w0b, x23[rl]);
                    ffma2(acc[1][ri], w1a, x01[rl]); ffma2(acc[1][ri], w1b, x23[rl]);
                    ffma2(acc[2][ri], w2a, x01[rl]); ffma2(acc[2][ri], w2b, x23[rl]);
                }
            }
        }
        for (int rl = 0; rl < nr; rl++) {
            float* gr = gi + (size_t)(rt + rl) * G3 + tid;
            gr[0]   = uns(acc[0][rl]);
            gr[256] = uns(acc[1][rl]);
            gr[512] = uns(acc[2][rl]);
        }
    }
}

// ---------------- doc recurrence: 8 warps, k-split halves, warp pair = 2 cols ----------------
__device__ void run_doc(int cb, const float* __restrict__ Whh, const float* __restrict__ bhh,
                        const float* __restrict__ gi, float* hb0, float* hb1,
                        unsigned* bar, float* ws, float* red, float* hst)
{
    int tid = threadIdx.x;
    int cbase = cb << 3;
    for (int idx = tid; idx < 6144; idx += 256) {
        int rl = idx >> 8, j = idx & 255;
        int gate = rl >> 3, cc = rl & 7;
        ws[idx] = __ldg(Whh + (size_t)(gate * Hn + cbase + cc) * Hn + j);
    }
    int wid = tid >> 5, lane = tid & 31;
    int khalf = wid >> 2, wl = wid & 3;
    int c0 = wl * 2, c1 = c0 + 1;
    int j0 = cbase + c0, j1 = cbase + c1;
    bool fin = (khalf == 0) && (lane < DTn);
    float br0 = 0.f, bz0 = 0.f, bn0 = 0.f, br1 = 0.f, bz1 = 0.f, bn1 = 0.f;
    if (khalf == 0) {
        br0 = __ldg(bhh + j0); bz0 = __ldg(bhh + Hn + j0); bn0 = __ldg(bhh + 2 * Hn + j0);
        br1 = __ldg(bhh + j1); bz1 = __ldg(bhh + Hn + j1); bn1 = __ldg(bhh + 2 * Hn + j1);
    }
    unsigned wsa = sptr(ws);
    unsigned kofs = (unsigned)khalf * 512;         // 128 floats
    unsigned wA[6];
    #pragma unroll
    for (int g = 0; g < 3; g++) {
        wA[g * 2 + 0] = wsa + ((g * 8 + c0) << 10) + kofs;
        wA[g * 2 + 1] = wsa + ((g * 8 + c1) << 10) + kofs;
    }
    unsigned hA = sptr(hst) + (unsigned)lane * (HSTR * 4) + kofs;
    float* myred = red + (wl * 32 + lane) * 7;
    float* hb[2] = { hb0, hb1 };

    for (int t = 0; t < LD; t++) {
        const float4* hg = (const float4*)hb[t & 1];
        float* hn_ = hb[(t & 1) ^ 1];
        #pragma unroll
        for (int i = 0; i < 6; i++) {
            int idx = tid + (i << 8);          // < 1536 float4
            int row = idx >> 6, col = idx & 63;
            float4 v = __ldcg(hg + idx);
            *(float4*)(hst + row * HSTR + (col << 2)) = v;
        }
        // prefetch gi early (overlaps staging + compute)
        float g_r0 = 0.f, g_z0 = 0.f, g_n0 = 0.f, g_r1 = 0.f, g_z1 = 0.f, g_n1 = 0.f;
        if (fin) {
            const float* gib = gi + ((size_t)t * DTn + lane) * G3;
            g_r0 = __ldg(gib + j0); g_z0 = __ldg(gib + Hn + j0); g_n0 = __ldg(gib + 2 * Hn + j0);
            g_r1 = __ldg(gib + j1); g_z1 = __ldg(gib + Hn + j1); g_n1 = __ldg(gib + 2 * Hn + j1);
        }
        __syncthreads();
        u64 ar0 = pk(br0, 0.f), az0 = pk(bz0, 0.f), an0 = pk(bn0, 0.f);
        u64 ar1 = pk(br1, 0.f), az1 = pk(bz1, 0.f), an1 = pk(bn1, 0.f);
        #pragma unroll 4
        for (int jj = 0; jj < 32; jj++) {
            unsigned off = jj << 4;
            u64 h01, h23, w01, w23;
            lds2(h01, h23, hA + off);
            lds2(w01, w23, wA[0] + off);
            ffma2(ar0, w01, h01); ffma2(ar0, w23, h23);
            lds2(w01, w23, wA[1] + off);
            ffma2(ar1, w01, h01); ffma2(ar1, w23, h23);
            lds2(w01, w23, wA[2] + off);
            ffma2(az0, w01, h01); ffma2(az0, w23, h23);
            lds2(w01, w23, wA[3] + off);
            ffma2(az1, w01, h01); ffma2(az1, w23, h23);
            lds2(w01, w23, wA[4] + off);
            ffma2(an0, w01, h01); ffma2(an0, w23, h23);
            lds2(w01, w23, wA[5] + off);
            ffma2(an1, w01, h01); ffma2(an1, w23, h23);
        }
        if (khalf == 1) {
            myred[0] = uns(ar0); myred[1] = uns(ar1);
            myred[2] = uns(az0); myred[3] = uns(az1);
            myred[4] = uns(an0); myred[5] = uns(an1);
        }
        __syncthreads();
        if (fin) {
            float r0 = sigm(g_r0 + uns(ar0) + myred[0]);
            float r1 = sigm(g_r1 + uns(ar1) + myred[1]);
            float z0 = sigm(g_z0 + uns(az0) + myred[2]);
            float z1 = sigm(g_z1 + uns(az1) + myred[3]);
            float n0 = tanhf(g_n0 + r0 * (uns(an0) + myred[4]));
            float n1 = tanhf(g_n1 + r1 * (uns(an1) + myred[5]));
            float ho0 = hst[lane * HSTR + j0];
            float ho1 = hst[lane * HSTR + j1];
            hn_[(lane << 8) + j0] = (1.0f - z0) * n0 + z0 * ho0;
            hn_[(lane << 8) + j1] = (1.0f - z1) * n1 + z1 * ho1;
        }
        groupbar(bar, 32);
    }
}

// ---------------- term recurrence: 8 warps, k-split halves, 2 q-halves ----------------
__device__ void run_term(int cb, const float* __restrict__ Whh, const float* __restrict__ bhh,
                         float* ws, float* red, float* hst)
{
    int tid = threadIdx.x;
    int cbase = cb << 3;
    for (int idx = tid; idx < 6144; idx += 256) {
        int rl = idx >> 8, j = idx & 255;
        int gate = rl >> 3, cc = rl & 7;
        ws[idx] = __ldg(Whh + (size_t)(gate * Hn + cbase + cc) * Hn + j);
    }
    int wid = tid >> 5, lane = tid & 31;
    int khalf = wid >> 2, wl = wid & 3;
    int c0 = wl * 2, c1 = c0 + 1;
    int j0 = cbase + c0, j1 = cbase + c1;
    float br0 = 0.f, bz0 = 0.f, bn0 = 0.f, br1 = 0.f, bz1 = 0.f, bn1 = 0.f;
    if (khalf == 0) {
        br0 = __ldg(bhh + j0); bz0 = __ldg(bhh + Hn + j0); bn0 = __ldg(bhh + 2 * Hn + j0);
        br1 = __ldg(bhh + j1); bz1 = __ldg(bhh + Hn + j1); bn1 = __ldg(bhh + 2 * Hn + j1);
    }
    unsigned wsa = sptr(ws);
    unsigned kofs = (unsigned)khalf * 512;
    unsigned wA[6];
    #pragma unroll
    for (int g = 0; g < 3; g++) {
        wA[g * 2 + 0] = wsa + ((g * 8 + c0) << 10) + kofs;
        wA[g * 2 + 1] = wsa + ((g * 8 + c1) << 10) + kofs;
    }
    unsigned h0A = sptr(hst) + (unsigned)lane * (HSTR * 4) + kofs;
    unsigned h1A = sptr(hst) + (unsigned)(lane + 32) * (HSTR * 4) + kofs;
    float* myred = red + (wl * 32 + lane) * 13;

    for (int t = 0; t < LQ; t++) {
        const float4* hg = (const float4*)g_hq[t & 1];
        float* hn_ = g_hq[(t & 1) ^ 1];
        #pragma unroll
        for (int i = 0; i < 16; i++) {
            int idx = tid + (i << 8);          // < 4096 float4
            int row = idx >> 6, col = idx & 63;
            float4 v = __ldcg(hg + idx);
            *(float4*)(hst + row * HSTR + (col << 2)) = v;
        }
        int q0 = lane, q1 = lane + 32;
        float gr00 = 0.f, gz00 = 0.f, gn00 = 0.f, gr01 = 0.f, gz01 = 0.f, gn01 = 0.f;
        float gr10 = 0.f, gz10 = 0.f, gn10 = 0.f, gr11 = 0.f, gz11 = 0.f, gn11 = 0.f;
        if (khalf == 0) {
            const float* gA = g_gi_q + ((size_t)t * Qn + q0) * G3;
            const float* gB = g_gi_q + ((size_t)t * Qn + q1) * G3;
            gr00 = __ldg(gA + j0); gz00 = __ldg(gA + Hn + j0); gn00 = __ldg(gA + 2 * Hn + j0);
            gr01 = __ldg(gA + j1); gz01 = __ldg(gA + Hn + j1); gn01 = __ldg(gA + 2 * Hn + j1);
            gr10 = __ldg(gB + j0); gz10 = __ldg(gB + Hn + j0); gn10 = __ldg(gB + 2 * Hn + j0);
            gr11 = __ldg(gB + j1); gz11 = __ldg(gB + Hn + j1); gn11 = __ldg(gB + 2 * Hn + j1);
        }
        __syncthreads();
        u64 ar00 = pk(br0, 0.f), az00 = pk(bz0, 0.f), an00 = pk(bn0, 0.f);
        u64 ar01 = pk(br1, 0.f), az01 = pk(bz1, 0.f), an01 = pk(bn1, 0.f);
        u64 ar10 = pk(br0, 0.f), az10 = pk(bz0, 0.f), an10 = pk(bn0, 0.f);
        u64 ar11 = pk(br1, 0.f), az11 = pk(bz1, 0.f), an11 = pk(bn1, 0.f);
        #pragma unroll 4
        for (int jj = 0; jj < 32; jj++) {
            unsigned off = jj << 4;
            u64 h0a, h0b, h1a, h1b, w01, w23;
            lds2(h0a, h0b, h0A + off);
            lds2(h1a, h1b, h1A + off);
            lds2(w01, w23, wA[0] + off);
            ffma2(ar00, w01, h0a); ffma2(ar00, w23, h0b);
            ffma2(ar10, w01, h1a); ffma2(ar10, w23, h1b);
            lds2(w01, w23, wA[1] + off);
            ffma2(ar01, w01, h0a); ffma2(ar01, w23, h0b);
            ffma2(ar11, w01, h1a); ffma2(ar11, w23, h1b);
            lds2(w01, w23, wA[2] + off);
            ffma2(az00, w01, h0a); ffma2(az00, w23, h0b);
            ffma2(az10, w01, h1a); ffma2(az10, w23, h1b);
            lds2(w01, w23, wA[3] + off);
            ffma2(az01, w01, h0a); ffma2(az01, w23, h0b);
            ffma2(az11, w01, h1a); ffma2(az11, w23, h1b);
            lds2(w01, w23, wA[4] + off);
            ffma2(an00, w01, h0a); ffma2(an00, w23, h0b);
            ffma2(an10, w01, h1a); ffma2(an10, w23, h1b);
            lds2(w01, w23, wA[5] + off);
            ffma2(an01, w01, h0a); ffma2(an01, w23, h0b);
            ffma2(an11, w01, h1a); ffma2(an11, w23, h1b);
        }
        if (khalf == 1) {
            myred[0]  = uns(ar00); myred[1]  = uns(ar01);
            myred[2]  = uns(az00); myred[3]  = uns(az01);
            myred[4]  = uns(an00); myred[5]  = uns(an01);
            myred[6]  = uns(ar10); myred[7]  = uns(ar11);
            myred[8]  = uns(az10); myred[9]  = uns(az11);
            myred[10] = uns(an10); myred[11] = uns(an11);
        }
        __syncthreads();
        if (khalf == 0) {
            float r, z, n, ho;
            r = sigm(gr00 + uns(ar00) + myred[0]);
            z = sigm(gz00 + uns(az00) + myred[2]);
            n = tanhf(gn00 + r * (uns(an00) + myred[4]));
            ho = hst[q0 * HSTR + j0];
            hn_[(q0 << 8) + j0] = (1.0f - z) * n + z * ho;
            r = sigm(gr01 + uns(ar01) + myred[1]);
            z = sigm(gz01 + uns(az01) + myred[3]);
            n = tanhf(gn01 + r * (uns(an01) + myred[5]));
            ho = hst[q0 * HSTR + j1];
            hn_[(q0 << 8) + j1] = (1.0f - z) * n + z * ho;
            r = sigm(gr10 + uns(ar10) + myred[6]);
            z = sigm(gz10 + uns(az10) + myred[8]);
            n = tanhf(gn10 + r * (uns(an10) + myred[10]));
            ho = hst[q1 * HSTR + j0];
            hn_[(q1 << 8) + j0] = (1.0f - z) * n + z * ho;
            r = sigm(gr11 + uns(ar11) + myred[7]);
            z = sigm(gz11 + uns(az11) + myred[9]);
            n = tanhf(gn11 + r * (uns(an11) + myred[11]));
            ho = hst[q1 * HSTR + j1];
            hn_[(q1 << 8) + j1] = (1.0f - z) * n + z * ho;
        }
        groupbar(&g_bar_t, 32);
    }
}

// ---------------- persistent kernel ----------------
__global__ void __launch_bounds__(256, 1)
fmn_kernel(const int* __restrict__ q_tok, const int* __restrict__ p_tok, const int* __restrict__ n_tok,
           const float* __restrict__ term_emb, const float* __restrict__ term_Wih,
           const float* __restrict__ term_Whh, const float* __restrict__ term_bih,
           const float* __restrict__ term_bhh,
           const float* __restrict__ doc_emb,
           const float* __restrict__ dc_Wih, const float* __restrict__ dc_Whh,
           const float* __restrict__ dc_bih, const float* __restrict__ dc_bhh,
           const float* __restrict__ da_Wih, const float* __restrict__ da_Whh,
           const float* __restrict__ da_bih, const float* __restrict__ da_bhh,
           const float* __restrict__ pos_table, const float* __restrict__ posd_W,
           const float* __restrict__ posd_b,
           const float* __restrict__ qy_Wih, const float* __restrict__ qy_Whh,
           const float* __restrict__ qy_bih, const float* __restrict__ qy_bhh,
           float* __restrict__ out)
{
    __shared__ float ws[24 * 256];
    __shared__ float red[4 * 32 * 13];
    extern __shared__ float dyn[];
    int bid = blockIdx.x;
    int tid = threadIdx.x;

    if (bid < 32) {                       // doc content GRU
        if (bid == 0)
            for (int i = tid; i < DTn * Hn; i += 256) g_hc[0][i] = 0.0f;
        phase0_gemm(bid, LD * DTn, 1, p_tok, n_tok, doc_emb, dc_Wih, dc_bih, g_gi_c, dyn);
        groupbar(&g_bar_c, 32);
        run_doc(bid, dc_Whh, dc_bhh, g_gi_c, g_hc[0], g_hc[1], &g_bar_c, ws, red, dyn);
    } else if (bid < 64) {                // doc attention GRU
        int gid = bid - 32;
        if (gid == 0)
            for (int i = tid; i < DTn * Hn; i += 256) g_ha[0][i] = 0.0f;
        phase0_gemm(gid, LD * DTn, 1, p_tok, n_tok, doc_emb, da_Wih, da_bih, g_gi_a, dyn);
        groupbar(&g_bar_a, 32);
        run_doc(gid, da_Whh, da_bhh, g_gi_a, g_ha[0], g_ha[1], &g_bar_a, ws, red, dyn);
    } else {                              // term GRU
        int gid = bid - 64;
        if (gid == 0)
            for (int i = tid; i < Qn * Hn; i += 256) g_hq[0][i] = 0.0f;
        phase0_gemm(gid, LQ * Qn, 0, q_tok, (const int*)0, term_emb, term_Wih, term_bih, g_gi_q, dyn);
        groupbar(&g_bar_t, 32);
        run_term(gid, term_Whh, term_bhh, ws, red, dyn);
    }

    groupbar(&g_bar_all, 96);

    // ---- phase A: position dense on content vectors (blocks 0..23) ----
    if (bid < DTn) {
        float* hrow = ws;
        hrow[tid] = __ldcg(&g_hc[0][bid * Hn + tid]);
        __syncthreads();
        int dset = bid % DSET;
        float pe0 = __ldg(&pos_table[dset * 4 + 0]);
        float pe1 = __ldg(&pos_table[dset * 4 + 1]);
        float pe2 = __ldg(&pos_table[dset * 4 + 2]);
        float pe3 = __ldg(&pos_table[dset * 4 + 3]);
        int j = tid;
        const float* wrow = posd_W + (size_t)j * (Hn + 4);
        unsigned xsa = sptr(hrow);
        u64 acc = pk(0.0f, 0.0f);
        #pragma unroll 4
        for (int ii = 0; ii < 64; ii++) {
            u64 w01, w23, x01, x23;
            ldg2(w01, w23, wrow + (ii << 2));
            lds2(x01, x23, xsa + (ii << 4));
            ffma2(acc, w01, x01);
            ffma2(acc, w23, x23);
        }
        float a = uns(acc);
        a = fmaf(pe0, __ldg(wrow + 256), a);
        a = fmaf(pe1, __ldg(wrow + 257), a);
        a = fmaf(pe2, __ldg(wrow + 258), a);
        a = fmaf(pe3, __ldg(wrow + 259), a);
        a += __ldg(&posd_b[j]);
        g_attc[bid * Hn + j] = a;
    } else if (bid >= 32) {
        // ---- phase B: attention scores (blocks 32..95 -> q 0..63) ----
        int q = bid - 32;
        float* eq = ws;
        eq[tid] = __ldcg(&g_hq[0][q * Hn + tid]);
        __syncthreads();
        if (tid < DTn) {
            const float4* ap = (const float4*)(g_ha[0] + tid * Hn);
            const float4* e4 = (const float4*)eq;
            float acc = 0.0f;
            #pragma unroll 4
            for (int ii = 0; ii < 64; ii++) {
                float4 a4 = __ldcg(ap + ii);
                float4 x4 = e4[ii];
                acc = fmaf(a4.x, x4.x, acc);
                acc = fmaf(a4.y, x4.y, acc);
                acc = fmaf(a4.z, x4.z, acc);
                acc = fmaf(a4.w, x4.w, acc);
            }
            g_scores[q * DTn + tid] = acc;
        }
    }

    groupbar(&g_bar_all, 96);

    // ---- phase C: softmax + memory read + final GRU step (blocks 0..63) ----
    if (bid < Qn) {
        int q = bid;
        float* sv = ws;
        float* wv = ws + 32;
        float* qs = ws + 64;
        if (tid < DTn) sv[tid] = __ldcg(&g_scores[q * DTn + tid]);
        __syncthreads();
        if (tid < 2) {
            int off = tid * DSET;
            float mx = -1e30f;
            for (int d2 = 0; d2 < DSET; d2++) mx = fmaxf(mx, sv[off + d2]);
            float s = 0.0f;
            for (int d2 = 0; d2 < DSET; d2++) {
                float e = __expf(sv[off + d2] - mx);
                wv[off + d2] = e;
                s += e;
            }
            float inv = 1.0f / s;
            for (int d2 = 0; d2 < DSET; d2++) wv[off + d2] *= inv;
        }
        __syncthreads();
        int j = tid;
        float val = __ldcg(&g_hq[0][q * Hn + j]);
        #pragma unroll
        for (int d2 = 0; d2 < DSET; d2++)
            val = fmaf(wv[d2], __ldcg(&g_attc[d2 * Hn + j]), val);
        #pragma unroll
        for (int d2 = 0; d2 < DSET; d2++)
            val = fmaf(wv[DSET + d2], __ldcg(&g_attc[(DSET + d2) * Hn + j]), val);
        qs[j] = val;
        __syncthreads();
        u64 dr = pk(0.0f, 0.0f), dz = pk(0.0f, 0.0f), dn = pk(0.0f, 0.0f);
        unsigned qsa = sptr(qs);
        const float* wr = qy_Wih + (size_t)j * Hn;
        const float* wz = qy_Wih + (size_t)(Hn + j) * Hn;
        const float* wn = qy_Wih + (size_t)(2 * Hn + j) * Hn;
        #pragma unroll 4
        for (int ii = 0; ii < 64; ii++) {
            u64 x01, x23, w01, w23;
            lds2(x01, x23, qsa + (ii << 4));
            ldg2(w01, w23, wr + (ii << 2));
            ffma2(dr, w01, x01); ffma2(dr, w23, x23);
            ldg2(w01, w23, wz + (ii << 2));
            ffma2(dz, w01, x01); ffma2(dz, w23, x23);
            ldg2(w01, w23, wn + (ii << 2));
            ffma2(dn, w01, x01); ffma2(dn, w23, x23);
        }
        float r = sigm(uns(dr) + __ldg(&qy_bih[j]) + __ldg(&qy_bhh[j]));
        float z = sigm(uns(dz) + __ldg(&qy_bih[Hn + j]) + __ldg(&qy_bhh[Hn + j]));
        float n = tanhf(uns(dn) + __ldg(&qy_bih[2 * Hn + j]) + r * __ldg(&qy_bhh[2 * Hn + j]));
        out[q * Hn + j] = (1.0f - z) * n;
    }
}

extern "C" void kernel_launch(void* const* d_in, const int* in_sizes, int n_in,
                              void* d_out, int out_size) {
    const int*   q_tok    = (const int*)d_in[0];
    const int*   p_tok    = (const int*)d_in[1];
    const int*   n_tok    = (const int*)d_in[2];
    const float* term_emb = (const float*)d_in[3];
    const float* term_Wih = (const float*)d_in[4];
    const float* term_Whh = (const float*)d_in[5];
    const float* term_bih = (const float*)d_in[6];
    const float* term_bhh = (const float*)d_in[7];
    const float* doc_emb  = (const float*)d_in[8];
    const float* dc_Wih   = (const float*)d_in[9];
    const float* dc_Whh   = (const float*)d_in[10];
    const float* dc_bih   = (const float*)d_in[11];
    const float* dc_bhh   = (const float*)d_in[12];
    const float* da_Wih   = (const float*)d_in[13];
    const float* da_Whh   = (const float*)d_in[14];
    const float* da_bih   = (const float*)d_in[15];
    const float* da_bhh   = (const float*)d_in[16];
    const float* pos_tab  = (const float*)d_in[17];
    const float* posd_W   = (const float*)d_in[18];
    const float* posd_b   = (const float*)d_in[19];
    const float* qy_Wih   = (const float*)d_in[20];
    const float* qy_Whh   = (const float*)d_in[21];
    const float* qy_bih   = (const float*)d_in[22];
    const float* qy_bhh   = (const float*)d_in[23];
    float* out = (float*)d_out;

    const int dyn_bytes = 64 * HSTR * 4;   // 66560: term h stage (doc uses 24 rows; phase0 xs uses 2048 floats)
    cudaFuncSetAttribute(fmn_kernel, cudaFuncAttributeMaxDynamicSharedMemorySize, dyn_bytes);
    fmn_kernel<<<96, 256, dyn_bytes>>>(q_tok, p_tok, n_tok,
                            term_emb, term_Wih, term_Whh, term_bih, term_bhh,
                            doc_emb, dc_Wih, dc_Whh, dc_bih, dc_bhh,
                            da_Wih, da_Whh, da_bih, da_bhh,
                            pos_tab, posd_W, posd_b,
                            qy_Wih, qy_Whh, qy_bih, qy_bhh,
                            out);
}

// round 8
// speedup vs baseline: 3.7097x; 1.2036x over previous
#include <cuda_runtime.h>

typedef unsigned long long u64;

#define Qn   64
#define LQ   20
#define DSET 12
#define DTn  24
#define LD   50
#define Hn   256
#define G3   768
#define HSTR 260   // h row stride (floats): 260 % 32 == 4 -> 3-wf h reads for 24 lanes

// ---------------- device scratch ----------------
__device__ float g_gi_q[LQ * Qn * G3];
__device__ float g_gi_c[LD * DTn * G3];
__device__ float g_gi_a[LD * DTn * G3];
__device__ float4 g_wt_c[64 * G3];   // k-major transposed Wih: Wt[kk][r] = W[r][4kk..4kk+3]
__device__ float4 g_wt_a[64 * G3];
__device__ float4 g_wt_q[64 * G3];
__device__ float g_hq[2][Qn * Hn];
__device__ float g_hc[2][DTn * Hn];
__device__ float g_ha[2][DTn * Hn];
__device__ float g_attc[DTn * Hn];
__device__ float g_scores[Qn * DTn];
__device__ unsigned g_bar_t, g_bar_c, g_bar_a, g_bar_all;

// ---------------- helpers ----------------
__device__ __forceinline__ float sigm(float x) { return 1.0f / (1.0f + __expf(-x)); }
__device__ __forceinline__ u64 pk(float lo, float hi) {
    u64 r; asm("mov.b64 %0, {%1,%2};" : "=l"(r) : "f"(lo), "f"(hi)); return r;
}
__device__ __forceinline__ float uns(u64 v) {
    float lo, hi; asm("mov.b64 {%0,%1}, %2;" : "=f"(lo), "=f"(hi) : "l"(v));
    return lo + hi;
}
__device__ __forceinline__ void ffma2(u64& d, u64 a, u64 b) {
    asm("fma.rn.f32x2 %0, %1, %2, %0;" : "+l"(d) : "l"(a), "l"(b));
}
__device__ __forceinline__ unsigned sptr(const void* p) {
    return (unsigned)__cvta_generic_to_shared(p);
}
__device__ __forceinline__ void lds2(u64& a, u64& b, unsigned addr) {
    asm volatile("ld.shared.v2.u64 {%0,%1}, [%2];" : "=l"(a), "=l"(b) : "r"(addr));
}
__device__ __forceinline__ void ldg2(u64& a, u64& b, const float* p) {
    asm volatile("ld.global.nc.v2.u64 {%0,%1}, [%2];" : "=l"(a), "=l"(b) : "l"(p));
}

// Generation-counting barrier, release/acquire.
__device__ __forceinline__ void groupbar(unsigned* ctr, unsigned n) {
    __syncthreads();
    if (threadIdx.x == 0) {
        unsigned old;
        asm volatile("atom.release.gpu.global.add.u32 %0, [%1], 1;"
                     : "=r"(old) : "l"(ctr) : "memory");
        unsigned target = (old / n + 1u) * n;
        unsigned cur;
        do {
            asm volatile("ld.acquire.gpu.global.u32 %0, [%1];"
                         : "=r"(cur) : "l"(ctr) : "memory");
        } while (cur < target);
    }
    __syncthreads();
}

// ---------------- W transpose: W[768][256] -> Wt[64][768] float4 ----------------
// Block gid handles rows [gid*24, gid*24+24). Coalesced read, smem re-tile, coalesced write.
__device__ void transpose_w(int gid, const float* __restrict__ W, float4* __restrict__ Wt,
                            float* sbuf)
{
    int tid = threadIdx.x;
    int r0 = gid * 24;
    // stage 24 rows with padded stride 260 (bank-spread on re-read)
    for (int i = tid; i < 24 * 256; i += 256) {
        int rl = i >> 8, j = i & 255;
        sbuf[rl * 260 + j] = __ldg(W + (size_t)(r0 + rl) * Hn + j);
    }
    __syncthreads();
    // Wt[kk][r0+rl] = float4 of sbuf[rl][4kk..4kk+3]
    for (int i = tid; i < 24 * 64; i += 256) {
        int rl = i % 24, kk = i / 24;
        float4 v = *(float4*)(sbuf + rl * 260 + (kk << 2));
        Wt[kk * G3 + r0 + rl] = v;
    }
}

// ---------------- phase 0: gi = embed(tokens) @ Wih^T + bih (k-major Wt) ----------------
__device__ void phase0_gemm(int gid, int R, int mode,
                            const int* __restrict__ tokA, const int* __restrict__ tokB,
                            const float* __restrict__ emb, const float4* __restrict__ Wt,
                            const float* __restrict__ bias, float* __restrict__ gi,
                            float* xs)
{
    int tid = threadIdx.x;
    int rpb = (R + 31) >> 5;
    int r0 = gid * rpb;
    int r1 = min(R, r0 + rpb);
    unsigned xsa = sptr(xs);
    float b0 = __ldg(bias + tid), b1 = __ldg(bias + tid + 256), b2 = __ldg(bias + tid + 512);

    for (int rt = r0; rt < r1; rt += 8) {
        int nr = min(8, r1 - rt);
        __syncthreads();
        for (int idx = tid; idx < (nr << 8); idx += 256) {
            int rl = idx >> 8, j = idx & 255;
            int r = rt + rl;
            int tok;
            if (mode == 0) {
                int t = r >> 6, q = r & 63;
                tok = tokA[q * LQ + t];
            } else {
                int t = r / DTn, dt = r - t * DTn;
                tok = (dt < DSET) ? tokA[dt * LD + t] : tokB[(dt - DSET) * LD + t];
            }
            xs[(rl << 8) + j] = __ldg(emb + (size_t)tok * Hn + j);
        }
        __syncthreads();

        u64 acc[3][8];
        #pragma unroll
        for (int rl = 0; rl < 8; rl++) {
            acc[0][rl] = pk(b0, 0.0f);
            acc[1][rl] = pk(b1, 0.0f);
            acc[2][rl] = pk(b2, 0.0f);
        }
        #pragma unroll 2
        for (int jj = 0; jj < 64; jj++) {
            // coalesced: lanes read consecutive float4s (4wf instead of 32wf)
            const float* wp = (const float*)(Wt + jj * G3 + tid);
            u64 w0a, w0b, w1a, w1b, w2a, w2b;
            ldg2(w0a, w0b, wp);
            ldg2(w1a, w1b, wp + 1024);        // +256 float4
            ldg2(w2a, w2b, wp + 2048);        // +512 float4
            unsigned xo = xsa + (jj << 4);
            #pragma unroll
            for (int rlb = 0; rlb < 2; rlb++) {
                u64 x01[4], x23[4];
                #pragma unroll
                for (int rl = 0; rl < 4; rl++)
                    lds2(x01[rl], x23[rl], xo + ((rlb * 4 + rl) << 10));
                #pragma unroll
                for (int rl = 0; rl < 4; rl++) {
                    int ri = rlb * 4 + rl;
                    ffma2(acc[0][ri], w0a, x01[rl]); ffma2(acc[0][ri], w0b, x23[rl]);
                    ffma2(acc[1][ri], w1a, x01[rl]); ffma2(acc[1][ri], w1b, x23[rl]);
                    ffma2(acc[2][ri], w2a, x01[rl]); ffma2(acc[2][ri], w2b, x23[rl]);
                }
            }
        }
        for (int rl = 0; rl < nr; rl++) {
            float* gr = gi + (size_t)(rt + rl) * G3 + tid;
            gr[0]   = uns(acc[0][rl]);
            gr[256] = uns(acc[1][rl]);
            gr[512] = uns(acc[2][rl]);
        }
    }
}

// ---------------- doc recurrence: 8 warps, k-split halves, warp pair = 2 cols ----------------
__device__ void run_doc(int cb, const float* __restrict__ Whh, const float* __restrict__ bhh,
                        const float* __restrict__ gi, float* hb0, float* hb1,
                        unsigned* bar, float* ws, float* red, float* hst)
{
    int tid = threadIdx.x;
    int cbase = cb << 3;
    for (int idx = tid; idx < 6144; idx += 256) {
        int rl = idx >> 8, j = idx & 255;
        int gate = rl >> 3, cc = rl & 7;
        ws[idx] = __ldg(Whh + (size_t)(gate * Hn + cbase + cc) * Hn + j);
    }
    int wid = tid >> 5, lane = tid & 31;
    int khalf = wid >> 2, wl = wid & 3;
    int c0 = wl * 2, c1 = c0 + 1;
    int j0 = cbase + c0, j1 = cbase + c1;
    bool fin = (khalf == 0) && (lane < DTn);
    float br0 = 0.f, bz0 = 0.f, bn0 = 0.f, br1 = 0.f, bz1 = 0.f, bn1 = 0.f;
    if (khalf == 0) {
        br0 = __ldg(bhh + j0); bz0 = __ldg(bhh + Hn + j0); bn0 = __ldg(bhh + 2 * Hn + j0);
        br1 = __ldg(bhh + j1); bz1 = __ldg(bhh + Hn + j1); bn1 = __ldg(bhh + 2 * Hn + j1);
    }
    unsigned wsa = sptr(ws);
    unsigned kofs = (unsigned)khalf * 512;         // 128 floats
    unsigned wA[6];
    #pragma unroll
    for (int g = 0; g < 3; g++) {
        wA[g * 2 + 0] = wsa + ((g * 8 + c0) << 10) + kofs;
        wA[g * 2 + 1] = wsa + ((g * 8 + c1) << 10) + kofs;
    }
    unsigned hA = sptr(hst) + (unsigned)lane * (HSTR * 4) + kofs;
    float* myred = red + (wl * 32 + lane) * 7;
    float* hb[2] = { hb0, hb1 };

    for (int t = 0; t < LD; t++) {
        const float4* hg = (const float4*)hb[t & 1];
        float* hn_ = hb[(t & 1) ^ 1];
        #pragma unroll
        for (int i = 0; i < 6; i++) {
            int idx = tid + (i << 8);          // < 1536 float4
            int row = idx >> 6, col = idx & 63;
            float4 v = __ldcg(hg + idx);
            *(float4*)(hst + row * HSTR + (col << 2)) = v;
        }
        // prefetch gi early (overlaps staging + compute)
        float g_r0 = 0.f, g_z0 = 0.f, g_n0 = 0.f, g_r1 = 0.f, g_z1 = 0.f, g_n1 = 0.f;
        if (fin) {
            const float* gib = gi + ((size_t)t * DTn + lane) * G3;
            g_r0 = __ldg(gib + j0); g_z0 = __ldg(gib + Hn + j0); g_n0 = __ldg(gib + 2 * Hn + j0);
            g_r1 = __ldg(gib + j1); g_z1 = __ldg(gib + Hn + j1); g_n1 = __ldg(gib + 2 * Hn + j1);
        }
        __syncthreads();
        u64 ar0 = pk(br0, 0.f), az0 = pk(bz0, 0.f), an0 = pk(bn0, 0.f);
        u64 ar1 = pk(br1, 0.f), az1 = pk(bz1, 0.f), an1 = pk(bn1, 0.f);
        #pragma unroll 4
        for (int jj = 0; jj < 32; jj++) {
            unsigned off = jj << 4;
            u64 h01, h23, w01, w23;
            lds2(h01, h23, hA + off);
            lds2(w01, w23, wA[0] + off);
            ffma2(ar0, w01, h01); ffma2(ar0, w23, h23);
            lds2(w01, w23, wA[1] + off);
            ffma2(ar1, w01, h01); ffma2(ar1, w23, h23);
            lds2(w01, w23, wA[2] + off);
            ffma2(az0, w01, h01); ffma2(az0, w23, h23);
            lds2(w01, w23, wA[3] + off);
            ffma2(az1, w01, h01); ffma2(az1, w23, h23);
            lds2(w01, w23, wA[4] + off);
            ffma2(an0, w01, h01); ffma2(an0, w23, h23);
            lds2(w01, w23, wA[5] + off);
            ffma2(an1, w01, h01); ffma2(an1, w23, h23);
        }
        if (khalf == 1) {
            myred[0] = uns(ar0); myred[1] = uns(ar1);
            myred[2] = uns(az0); myred[3] = uns(az1);
            myred[4] = uns(an0); myred[5] = uns(an1);
        }
        __syncthreads();
        if (fin) {
            float r0 = sigm(g_r0 + uns(ar0) + myred[0]);
            float r1 = sigm(g_r1 + uns(ar1) + myred[1]);
            float z0 = sigm(g_z0 + uns(az0) + myred[2]);
            float z1 = sigm(g_z1 + uns(az1) + myred[3]);
            float n0 = tanhf(g_n0 + r0 * (uns(an0) + myred[4]));
            float n1 = tanhf(g_n1 + r1 * (uns(an1) + myred[5]));
            float ho0 = hst[lane * HSTR + j0];
            float ho1 = hst[lane * HSTR + j1];
            hn_[(lane << 8) + j0] = (1.0f - z0) * n0 + z0 * ho0;
            hn_[(lane << 8) + j1] = (1.0f - z1) * n1 + z1 * ho1;
        }
        groupbar(bar, 32);
    }
}

// ---------------- term recurrence: 8 warps, k-split halves, 2 q-halves ----------------
__device__ void run_term(int cb, const float* __restrict__ Whh, const float* __restrict__ bhh,
                         float* ws, float* red, float* hst)
{
    int tid = threadIdx.x;
    int cbase = cb << 3;
    for (int idx = tid; idx < 6144; idx += 256) {
        int rl = idx >> 8, j = idx & 255;
        int gate = rl >> 3, cc = rl & 7;
        ws[idx] = __ldg(Whh + (size_t)(gate * Hn + cbase + cc) * Hn + j);
    }
    int wid = tid >> 5, lane = tid & 31;
    int khalf = wid >> 2, wl = wid & 3;
    int c0 = wl * 2, c1 = c0 + 1;
    int j0 = cbase + c0, j1 = cbase + c1;
    float br0 = 0.f, bz0 = 0.f, bn0 = 0.f, br1 = 0.f, bz1 = 0.f, bn1 = 0.f;
    if (khalf == 0) {
        br0 = __ldg(bhh + j0); bz0 = __ldg(bhh + Hn + j0); bn0 = __ldg(bhh + 2 * Hn + j0);
        br1 = __ldg(bhh + j1); bz1 = __ldg(bhh + Hn + j1); bn1 = __ldg(bhh + 2 * Hn + j1);
    }
    unsigned wsa = sptr(ws);
    unsigned kofs = (unsigned)khalf * 512;
    unsigned wA[6];
    #pragma unroll
    for (int g = 0; g < 3; g++) {
        wA[g * 2 + 0] = wsa + ((g * 8 + c0) << 10) + kofs;
        wA[g * 2 + 1] = wsa + ((g * 8 + c1) << 10) + kofs;
    }
    unsigned h0A = sptr(hst) + (unsigned)lane * (HSTR * 4) + kofs;
    unsigned h1A = sptr(hst) + (unsigned)(lane + 32) * (HSTR * 4) + kofs;
    float* myred = red + (wl * 32 + lane) * 13;

    for (int t = 0; t < LQ; t++) {
        const float4* hg = (const float4*)g_hq[t & 1];
        float* hn_ = g_hq[(t & 1) ^ 1];
        #pragma unroll
        for (int i = 0; i < 16; i++) {
            int idx = tid + (i << 8);          // < 4096 float4
            int row = idx >> 6, col = idx & 63;
            float4 v = __ldcg(hg + idx);
            *(float4*)(hst + row * HSTR + (col << 2)) = v;
        }
        int q0 = lane, q1 = lane + 32;
        float gr00 = 0.f, gz00 = 0.f, gn00 = 0.f, gr01 = 0.f, gz01 = 0.f, gn01 = 0.f;
        float gr10 = 0.f, gz10 = 0.f, gn10 = 0.f, gr11 = 0.f, gz11 = 0.f, gn11 = 0.f;
        if (khalf == 0) {
            const float* gA = g_gi_q + ((size_t)t * Qn + q0) * G3;
            const float* gB = g_gi_q + ((size_t)t * Qn + q1) * G3;
            gr00 = __ldg(gA + j0); gz00 = __ldg(gA + Hn + j0); gn00 = __ldg(gA + 2 * Hn + j0);
            gr01 = __ldg(gA + j1); gz01 = __ldg(gA + Hn + j1); gn01 = __ldg(gA + 2 * Hn + j1);
            gr10 = __ldg(gB + j0); gz10 = __ldg(gB + Hn + j0); gn10 = __ldg(gB + 2 * Hn + j0);
            gr11 = __ldg(gB + j1); gz11 = __ldg(gB + Hn + j1); gn11 = __ldg(gB + 2 * Hn + j1);
        }
        __syncthreads();
        u64 ar00 = pk(br0, 0.f), az00 = pk(bz0, 0.f), an00 = pk(bn0, 0.f);
        u64 ar01 = pk(br1, 0.f), az01 = pk(bz1, 0.f), an01 = pk(bn1, 0.f);
        u64 ar10 = pk(br0, 0.f), az10 = pk(bz0, 0.f), an10 = pk(bn0, 0.f);
        u64 ar11 = pk(br1, 0.f), az11 = pk(bz1, 0.f), an11 = pk(bn1, 0.f);
        #pragma unroll 4
        for (int jj = 0; jj < 32; jj++) {
            unsigned off = jj << 4;
            u64 h0a, h0b, h1a, h1b, w01, w23;
            lds2(h0a, h0b, h0A + off);
            lds2(h1a, h1b, h1A + off);
            lds2(w01, w23, wA[0] + off);
            ffma2(ar00, w01, h0a); ffma2(ar00, w23, h0b);
            ffma2(ar10, w01, h1a); ffma2(ar10, w23, h1b);
            lds2(w01, w23, wA[1] + off);
            ffma2(ar01, w01, h0a); ffma2(ar01, w23, h0b);
            ffma2(ar11, w01, h1a); ffma2(ar11, w23, h1b);
            lds2(w01, w23, wA[2] + off);
            ffma2(az00, w01, h0a); ffma2(az00, w23, h0b);
            ffma2(az10, w01, h1a); ffma2(az10, w23, h1b);
            lds2(w01, w23, wA[3] + off);
            ffma2(az01, w01, h0a); ffma2(az01, w23, h0b);
            ffma2(az11, w01, h1a); ffma2(az11, w23, h1b);
            lds2(w01, w23, wA[4] + off);
            ffma2(an00, w01, h0a); ffma2(an00, w23, h0b);
            ffma2(an10, w01, h1a); ffma2(an10, w23, h1b);
            lds2(w01, w23, wA[5] + off);
            ffma2(an01, w01, h0a); ffma2(an01, w23, h0b);
            ffma2(an11, w01, h1a); ffma2(an11, w23, h1b);
        }
        if (khalf == 1) {
            myred[0]  = uns(ar00); myred[1]  = uns(ar01);
            myred[2]  = uns(az00); myred[3]  = uns(az01);
            myred[4]  = uns(an00); myred[5]  = uns(an01);
            myred[6]  = uns(ar10); myred[7]  = uns(ar11);
            myred[8]  = uns(az10); myred[9]  = uns(az11);
            myred[10] = uns(an10); myred[11] = uns(an11);
        }
        __syncthreads();
        if (khalf == 0) {
            float r, z, n, ho;
            r = sigm(gr00 + uns(ar00) + myred[0]);
            z = sigm(gz00 + uns(az00) + myred[2]);
            n = tanhf(gn00 + r * (uns(an00) + myred[4]));
            ho = hst[q0 * HSTR + j0];
            hn_[(q0 << 8) + j0] = (1.0f - z) * n + z * ho;
            r = sigm(gr01 + uns(ar01) + myred[1]);
            z = sigm(gz01 + uns(az01) + myred[3]);
            n = tanhf(gn01 + r * (uns(an01) + myred[5]));
            ho = hst[q0 * HSTR + j1];
            hn_[(q0 << 8) + j1] = (1.0f - z) * n + z * ho;
            r = sigm(gr10 + uns(ar10) + myred[6]);
            z = sigm(gz10 + uns(az10) + myred[8]);
            n = tanhf(gn10 + r * (uns(an10) + myred[10]));
            ho = hst[q1 * HSTR + j0];
            hn_[(q1 << 8) + j0] = (1.0f - z) * n + z * ho;
            r = sigm(gr11 + uns(ar11) + myred[7]);
            z = sigm(gz11 + uns(az11) + myred[9]);
            n = tanhf(gn11 + r * (uns(an11) + myred[11]));
            ho = hst[q1 * HSTR + j1];
            hn_[(q1 << 8) + j1] = (1.0f - z) * n + z * ho;
        }
        groupbar(&g_bar_t, 32);
    }
}

// ---------------- persistent kernel ----------------
__global__ void __launch_bounds__(256, 1)
fmn_kernel(const int* __restrict__ q_tok, const int* __restrict__ p_tok, const int* __restrict__ n_tok,
           const float* __restrict__ term_emb, const float* __restrict__ term_Wih,
           const float* __restrict__ term_Whh, const float* __restrict__ term_bih,
           const float* __restrict__ term_bhh,
           const float* __restrict__ doc_emb,
           const float* __restrict__ dc_Wih, const float* __restrict__ dc_Whh,
           const float* __restrict__ dc_bih, const float* __restrict__ dc_bhh,
           const float* __restrict__ da_Wih, const float* __restrict__ da_Whh,
           const float* __restrict__ da_bih, const float* __restrict__ da_bhh,
           const float* __restrict__ pos_table, const float* __restrict__ posd_W,
           const float* __restrict__ posd_b,
           const float* __restrict__ qy_Wih, const float* __restrict__ qy_Whh,
           const float* __restrict__ qy_bih, const float* __restrict__ qy_bhh,
           float* __restrict__ out)
{
    __shared__ float ws[24 * 256];
    __shared__ float red[4 * 32 * 13];
    extern __shared__ float dyn[];
    int bid = blockIdx.x;
    int tid = threadIdx.x;

    if (bid < 32) {                       // doc content GRU
        if (bid == 0)
            for (int i = tid; i < DTn * Hn; i += 256) g_hc[0][i] = 0.0f;
        transpose_w(bid, dc_Wih, g_wt_c, dyn);
        groupbar(&g_bar_c, 32);
        phase0_gemm(bid, LD * DTn, 1, p_tok, n_tok, doc_emb, g_wt_c, dc_bih, g_gi_c, dyn);
        groupbar(&g_bar_c, 32);
        run_doc(bid, dc_Whh, dc_bhh, g_gi_c, g_hc[0], g_hc[1], &g_bar_c, ws, red, dyn);
    } else if (bid < 64) {                // doc attention GRU
        int gid = bid - 32;
        if (gid == 0)
            for (int i = tid; i < DTn * Hn; i += 256) g_ha[0][i] = 0.0f;
        transpose_w(gid, da_Wih, g_wt_a, dyn);
        groupbar(&g_bar_a, 32);
        phase0_gemm(gid, LD * DTn, 1, p_tok, n_tok, doc_emb, g_wt_a, da_bih, g_gi_a, dyn);
        groupbar(&g_bar_a, 32);
        run_doc(gid, da_Whh, da_bhh, g_gi_a, g_ha[0], g_ha[1], &g_bar_a, ws, red, dyn);
    } else {                              // term GRU
        int gid = bid - 64;
        if (gid == 0)
            for (int i = tid; i < Qn * Hn; i += 256) g_hq[0][i] = 0.0f;
        transpose_w(gid, term_Wih, g_wt_q, dyn);
        groupbar(&g_bar_t, 32);
        phase0_gemm(gid, LQ * Qn, 0, q_tok, (const int*)0, term_emb, g_wt_q, term_bih, g_gi_q, dyn);
        groupbar(&g_bar_t, 32);
        run_term(gid, term_Whh, term_bhh, ws, red, dyn);
    }

    groupbar(&g_bar_all, 96);

    // ---- phase A: position dense on content vectors (blocks 0..23) ----
    if (bid < DTn) {
        float* hrow = ws;
        hrow[tid] = __ldcg(&g_hc[0][bid * Hn + tid]);
        __syncthreads();
        int dset = bid % DSET;
        float pe0 = __ldg(&pos_table[dset * 4 + 0]);
        float pe1 = __ldg(&pos_table[dset * 4 + 1]);
        float pe2 = __ldg(&pos_table[dset * 4 + 2]);
        float pe3 = __ldg(&pos_table[dset * 4 + 3]);
        int j = tid;
        const float* wrow = posd_W + (size_t)j * (Hn + 4);
        unsigned xsa = sptr(hrow);
        u64 acc = pk(0.0f, 0.0f);
        #pragma unroll 4
        for (int ii = 0; ii < 64; ii++) {
            u64 w01, w23, x01, x23;
            ldg2(w01, w23, wrow + (ii << 2));
            lds2(x01, x23, xsa + (ii << 4));
            ffma2(acc, w01, x01);
            ffma2(acc, w23, x23);
        }
        float a = uns(acc);
        a = fmaf(pe0, __ldg(wrow + 256), a);
        a = fmaf(pe1, __ldg(wrow + 257), a);
        a = fmaf(pe2, __ldg(wrow + 258), a);
        a = fmaf(pe3, __ldg(wrow + 259), a);
        a += __ldg(&posd_b[j]);
        g_attc[bid * Hn + j] = a;
    } else if (bid >= 32) {
        // ---- phase B: attention scores (blocks 32..95 -> q 0..63) ----
        int q = bid - 32;
        float* eq = ws;
        eq[tid] = __ldcg(&g_hq[0][q * Hn + tid]);
        __syncthreads();
        if (tid < DTn) {
            const float4* ap = (const float4*)(g_ha[0] + tid * Hn);
            const float4* e4 = (const float4*)eq;
            float acc = 0.0f;
            #pragma unroll 4
            for (int ii = 0; ii < 64; ii++) {
                float4 a4 = __ldcg(ap + ii);
                float4 x4 = e4[ii];
                acc = fmaf(a4.x, x4.x, acc);
                acc = fmaf(a4.y, x4.y, acc);
                acc = fmaf(a4.z, x4.z, acc);
                acc = fmaf(a4.w, x4.w, acc);
            }
            g_scores[q * DTn + tid] = acc;
        }
    }

    groupbar(&g_bar_all, 96);

    // ---- phase C: softmax + memory read + final GRU step (blocks 0..63) ----
    if (bid < Qn) {
        int q = bid;
        float* sv = ws;
        float* wv = ws + 32;
        float* qs = ws + 64;
        if (tid < DTn) sv[tid] = __ldcg(&g_scores[q * DTn + tid]);
        __syncthreads();
        if (tid < 2) {
            int off = tid * DSET;
            float mx = -1e30f;
            for (int d2 = 0; d2 < DSET; d2++) mx = fmaxf(mx, sv[off + d2]);
            float s = 0.0f;
            for (int d2 = 0; d2 < DSET; d2++) {
                float e = __expf(sv[off + d2] - mx);
                wv[off + d2] = e;
                s += e;
            }
            float inv = 1.0f / s;
            for (int d2 = 0; d2 < DSET; d2++) wv[off + d2] *= inv;
        }
        __syncthreads();
        int j = tid;
        float val = __ldcg(&g_hq[0][q * Hn + j]);
        #pragma unroll
        for (int d2 = 0; d2 < DSET; d2++)
            val = fmaf(wv[d2], __ldcg(&g_attc[d2 * Hn + j]), val);
        #pragma unroll
        for (int d2 = 0; d2 < DSET; d2++)
            val = fmaf(wv[DSET + d2], __ldcg(&g_attc[(DSET + d2) * Hn + j]), val);
        qs[j] = val;
        __syncthreads();
        u64 dr = pk(0.0f, 0.0f), dz = pk(0.0f, 0.0f), dn = pk(0.0f, 0.0f);
        unsigned qsa = sptr(qs);
        const float* wr = qy_Wih + (size_t)j * Hn;
        const float* wz = qy_Wih + (size_t)(Hn + j) * Hn;
        const float* wn = qy_Wih + (size_t)(2 * Hn + j) * Hn;
        #pragma unroll 4
        for (int ii = 0; ii < 64; ii++) {
            u64 x01, x23, w01, w23;
            lds2(x01, x23, qsa + (ii << 4));
            ldg2(w01, w23, wr + (ii << 2));
            ffma2(dr, w01, x01); ffma2(dr, w23, x23);
            ldg2(w01, w23, wz + (ii << 2));
            ffma2(dz, w01, x01); ffma2(dz, w23, x23);
            ldg2(w01, w23, wn + (ii << 2));
            ffma2(dn, w01, x01); ffma2(dn, w23, x23);
        }
        float r = sigm(uns(dr) + __ldg(&qy_bih[j]) + __ldg(&qy_bhh[j]));
        float z = sigm(uns(dz) + __ldg(&qy_bih[Hn + j]) + __ldg(&qy_bhh[Hn + j]));
        float n = tanhf(uns(dn) + __ldg(&qy_bih[2 * Hn + j]) + r * __ldg(&qy_bhh[2 * Hn + j]));
        out[q * Hn + j] = (1.0f - z) * n;
    }
}

extern "C" void kernel_launch(void* const* d_in, const int* in_sizes, int n_in,
                              void* d_out, int out_size) {
    const int*   q_tok    = (const int*)d_in[0];
    const int*   p_tok    = (const int*)d_in[1];
    const int*   n_tok    = (const int*)d_in[2];
    const float* term_emb = (const float*)d_in[3];
    const float* term_Wih = (const float*)d_in[4];
    const float* term_Whh = (const float*)d_in[5];
    const float* term_bih = (const float*)d_in[6];
    const float* term_bhh = (const float*)d_in[7];
    const float* doc_emb  = (const float*)d_in[8];
    const float* dc_Wih   = (const float*)d_in[9];
    const float* dc_Whh   = (const float*)d_in[10];
    const float* dc_bih   = (const float*)d_in[11];
    const float* dc_bhh   = (const float*)d_in[12];
    const float* da_Wih   = (const float*)d_in[13];
    const float* da_Whh   = (const float*)d_in[14];
    const float* da_bih   = (const float*)d_in[15];
    const float* da_bhh   = (const float*)d_in[16];
    const float* pos_tab  = (const float*)d_in[17];
    const float* posd_W   = (const float*)d_in[18];
    const float* posd_b   = (const float*)d_in[19];
    const float* qy_Wih   = (const float*)d_in[20];
    const float* qy_Whh   = (const float*)d_in[21];
    const float* qy_bih   = (const float*)d_in[22];
    const float* qy_bhh   = (const float*)d_in[23];
    float* out = (float*)d_out;

    const int dyn_bytes = 64 * HSTR * 4;   // 66560: term h stage / transpose buf / phase0 xs
    cudaFuncSetAttribute(fmn_kernel, cudaFuncAttributeMaxDynamicSharedMemorySize, dyn_bytes);
    fmn_kernel<<<96, 256, dyn_bytes>>>(q_tok, p_tok, n_tok,
                            term_emb, term_Wih, term_Whh, term_bih, term_bhh,
                            doc_emb, dc_Wih, dc_Whh, dc_bih, dc_bhh,
                            da_Wih, da_Whh, da_bih, da_bhh,
                            pos_tab, posd_W, posd_b,
                            qy_Wih, qy_Whh, qy_bih, qy_bhh,
                            out);
}

// round 9
// speedup vs baseline: 3.8852x; 1.0473x over previous
#include <cuda_runtime.h>

typedef unsigned long long u64;

#define Qn   64
#define LQ   20
#define DSET 12
#define DTn  24
#define LD   50
#define Hn   256
#define G3   768
#define HSTR 260   // h row stride (floats): 260 % 32 == 4 -> 3-wf h reads for 24 lanes
#define NB_DOC 52  // blocks on each doc phase0 GEMM (32 main + 20 helpers)
#define NB_TRM 40  // blocks on term phase0 GEMM (32 main + 8 helpers)
#define NBLK 144

// ---------------- device scratch ----------------
__device__ float g_gi_q[LQ * Qn * G3];
__device__ float g_gi_c[LD * DTn * G3];
__device__ float g_gi_a[LD * DTn * G3];
__device__ float4 g_wt_c[64 * G3];   // k-major transposed Wih
__device__ float4 g_wt_a[64 * G3];
__device__ float4 g_wt_q[64 * G3];
__device__ float g_hq[2][Qn * Hn];
__device__ float g_hc[2][DTn * Hn];
__device__ float g_ha[2][DTn * Hn];
__device__ float g_attc[DTn * Hn];
__device__ float g_scores[Qn * DTn];
// flag arrays: one 128B line per block, generation-counting (monotonic across replays)
__device__ unsigned g_f_p0c[NB_DOC * 32];
__device__ unsigned g_f_p0a[NB_DOC * 32];
__device__ unsigned g_f_p0t[NB_TRM * 32];
__device__ unsigned g_f_rc[32 * 32];
__device__ unsigned g_f_ra[32 * 32];
__device__ unsigned g_f_rt[32 * 32];
__device__ unsigned g_f_all[NBLK * 32];

// ---------------- helpers ----------------
__device__ __forceinline__ float sigm(float x) { return 1.0f / (1.0f + __expf(-x)); }
__device__ __forceinline__ u64 pk(float lo, float hi) {
    u64 r; asm("mov.b64 %0, {%1,%2};" : "=l"(r) : "f"(lo), "f"(hi)); return r;
}
__device__ __forceinline__ float uns(u64 v) {
    float lo, hi; asm("mov.b64 {%0,%1}, %2;" : "=f"(lo), "=f"(hi) : "l"(v));
    return lo + hi;
}
__device__ __forceinline__ void ffma2(u64& d, u64 a, u64 b) {
    asm("fma.rn.f32x2 %0, %1, %2, %0;" : "+l"(d) : "l"(a), "l"(b));
}
__device__ __forceinline__ unsigned sptr(const void* p) {
    return (unsigned)__cvta_generic_to_shared(p);
}
__device__ __forceinline__ void lds2(u64& a, u64& b, unsigned addr) {
    asm volatile("ld.shared.v2.u64 {%0,%1}, [%2];" : "=l"(a), "=l"(b) : "r"(addr));
}
__device__ __forceinline__ void ldg2(u64& a, u64& b, const float* p) {
    asm volatile("ld.global.nc.v2.u64 {%0,%1}, [%2];" : "=l"(a), "=l"(b) : "l"(p));
}

// ---- flag barrier: no atomic contention; one release store + parallel acquire polls
__device__ __forceinline__ void bar_arrive(unsigned* fl, int idx, unsigned gen) {
    __syncthreads();                       // all block writes done
    if (threadIdx.x == 0)
        asm volatile("st.release.gpu.global.u32 [%0], %1;"
                     :: "l"(fl + idx * 32), "r"(gen) : "memory");
}
__device__ __forceinline__ void bar_wait(unsigned* fl, int n, unsigned gen) {
    if (threadIdx.x < (unsigned)n) {
        unsigned cur;
        do {
            asm volatile("ld.acquire.gpu.global.u32 %0, [%1];"
                         : "=r"(cur) : "l"(fl + threadIdx.x * 32) : "memory");
        } while (cur < gen);
    }
    __syncthreads();
}
__device__ __forceinline__ unsigned rd_base(unsigned* fl, int idx) {
    return *(volatile unsigned*)(fl + idx * 32);
}

// ---------------- W transpose: W[768][256] -> Wt[64][768] float4 ----------------
__device__ void transpose_w(int gid, const float* __restrict__ W, float4* __restrict__ Wt,
                            float* sbuf)
{
    int tid = threadIdx.x;
    int r0 = gid * 24;
    for (int i = tid; i < 24 * 256; i += 256) {
        int rl = i >> 8, j = i & 255;
        sbuf[rl * 260 + j] = __ldg(W + (size_t)(r0 + rl) * Hn + j);
    }
    __syncthreads();
    for (int i = tid; i < 24 * 64; i += 256) {
        int rl = i % 24, kk = i / 24;
        float4 v = *(float4*)(sbuf + rl * 260 + (kk << 2));
        Wt[kk * G3 + r0 + rl] = v;
    }
}

// ---------------- phase 0: gi = embed(tokens) @ Wih^T + bih (k-major Wt) ----------------
__device__ void phase0_gemm(int gid, int nb, int R, int mode,
                            const int* __restrict__ tokA, const int* __restrict__ tokB,
                            const float* __restrict__ emb, const float4* __restrict__ Wt,
                            const float* __restrict__ bias, float* __restrict__ gi,
                            float* xs)
{
    int tid = threadIdx.x;
    int rpb = (R + nb - 1) / nb;
    int r0 = gid * rpb;
    int r1 = min(R, r0 + rpb);
    unsigned xsa = sptr(xs);
    float b0 = __ldg(bias + tid), b1 = __ldg(bias + tid + 256), b2 = __ldg(bias + tid + 512);

    for (int rt = r0; rt < r1; rt += 8) {
        int nr = min(8, r1 - rt);
        __syncthreads();
        for (int idx = tid; idx < (nr << 8); idx += 256) {
            int rl = idx >> 8, j = idx & 255;
            int r = rt + rl;
            int tok;
            if (mode == 0) {
                int t = r >> 6, q = r & 63;
                tok = tokA[q * LQ + t];
            } else {
                int t = r / DTn, dt = r - t * DTn;
                tok = (dt < DSET) ? tokA[dt * LD + t] : tokB[(dt - DSET) * LD + t];
            }
            xs[(rl << 8) + j] = __ldg(emb + (size_t)tok * Hn + j);
        }
        __syncthreads();

        u64 acc[3][8];
        #pragma unroll
        for (int rl = 0; rl < 8; rl++) {
            acc[0][rl] = pk(b0, 0.0f);
            acc[1][rl] = pk(b1, 0.0f);
            acc[2][rl] = pk(b2, 0.0f);
        }
        #pragma unroll 2
        for (int jj = 0; jj < 64; jj++) {
            const float* wp = (const float*)(Wt + jj * G3 + tid);
            u64 w0a, w0b, w1a, w1b, w2a, w2b;
            ldg2(w0a, w0b, wp);
            ldg2(w1a, w1b, wp + 1024);
            ldg2(w2a, w2b, wp + 2048);
            unsigned xo = xsa + (jj << 4);
            #pragma unroll
            for (int rlb = 0; rlb < 2; rlb++) {
                u64 x01[4], x23[4];
                #pragma unroll
                for (int rl = 0; rl < 4; rl++)
                    lds2(x01[rl], x23[rl], xo + ((rlb * 4 + rl) << 10));
                #pragma unroll
                for (int rl = 0; rl < 4; rl++) {
                    int ri = rlb * 4 + rl;
                    ffma2(acc[0][ri], w0a, x01[rl]); ffma2(acc[0][ri], w0b, x23[rl]);
                    ffma2(acc[1][ri], w1a, x01[rl]); ffma2(acc[1][ri], w1b, x23[rl]);
                    ffma2(acc[2][ri], w2a, x01[rl]); ffma2(acc[2][ri], w2b, x23[rl]);
                }
            }
        }
        for (int rl = 0; rl < nr; rl++) {
            float* gr = gi + (size_t)(rt + rl) * G3 + tid;
            gr[0]   = uns(acc[0][rl]);
            gr[256] = uns(acc[1][rl]);
            gr[512] = uns(acc[2][rl]);
        }
    }
}

// ---------------- doc recurrence: 8 warps, k-split halves, warp pair = 2 cols ----------------
__device__ void run_doc(int cb, const float* __restrict__ Whh, const float* __restrict__ bhh,
                        const float* __restrict__ gi, float* hb0, float* hb1,
                        unsigned* fl, unsigned fbase, float* ws, float* red, float* hst)
{
    int tid = threadIdx.x;
    int cbase = cb << 3;
    for (int idx = tid; idx < 6144; idx += 256) {
        int rl = idx >> 8, j = idx & 255;
        int gate = rl >> 3, cc = rl & 7;
        ws[idx] = __ldg(Whh + (size_t)(gate * Hn + cbase + cc) * Hn + j);
    }
    int wid = tid >> 5, lane = tid & 31;
    int khalf = wid >> 2, wl = wid & 3;
    int c0 = wl * 2, c1 = c0 + 1;
    int j0 = cbase + c0, j1 = cbase + c1;
    bool fin = (khalf == 0) && (lane < DTn);
    float br0 = 0.f, bz0 = 0.f, bn0 = 0.f, br1 = 0.f, bz1 = 0.f, bn1 = 0.f;
    if (khalf == 0) {
        br0 = __ldg(bhh + j0); bz0 = __ldg(bhh + Hn + j0); bn0 = __ldg(bhh + 2 * Hn + j0);
        br1 = __ldg(bhh + j1); bz1 = __ldg(bhh + Hn + j1); bn1 = __ldg(bhh + 2 * Hn + j1);
    }
    unsigned wsa = sptr(ws);
    unsigned kofs = (unsigned)khalf * 512;
    unsigned wA[6];
    #pragma unroll
    for (int g = 0; g < 3; g++) {
        wA[g * 2 + 0] = wsa + ((g * 8 + c0) << 10) + kofs;
        wA[g * 2 + 1] = wsa + ((g * 8 + c1) << 10) + kofs;
    }
    unsigned hA = sptr(hst) + (unsigned)lane * (HSTR * 4) + kofs;
    float* myred = red + (wl * 32 + lane) * 7;
    float* hb[2] = { hb0, hb1 };

    for (int t = 0; t < LD; t++) {
        const float4* hg = (const float4*)hb[t & 1];
        float* hn_ = hb[(t & 1) ^ 1];
        #pragma unroll
        for (int i = 0; i < 6; i++) {
            int idx = tid + (i << 8);
            int row = idx >> 6, col = idx & 63;
            float4 v = __ldcg(hg + idx);
            *(float4*)(hst + row * HSTR + (col << 2)) = v;
        }
        float g_r0 = 0.f, g_z0 = 0.f, g_n0 = 0.f, g_r1 = 0.f, g_z1 = 0.f, g_n1 = 0.f;
        if (fin) {
            const float* gib = gi + ((size_t)t * DTn + lane) * G3;
            g_r0 = __ldg(gib + j0); g_z0 = __ldg(gib + Hn + j0); g_n0 = __ldg(gib + 2 * Hn + j0);
            g_r1 = __ldg(gib + j1); g_z1 = __ldg(gib + Hn + j1); g_n1 = __ldg(gib + 2 * Hn + j1);
        }
        __syncthreads();
        u64 ar0 = pk(br0, 0.f), az0 = pk(bz0, 0.f), an0 = pk(bn0, 0.f);
        u64 ar1 = pk(br1, 0.f), az1 = pk(bz1, 0.f), an1 = pk(bn1, 0.f);
        #pragma unroll 4
        for (int jj = 0; jj < 32; jj++) {
            unsigned off = jj << 4;
            u64 h01, h23, w01, w23;
            lds2(h01, h23, hA + off);
            lds2(w01, w23, wA[0] + off);
            ffma2(ar0, w01, h01); ffma2(ar0, w23, h23);
            lds2(w01, w23, wA[1] + off);
            ffma2(ar1, w01, h01); ffma2(ar1, w23, h23);
            lds2(w01, w23, wA[2] + off);
            ffma2(az0, w01, h01); ffma2(az0, w23, h23);
            lds2(w01, w23, wA[3] + off);
            ffma2(az1, w01, h01); ffma2(az1, w23, h23);
            lds2(w01, w23, wA[4] + off);
            ffma2(an0, w01, h01); ffma2(an0, w23, h23);
            lds2(w01, w23, wA[5] + off);
            ffma2(an1, w01, h01); ffma2(an1, w23, h23);
        }
        if (khalf == 1) {
            myred[0] = uns(ar0); myred[1] = uns(ar1);
            myred[2] = uns(az0); myred[3] = uns(az1);
            myred[4] = uns(an0); myred[5] = uns(an1);
        }
        __syncthreads();
        if (fin) {
            float r0 = sigm(g_r0 + uns(ar0) + myred[0]);
            float r1 = sigm(g_r1 + uns(ar1) + myred[1]);
            float z0 = sigm(g_z0 + uns(az0) + myred[2]);
            float z1 = sigm(g_z1 + uns(az1) + myred[3]);
            float n0 = tanhf(g_n0 + r0 * (uns(an0) + myred[4]));
            float n1 = tanhf(g_n1 + r1 * (uns(an1) + myred[5]));
            float ho0 = hst[lane * HSTR + j0];
            float ho1 = hst[lane * HSTR + j1];
            hn_[(lane << 8) + j0] = (1.0f - z0) * n0 + z0 * ho0;
            hn_[(lane << 8) + j1] = (1.0f - z1) * n1 + z1 * ho1;
        }
        bar_arrive(fl, cb, fbase + t + 1);
        bar_wait(fl, 32, fbase + t + 1);
    }
}

// ---------------- term recurrence: 8 warps, k-split halves, 2 q-halves ----------------
__device__ void run_term(int cb, const float* __restrict__ Whh, const float* __restrict__ bhh,
                         unsigned* fl, unsigned fbase, float* ws, float* red, float* hst)
{
    int tid = threadIdx.x;
    int cbase = cb << 3;
    for (int idx = tid; idx < 6144; idx += 256) {
        int rl = idx >> 8, j = idx & 255;
        int gate = rl >> 3, cc = rl & 7;
        ws[idx] = __ldg(Whh + (size_t)(gate * Hn + cbase + cc) * Hn + j);
    }
    int wid = tid >> 5, lane = tid & 31;
    int khalf = wid >> 2, wl = wid & 3;
    int c0 = wl * 2, c1 = c0 + 1;
    int j0 = cbase + c0, j1 = cbase + c1;
    float br0 = 0.f, bz0 = 0.f, bn0 = 0.f, br1 = 0.f, bz1 = 0.f, bn1 = 0.f;
    if (khalf == 0) {
        br0 = __ldg(bhh + j0); bz0 = __ldg(bhh + Hn + j0); bn0 = __ldg(bhh + 2 * Hn + j0);
        br1 = __ldg(bhh + j1); bz1 = __ldg(bhh + Hn + j1); bn1 = __ldg(bhh + 2 * Hn + j1);
    }
    unsigned wsa = sptr(ws);
    unsigned kofs = (unsigned)khalf * 512;
    unsigned wA[6];
    #pragma unroll
    for (int g = 0; g < 3; g++) {
        wA[g * 2 + 0] = wsa + ((g * 8 + c0) << 10) + kofs;
        wA[g * 2 + 1] = wsa + ((g * 8 + c1) << 10) + kofs;
    }
    unsigned h0A = sptr(hst) + (unsigned)lane * (HSTR * 4) + kofs;
    unsigned h1A = sptr(hst) + (unsigned)(lane + 32) * (HSTR * 4) + kofs;
    float* myred = red + (wl * 32 + lane) * 13;

    for (int t = 0; t < LQ; t++) {
        const float4* hg = (const float4*)g_hq[t & 1];
        float* hn_ = g_hq[(t & 1) ^ 1];
        #pragma unroll
        for (int i = 0; i < 16; i++) {
            int idx = tid + (i << 8);
            int row = idx >> 6, col = idx & 63;
            float4 v = __ldcg(hg + idx);
            *(float4*)(hst + row * HSTR + (col << 2)) = v;
        }
        int q0 = lane, q1 = lane + 32;
        float gr00 = 0.f, gz00 = 0.f, gn00 = 0.f, gr01 = 0.f, gz01 = 0.f, gn01 = 0.f;
        float gr10 = 0.f, gz10 = 0.f, gn10 = 0.f, gr11 = 0.f, gz11 = 0.f, gn11 = 0.f;
        if (khalf == 0) {
            const float* gA = g_gi_q + ((size_t)t * Qn + q0) * G3;
            const float* gB = g_gi_q + ((size_t)t * Qn + q1) * G3;
            gr00 = __ldg(gA + j0); gz00 = __ldg(gA + Hn + j0); gn00 = __ldg(gA + 2 * Hn + j0);
            gr01 = __ldg(gA + j1); gz01 = __ldg(gA + Hn + j1); gn01 = __ldg(gA + 2 * Hn + j1);
            gr10 = __ldg(gB + j0); gz10 = __ldg(gB + Hn + j0); gn10 = __ldg(gB + 2 * Hn + j0);
            gr11 = __ldg(gB + j1); gz11 = __ldg(gB + Hn + j1); gn11 = __ldg(gB + 2 * Hn + j1);
        }
        __syncthreads();
        u64 ar00 = pk(br0, 0.f), az00 = pk(bz0, 0.f), an00 = pk(bn0, 0.f);
        u64 ar01 = pk(br1, 0.f), az01 = pk(bz1, 0.f), an01 = pk(bn1, 0.f);
        u64 ar10 = pk(br0, 0.f), az10 = pk(bz0, 0.f), an10 = pk(bn0, 0.f);
        u64 ar11 = pk(br1, 0.f), az11 = pk(bz1, 0.f), an11 = pk(bn1, 0.f);
        #pragma unroll 4
        for (int jj = 0; jj < 32; jj++) {
            unsigned off = jj << 4;
            u64 h0a, h0b, h1a, h1b, w01, w23;
            lds2(h0a, h0b, h0A + off);
            lds2(h1a, h1b, h1A + off);
            lds2(w01, w23, wA[0] + off);
            ffma2(ar00, w01, h0a); ffma2(ar00, w23, h0b);
            ffma2(ar10, w01, h1a); ffma2(ar10, w23, h1b);
            lds2(w01, w23, wA[1] + off);
            ffma2(ar01, w01, h0a); ffma2(ar01, w23, h0b);
            ffma2(ar11, w01, h1a); ffma2(ar11, w23, h1b);
            lds2(w01, w23, wA[2] + off);
            ffma2(az00, w01, h0a); ffma2(az00, w23, h0b);
            ffma2(az10, w01, h1a); ffma2(az10, w23, h1b);
            lds2(w01, w23, wA[3] + off);
            ffma2(az01, w01, h0a); ffma2(az01, w23, h0b);
            ffma2(az11, w01, h1a); ffma2(az11, w23, h1b);
            lds2(w01, w23, wA[4] + off);
            ffma2(an00, w01, h0a); ffma2(an00, w23, h0b);
            ffma2(an10, w01, h1a); ffma2(an10, w23, h1b);
            lds2(w01, w23, wA[5] + off);
            ffma2(an01, w01, h0a); ffma2(an01, w23, h0b);
            ffma2(an11, w01, h1a); ffma2(an11, w23, h1b);
        }
        if (khalf == 1) {
            myred[0]  = uns(ar00); myred[1]  = uns(ar01);
            myred[2]  = uns(az00); myred[3]  = uns(az01);
            myred[4]  = uns(an00); myred[5]  = uns(an01);
            myred[6]  = uns(ar10); myred[7]  = uns(ar11);
            myred[8]  = uns(az10); myred[9]  = uns(az11);
            myred[10] = uns(an10); myred[11] = uns(an11);
        }
        __syncthreads();
        if (khalf == 0) {
            float r, z, n, ho;
            r = sigm(gr00 + uns(ar00) + myred[0]);
            z = sigm(gz00 + uns(az00) + myred[2]);
            n = tanhf(gn00 + r * (uns(an00) + myred[4]));
            ho = hst[q0 * HSTR + j0];
            hn_[(q0 << 8) + j0] = (1.0f - z) * n + z * ho;
            r = sigm(gr01 + uns(ar01) + myred[1]);
            z = sigm(gz01 + uns(az01) + myred[3]);
            n = tanhf(gn01 + r * (uns(an01) + myred[5]));
            ho = hst[q0 * HSTR + j1];
            hn_[(q0 << 8) + j1] = (1.0f - z) * n + z * ho;
            r = sigm(gr10 + uns(ar10) + myred[6]);
            z = sigm(gz10 + uns(az10) + myred[8]);
            n = tanhf(gn10 + r * (uns(an10) + myred[10]));
            ho = hst[q1 * HSTR + j0];
            hn_[(q1 << 8) + j0] = (1.0f - z) * n + z * ho;
            r = sigm(gr11 + uns(ar11) + myred[7]);
            z = sigm(gz11 + uns(az11) + myred[9]);
            n = tanhf(gn11 + r * (uns(an11) + myred[11]));
            ho = hst[q1 * HSTR + j1];
            hn_[(q1 << 8) + j1] = (1.0f - z) * n + z * ho;
        }
        bar_arrive(fl, cb, fbase + t + 1);
        bar_wait(fl, 32, fbase + t + 1);
    }
}

// ---------------- persistent kernel ----------------
__global__ void __launch_bounds__(256, 1)
fmn_kernel(const int* __restrict__ q_tok, const int* __restrict__ p_tok, const int* __restrict__ n_tok,
           const float* __restrict__ term_emb, const float* __restrict__ term_Wih,
           const float* __restrict__ term_Whh, const float* __restrict__ term_bih,
           const float* __restrict__ term_bhh,
           const float* __restrict__ doc_emb,
           const float* __restrict__ dc_Wih, const float* __restrict__ dc_Whh,
           const float* __restrict__ dc_bih, const float* __restrict__ dc_bhh,
           const float* __restrict__ da_Wih, const float* __restrict__ da_Whh,
           const float* __restrict__ da_bih, const float* __restrict__ da_bhh,
           const float* __restrict__ pos_table, const float* __restrict__ posd_W,
           const float* __restrict__ posd_b,
           const float* __restrict__ qy_Wih, const float* __restrict__ qy_Whh,
           const float* __restrict__ qy_bih, const float* __restrict__ qy_bhh,
           float* __restrict__ out)
{
    __shared__ float ws[24 * 256];
    __shared__ float red[4 * 32 * 13];
    extern __shared__ float dyn[];
    int bid = blockIdx.x;
    int tid = threadIdx.x;
    unsigned ball = rd_base(g_f_all, bid);

    if (bid < 32) {                       // doc content GRU main
        int gid = bid;
        unsigned bp0 = rd_base(g_f_p0c, gid);
        unsigned brr = rd_base(g_f_rc, gid);
        if (gid == 0)
            for (int i = tid; i < DTn * Hn; i += 256) g_hc[0][i] = 0.0f;
        transpose_w(gid, dc_Wih, g_wt_c, dyn);
        bar_arrive(g_f_p0c, gid, bp0 + 1); bar_wait(g_f_p0c, NB_DOC, bp0 + 1);
        phase0_gemm(gid, NB_DOC, LD * DTn, 1, p_tok, n_tok, doc_emb, g_wt_c, dc_bih, g_gi_c, dyn);
        bar_arrive(g_f_p0c, gid, bp0 + 2); bar_wait(g_f_p0c, NB_DOC, bp0 + 2);
        run_doc(gid, dc_Whh, dc_bhh, g_gi_c, g_hc[0], g_hc[1], g_f_rc, brr, ws, red, dyn);
    } else if (bid < 64) {                // doc attention GRU main
        int gid = bid - 32;
        unsigned bp0 = rd_base(g_f_p0a, gid);
        unsigned brr = rd_base(g_f_ra, gid);
        if (gid == 0)
            for (int i = tid; i < DTn * Hn; i += 256) g_ha[0][i] = 0.0f;
        transpose_w(gid, da_Wih, g_wt_a, dyn);
        bar_arrive(g_f_p0a, gid, bp0 + 1); bar_wait(g_f_p0a, NB_DOC, bp0 + 1);
        phase0_gemm(gid, NB_DOC, LD * DTn, 1, p_tok, n_tok, doc_emb, g_wt_a, da_bih, g_gi_a, dyn);
        bar_arrive(g_f_p0a, gid, bp0 + 2); bar_wait(g_f_p0a, NB_DOC, bp0 + 2);
        run_doc(gid, da_Whh, da_bhh, g_gi_a, g_ha[0], g_ha[1], g_f_ra, brr, ws, red, dyn);
    } else if (bid < 96) {                // term GRU main
        int gid = bid - 64;
        unsigned bp0 = rd_base(g_f_p0t, gid);
        unsigned brr = rd_base(g_f_rt, gid);
        if (gid == 0)
            for (int i = tid; i < Qn * Hn; i += 256) g_hq[0][i] = 0.0f;
        transpose_w(gid, term_Wih, g_wt_q, dyn);
        bar_arrive(g_f_p0t, gid, bp0 + 1); bar_wait(g_f_p0t, NB_TRM, bp0 + 1);
        phase0_gemm(gid, NB_TRM, LQ * Qn, 0, q_tok, (const int*)0, term_emb, g_wt_q, term_bih, g_gi_q, dyn);
        bar_arrive(g_f_p0t, gid, bp0 + 2); bar_wait(g_f_p0t, NB_TRM, bp0 + 2);
        run_term(gid, term_Whh, term_bhh, g_f_rt, brr, ws, red, dyn);
    } else if (bid < 116) {               // doc-c phase0 helper
        int gid = bid - 96 + 32;
        unsigned bp0 = rd_base(g_f_p0c, gid);
        bar_arrive(g_f_p0c, gid, bp0 + 1); bar_wait(g_f_p0c, NB_DOC, bp0 + 1);
        phase0_gemm(gid, NB_DOC, LD * DTn, 1, p_tok, n_tok, doc_emb, g_wt_c, dc_bih, g_gi_c, dyn);
        bar_arrive(g_f_p0c, gid, bp0 + 2);
    } else if (bid < 136) {               // doc-a phase0 helper
        int gid = bid - 116 + 32;
        unsigned bp0 = rd_base(g_f_p0a, gid);
        bar_arrive(g_f_p0a, gid, bp0 + 1); bar_wait(g_f_p0a, NB_DOC, bp0 + 1);
        phase0_gemm(gid, NB_DOC, LD * DTn, 1, p_tok, n_tok, doc_emb, g_wt_a, da_bih, g_gi_a, dyn);
        bar_arrive(g_f_p0a, gid, bp0 + 2);
    } else {                              // term phase0 helper
        int gid = bid - 136 + 32;
        unsigned bp0 = rd_base(g_f_p0t, gid);
        bar_arrive(g_f_p0t, gid, bp0 + 1); bar_wait(g_f_p0t, NB_TRM, bp0 + 1);
        phase0_gemm(gid, NB_TRM, LQ * Qn, 0, q_tok, (const int*)0, term_emb, g_wt_q, term_bih, g_gi_q, dyn);
        bar_arrive(g_f_p0t, gid, bp0 + 2);
    }

    bar_arrive(g_f_all, bid, ball + 1); bar_wait(g_f_all, NBLK, ball + 1);

    // ---- phase A: position dense on content vectors (blocks 0..23) ----
    if (bid < DTn) {
        float* hrow = ws;
        hrow[tid] = __ldcg(&g_hc[0][bid * Hn + tid]);
        __syncthreads();
        int dset = bid % DSET;
        float pe0 = __ldg(&pos_table[dset * 4 + 0]);
        float pe1 = __ldg(&pos_table[dset * 4 + 1]);
        float pe2 = __ldg(&pos_table[dset * 4 + 2]);
        float pe3 = __ldg(&pos_table[dset * 4 + 3]);
        int j = tid;
        const float* wrow = posd_W + (size_t)j * (Hn + 4);
        unsigned xsa = sptr(hrow);
        u64 acc = pk(0.0f, 0.0f);
        #pragma unroll 4
        for (int ii = 0; ii < 64; ii++) {
            u64 w01, w23, x01, x23;
            ldg2(w01, w23, wrow + (ii << 2));
            lds2(x01, x23, xsa + (ii << 4));
            ffma2(acc, w01, x01);
            ffma2(acc, w23, x23);
        }
        float a = uns(acc);
        a = fmaf(pe0, __ldg(wrow + 256), a);
        a = fmaf(pe1, __ldg(wrow + 257), a);
        a = fmaf(pe2, __ldg(wrow + 258), a);
        a = fmaf(pe3, __ldg(wrow + 259), a);
        a += __ldg(&posd_b[j]);
        g_attc[bid * Hn + j] = a;
    } else if (bid >= 32 && bid < 96) {
        // ---- phase B: attention scores (blocks 32..95 -> q 0..63) ----
        int q = bid - 32;
        float* eq = ws;
        eq[tid] = __ldcg(&g_hq[0][q * Hn + tid]);
        __syncthreads();
        if (tid < DTn) {
            const float4* ap = (const float4*)(g_ha[0] + tid * Hn);
            const float4* e4 = (const float4*)eq;
            float acc = 0.0f;
            #pragma unroll 4
            for (int ii = 0; ii < 64; ii++) {
                float4 a4 = __ldcg(ap + ii);
                float4 x4 = e4[ii];
                acc = fmaf(a4.x, x4.x, acc);
                acc = fmaf(a4.y, x4.y, acc);
                acc = fmaf(a4.z, x4.z, acc);
                acc = fmaf(a4.w, x4.w, acc);
            }
            g_scores[q * DTn + tid] = acc;
        }
    }

    bar_arrive(g_f_all, bid, ball + 2); bar_wait(g_f_all, NBLK, ball + 2);

    // ---- phase C: softmax + memory read + final GRU step (blocks 0..63) ----
    if (bid < Qn) {
        int q = bid;
        float* sv = ws;
        float* wv = ws + 32;
        float* qs = ws + 64;
        if (tid < DTn) sv[tid] = __ldcg(&g_scores[q * DTn + tid]);
        __syncthreads();
        if (tid < 2) {
            int off = tid * DSET;
            float mx = -1e30f;
            for (int d2 = 0; d2 < DSET; d2++) mx = fmaxf(mx, sv[off + d2]);
            float s = 0.0f;
            for (int d2 = 0; d2 < DSET; d2++) {
                float e = __expf(sv[off + d2] - mx);
                wv[off + d2] = e;
                s += e;
            }
            float inv = 1.0f / s;
            for (int d2 = 0; d2 < DSET; d2++) wv[off + d2] *= inv;
        }
        __syncthreads();
        int j = tid;
        float val = __ldcg(&g_hq[0][q * Hn + j]);
        #pragma unroll
        for (int d2 = 0; d2 < DSET; d2++)
            val = fmaf(wv[d2], __ldcg(&g_attc[d2 * Hn + j]), val);
        #pragma unroll
        for (int d2 = 0; d2 < DSET; d2++)
            val = fmaf(wv[DSET + d2], __ldcg(&g_attc[(DSET + d2) * Hn + j]), val);
        qs[j] = val;
        __syncthreads();
        u64 dr = pk(0.0f, 0.0f), dz = pk(0.0f, 0.0f), dn = pk(0.0f, 0.0f);
        unsigned qsa = sptr(qs);
        const float* wr = qy_Wih + (size_t)j * Hn;
        const float* wz = qy_Wih + (size_t)(Hn + j) * Hn;
        const float* wn = qy_Wih + (size_t)(2 * Hn + j) * Hn;
        #pragma unroll 4
        for (int ii = 0; ii < 64; ii++) {
            u64 x01, x23, w01, w23;
            lds2(x01, x23, qsa + (ii << 4));
            ldg2(w01, w23, wr + (ii << 2));
            ffma2(dr, w01, x01); ffma2(dr, w23, x23);
            ldg2(w01, w23, wz + (ii << 2));
            ffma2(dz, w01, x01); ffma2(dz, w23, x23);
            ldg2(w01, w23, wn + (ii << 2));
            ffma2(dn, w01, x01); ffma2(dn, w23, x23);
        }
        float r = sigm(uns(dr) + __ldg(&qy_bih[j]) + __ldg(&qy_bhh[j]));
        float z = sigm(uns(dz) + __ldg(&qy_bih[Hn + j]) + __ldg(&qy_bhh[Hn + j]));
        float n = tanhf(uns(dn) + __ldg(&qy_bih[2 * Hn + j]) + r * __ldg(&qy_bhh[2 * Hn + j]));
        out[q * Hn + j] = (1.0f - z) * n;
    }
}

extern "C" void kernel_launch(void* const* d_in, const int* in_sizes, int n_in,
                              void* d_out, int out_size) {
    const int*   q_tok    = (const int*)d_in[0];
    const int*   p_tok    = (const int*)d_in[1];
    const int*   n_tok    = (const int*)d_in[2];
    const float* term_emb = (const float*)d_in[3];
    const float* term_Wih = (const float*)d_in[4];
    const float* term_Whh = (const float*)d_in[5];
    const float* term_bih = (const float*)d_in[6];
    const float* term_bhh = (const float*)d_in[7];
    const float* doc_emb  = (const float*)d_in[8];
    const float* dc_Wih   = (const float*)d_in[9];
    const float* dc_Whh   = (const float*)d_in[10];
    const float* dc_bih   = (const float*)d_in[11];
    const float* dc_bhh   = (const float*)d_in[12];
    const float* da_Wih   = (const float*)d_in[13];
    const float* da_Whh   = (const float*)d_in[14];
    const float* da_bih   = (const float*)d_in[15];
    const float* da_bhh   = (const float*)d_in[16];
    const float* pos_tab  = (const float*)d_in[17];
    const float* posd_W   = (const float*)d_in[18];
    const float* posd_b   = (const float*)d_in[19];
    const float* qy_Wih   = (const float*)d_in[20];
    const float* qy_Whh   = (const float*)d_in[21];
    const float* qy_bih   = (const float*)d_in[22];
    const float* qy_bhh   = (const float*)d_in[23];
    float* out = (float*)d_out;

    const int dyn_bytes = 64 * HSTR * 4;
    cudaFuncSetAttribute(fmn_kernel, cudaFuncAttributeMaxDynamicSharedMemorySize, dyn_bytes);
    fmn_kernel<<<NBLK, 256, dyn_bytes>>>(q_tok, p_tok, n_tok,
                            term_emb, term_Wih, term_Whh, term_bih, term_bhh,
                            doc_emb, dc_Wih, dc_Whh, dc_bih, dc_bhh,
                            da_Wih, da_Whh, da_bih, da_bhh,
                            pos_tab, posd_W, posd_b,
                            qy_Wih, qy_Whh, qy_bih, qy_bhh,
                            out);
}

// round 10
// speedup vs baseline: 3.9226x; 1.0096x over previous
#include <cuda_runtime.h>

typedef unsigned long long u64;

#define Qn   64
#define LQ   20
#define DSET 12
#define DTn  24
#define LD   50
#define Hn   256
#define G3   768
#define HSTR 260
#define NB_DOC 52   // real blocks on each doc phase0 (32 main + 20 helpers) -> 104 virtual
#define NB_TRM 40   // real blocks on term phase0 (32 main + 8 helpers) -> 80 virtual
#define NBLK 144
#define NTHR 512

// ---------------- device scratch ----------------
__device__ float g_gi_q[LQ * Qn * G3];
__device__ float g_gi_c[LD * DTn * G3];
__device__ float g_gi_a[LD * DTn * G3];
__device__ float4 g_wt_c[64 * G3];
__device__ float4 g_wt_a[64 * G3];
__device__ float4 g_wt_q[64 * G3];
__device__ float g_hq[2][Qn * Hn];
__device__ float g_hc[2][DTn * Hn];
__device__ float g_ha[2][DTn * Hn];
__device__ float g_attc[DTn * Hn];
__device__ float g_scores[Qn * DTn];
__device__ unsigned g_f_p0c[NB_DOC * 32];
__device__ unsigned g_f_p0a[NB_DOC * 32];
__device__ unsigned g_f_p0t[NB_TRM * 32];
__device__ unsigned g_f_rc[32 * 32];
__device__ unsigned g_f_ra[32 * 32];
__device__ unsigned g_f_rt[32 * 32];
__device__ unsigned g_f_all[NBLK * 32];

// ---------------- helpers ----------------
__device__ __forceinline__ float sigm(float x) { return 1.0f / (1.0f + __expf(-x)); }
__device__ __forceinline__ u64 pk(float lo, float hi) {
    u64 r; asm("mov.b64 %0, {%1,%2};" : "=l"(r) : "f"(lo), "f"(hi)); return r;
}
__device__ __forceinline__ float uns(u64 v) {
    float lo, hi; asm("mov.b64 {%0,%1}, %2;" : "=f"(lo), "=f"(hi) : "l"(v));
    return lo + hi;
}
__device__ __forceinline__ void ffma2(u64& d, u64 a, u64 b) {
    asm("fma.rn.f32x2 %0, %1, %2, %0;" : "+l"(d) : "l"(a), "l"(b));
}
__device__ __forceinline__ unsigned sptr(const void* p) {
    return (unsigned)__cvta_generic_to_shared(p);
}
__device__ __forceinline__ void lds2(u64& a, u64& b, unsigned addr) {
    asm volatile("ld.shared.v2.u64 {%0,%1}, [%2];" : "=l"(a), "=l"(b) : "r"(addr));
}
__device__ __forceinline__ void ldg2(u64& a, u64& b, const float* p) {
    asm volatile("ld.global.nc.v2.u64 {%0,%1}, [%2];" : "=l"(a), "=l"(b) : "l"(p));
}
// named barrier over one 256-thread half (id 1 or 2)
__device__ __forceinline__ void barh(int h) {
    asm volatile("bar.sync %0, %1;" :: "r"(1 + h), "r"(256) : "memory");
}

// ---- flag barrier ----
__device__ __forceinline__ void bar_arrive(unsigned* fl, int idx, unsigned gen) {
    __syncthreads();
    if (threadIdx.x == 0)
        asm volatile("st.release.gpu.global.u32 [%0], %1;"
                     :: "l"(fl + idx * 32), "r"(gen) : "memory");
}
__device__ __forceinline__ void bar_wait(unsigned* fl, int n, unsigned gen) {
    if (threadIdx.x < (unsigned)n) {
        unsigned cur;
        do {
            asm volatile("ld.acquire.gpu.global.u32 %0, [%1];"
                         : "=r"(cur) : "l"(fl + threadIdx.x * 32) : "memory");
        } while (cur < gen);
    }
    __syncthreads();
}
__device__ __forceinline__ unsigned rd_base(unsigned* fl, int idx) {
    return *(volatile unsigned*)(fl + idx * 32);
}

// ---------------- W transpose (512 threads) ----------------
__device__ void transpose_w(int gid, const float* __restrict__ W, float4* __restrict__ Wt,
                            float* sbuf)
{
    int tid = threadIdx.x;
    int r0 = gid * 24;
    for (int i = tid; i < 24 * 256; i += NTHR) {
        int rl = i >> 8, j = i & 255;
        sbuf[rl * 260 + j] = __ldg(W + (size_t)(r0 + rl) * Hn + j);
    }
    __syncthreads();
    for (int i = tid; i < 24 * 64; i += NTHR) {
        int rl = i % 24, kk = i / 24;
        float4 v = *(float4*)(sbuf + rl * 260 + (kk << 2));
        Wt[kk * G3 + r0 + rl] = v;
    }
    __syncthreads();
}

// ---------------- phase 0 (one 256-thread half = one virtual block) ----------------
__device__ void phase0_gemm(int vgid, int nv, int half, int R, int mode,
                            const int* __restrict__ tokA, const int* __restrict__ tokB,
                            const float* __restrict__ emb, const float4* __restrict__ Wt,
                            const float* __restrict__ bias, float* __restrict__ gi,
                            float* xs)
{
    int th = threadIdx.x & 255;
    int rpb = (R + nv - 1) / nv;
    int r0 = vgid * rpb;
    int r1 = min(R, r0 + rpb);
    unsigned xsa = sptr(xs);
    float b0 = __ldg(bias + th), b1 = __ldg(bias + th + 256), b2 = __ldg(bias + th + 512);

    for (int rt = r0; rt < r1; rt += 8) {
        int nr = min(8, r1 - rt);
        barh(half);
        for (int idx = th; idx < (nr << 8); idx += 256) {
            int rl = idx >> 8, j = idx & 255;
            int r = rt + rl;
            int tok;
            if (mode == 0) {
                int t = r >> 6, q = r & 63;
                tok = tokA[q * LQ + t];
            } else {
                int t = r / DTn, dt = r - t * DTn;
                tok = (dt < DSET) ? tokA[dt * LD + t] : tokB[(dt - DSET) * LD + t];
            }
            xs[(rl << 8) + j] = __ldg(emb + (size_t)tok * Hn + j);
        }
        barh(half);

        u64 acc[3][8];
        #pragma unroll
        for (int rl = 0; rl < 8; rl++) {
            acc[0][rl] = pk(b0, 0.0f);
            acc[1][rl] = pk(b1, 0.0f);
            acc[2][rl] = pk(b2, 0.0f);
        }
        #pragma unroll 2
        for (int jj = 0; jj < 64; jj++) {
            const float* wp = (const float*)(Wt + jj * G3 + th);
            u64 w0a, w0b, w1a, w1b, w2a, w2b;
            ldg2(w0a, w0b, wp);
            ldg2(w1a, w1b, wp + 1024);
            ldg2(w2a, w2b, wp + 2048);
            unsigned xo = xsa + (jj << 4);
            #pragma unroll
            for (int rlb = 0; rlb < 2; rlb++) {
                u64 x01[4], x23[4];
                #pragma unroll
                for (int rl = 0; rl < 4; rl++)
                    lds2(x01[rl], x23[rl], xo + ((rlb * 4 + rl) << 10));
                #pragma unroll
                for (int rl = 0; rl < 4; rl++) {
                    int ri = rlb * 4 + rl;
                    ffma2(acc[0][ri], w0a, x01[rl]); ffma2(acc[0][ri], w0b, x23[rl]);
                    ffma2(acc[1][ri], w1a, x01[rl]); ffma2(acc[1][ri], w1b, x23[rl]);
                    ffma2(acc[2][ri], w2a, x01[rl]); ffma2(acc[2][ri], w2b, x23[rl]);
                }
            }
        }
        for (int rl = 0; rl < nr; rl++) {
            float* gr = gi + (size_t)(rt + rl) * G3 + th;
            gr[0]   = uns(acc[0][rl]);
            gr[256] = uns(acc[1][rl]);
            gr[512] = uns(acc[2][rl]);
        }
    }
}

// ---------------- doc recurrence: 16 warps, k-quarter split ----------------
__device__ void run_doc(int cb, const float* __restrict__ Whh, const float* __restrict__ bhh,
                        const float* __restrict__ gi, float* hb0, float* hb1,
                        unsigned* fl, unsigned fbase, float* ws, float* red, float* hst)
{
    int tid = threadIdx.x;
    int cbase = cb << 3;
    for (int idx = tid; idx < 6144; idx += NTHR) {
        int rl = idx >> 8, j = idx & 255;
        int gate = rl >> 3, cc = rl & 7;
        ws[idx] = __ldg(Whh + (size_t)(gate * Hn + cbase + cc) * Hn + j);
    }
    int wid = tid >> 5, lane = tid & 31;
    int kq = wid >> 2, wl = wid & 3;
    int c0 = wl * 2, c1 = c0 + 1;
    int j0 = cbase + c0, j1 = cbase + c1;
    bool fin = (kq == 0) && (lane < DTn);
    float br0 = 0.f, bz0 = 0.f, bn0 = 0.f, br1 = 0.f, bz1 = 0.f, bn1 = 0.f;
    if (kq == 0) {
        br0 = __ldg(bhh + j0); bz0 = __ldg(bhh + Hn + j0); bn0 = __ldg(bhh + 2 * Hn + j0);
        br1 = __ldg(bhh + j1); bz1 = __ldg(bhh + Hn + j1); bn1 = __ldg(bhh + 2 * Hn + j1);
    }
    unsigned wsa = sptr(ws);
    unsigned kofs = (unsigned)kq * 256;    // 64 floats
    unsigned wA[6];
    #pragma unroll
    for (int g = 0; g < 3; g++) {
        wA[g * 2 + 0] = wsa + ((g * 8 + c0) << 10) + kofs;
        wA[g * 2 + 1] = wsa + ((g * 8 + c1) << 10) + kofs;
    }
    unsigned hA = sptr(hst) + (unsigned)lane * (HSTR * 4) + kofs;
    float* myred = red + (wl * 32 + lane) * 7;   // partials land at [p*128*7 ...]
    float* hb[2] = { hb0, hb1 };

    for (int t = 0; t < LD; t++) {
        const float4* hg = (const float4*)hb[t & 1];
        float* hn_ = hb[(t & 1) ^ 1];
        #pragma unroll
        for (int i = 0; i < 3; i++) {
            int idx = tid + (i << 9);          // < 1536 float4
            int row = idx >> 6, col = idx & 63;
            float4 v = __ldcg(hg + idx);
            *(float4*)(hst + row * HSTR + (col << 2)) = v;
        }
        float g_r0 = 0.f, g_z0 = 0.f, g_n0 = 0.f, g_r1 = 0.f, g_z1 = 0.f, g_n1 = 0.f;
        if (fin) {
            const float* gib = gi + ((size_t)t * DTn + lane) * G3;
            g_r0 = __ldg(gib + j0); g_z0 = __ldg(gib + Hn + j0); g_n0 = __ldg(gib + 2 * Hn + j0);
            g_r1 = __ldg(gib + j1); g_z1 = __ldg(gib + Hn + j1); g_n1 = __ldg(gib + 2 * Hn + j1);
        }
        __syncthreads();
        u64 ar0 = pk(br0, 0.f), az0 = pk(bz0, 0.f), an0 = pk(bn0, 0.f);
        u64 ar1 = pk(br1, 0.f), az1 = pk(bz1, 0.f), an1 = pk(bn1, 0.f);
        #pragma unroll 4
        for (int jj = 0; jj < 16; jj++) {
            unsigned off = jj << 4;
            u64 h01, h23, w01, w23;
            lds2(h01, h23, hA + off);
            lds2(w01, w23, wA[0] + off);
            ffma2(ar0, w01, h01); ffma2(ar0, w23, h23);
            lds2(w01, w23, wA[1] + off);
            ffma2(ar1, w01, h01); ffma2(ar1, w23, h23);
            lds2(w01, w23, wA[2] + off);
            ffma2(az0, w01, h01); ffma2(az0, w23, h23);
            lds2(w01, w23, wA[3] + off);
            ffma2(az1, w01, h01); ffma2(az1, w23, h23);
            lds2(w01, w23, wA[4] + off);
            ffma2(an0, w01, h01); ffma2(an0, w23, h23);
            lds2(w01, w23, wA[5] + off);
            ffma2(an1, w01, h01); ffma2(an1, w23, h23);
        }
        if (kq > 0) {
            float* rp = myred + (kq - 1) * (128 * 7);
            rp[0] = uns(ar0); rp[1] = uns(ar1);
            rp[2] = uns(az0); rp[3] = uns(az1);
            rp[4] = uns(an0); rp[5] = uns(an1);
        }
        __syncthreads();
        if (fin) {
            float sr0 = uns(ar0), sr1 = uns(ar1);
            float sz0 = uns(az0), sz1 = uns(az1);
            float sn0 = uns(an0), sn1 = uns(an1);
            #pragma unroll
            for (int p = 0; p < 3; p++) {
                float* rp = myred + p * (128 * 7);
                sr0 += rp[0]; sr1 += rp[1];
                sz0 += rp[2]; sz1 += rp[3];
                sn0 += rp[4]; sn1 += rp[5];
            }
            float r0 = sigm(g_r0 + sr0);
            float r1 = sigm(g_r1 + sr1);
            float z0 = sigm(g_z0 + sz0);
            float z1 = sigm(g_z1 + sz1);
            float n0 = tanhf(g_n0 + r0 * sn0);
            float n1 = tanhf(g_n1 + r1 * sn1);
            float ho0 = hst[lane * HSTR + j0];
            float ho1 = hst[lane * HSTR + j1];
            hn_[(lane << 8) + j0] = (1.0f - z0) * n0 + z0 * ho0;
            hn_[(lane << 8) + j1] = (1.0f - z1) * n1 + z1 * ho1;
        }
        bar_arrive(fl, cb, fbase + t + 1);
        bar_wait(fl, 32, fbase + t + 1);
    }
}

// ---------------- term recurrence: 16 warps, k-quarter split, 2 q-halves ----------------
__device__ void run_term(int cb, const float* __restrict__ Whh, const float* __restrict__ bhh,
                         unsigned* fl, unsigned fbase, float* ws, float* red, float* hst)
{
    int tid = threadIdx.x;
    int cbase = cb << 3;
    for (int idx = tid; idx < 6144; idx += NTHR) {
        int rl = idx >> 8, j = idx & 255;
        int gate = rl >> 3, cc = rl & 7;
        ws[idx] = __ldg(Whh + (size_t)(gate * Hn + cbase + cc) * Hn + j);
    }
    int wid = tid >> 5, lane = tid & 31;
    int kq = wid >> 2, wl = wid & 3;
    int c0 = wl * 2, c1 = c0 + 1;
    int j0 = cbase + c0, j1 = cbase + c1;
    float br0 = 0.f, bz0 = 0.f, bn0 = 0.f, br1 = 0.f, bz1 = 0.f, bn1 = 0.f;
    if (kq == 0) {
        br0 = __ldg(bhh + j0); bz0 = __ldg(bhh + Hn + j0); bn0 = __ldg(bhh + 2 * Hn + j0);
        br1 = __ldg(bhh + j1); bz1 = __ldg(bhh + Hn + j1); bn1 = __ldg(bhh + 2 * Hn + j1);
    }
    unsigned wsa = sptr(ws);
    unsigned kofs = (unsigned)kq * 256;
    unsigned wA[6];
    #pragma unroll
    for (int g = 0; g < 3; g++) {
        wA[g * 2 + 0] = wsa + ((g * 8 + c0) << 10) + kofs;
        wA[g * 2 + 1] = wsa + ((g * 8 + c1) << 10) + kofs;
    }
    unsigned h0A = sptr(hst) + (unsigned)lane * (HSTR * 4) + kofs;
    unsigned h1A = sptr(hst) + (unsigned)(lane + 32) * (HSTR * 4) + kofs;
    float* myred = red + (wl * 32 + lane) * 13;

    for (int t = 0; t < LQ; t++) {
        const float4* hg = (const float4*)g_hq[t & 1];
        float* hn_ = g_hq[(t & 1) ^ 1];
        #pragma unroll
        for (int i = 0; i < 8; i++) {
            int idx = tid + (i << 9);          // < 4096 float4
            int row = idx >> 6, col = idx & 63;
            float4 v = __ldcg(hg + idx);
            *(float4*)(hst + row * HSTR + (col << 2)) = v;
        }
        int q0 = lane, q1 = lane + 32;
        float gr00 = 0.f, gz00 = 0.f, gn00 = 0.f, gr01 = 0.f, gz01 = 0.f, gn01 = 0.f;
        float gr10 = 0.f, gz10 = 0.f, gn10 = 0.f, gr11 = 0.f, gz11 = 0.f, gn11 = 0.f;
        if (kq == 0) {
            const float* gA = g_gi_q + ((size_t)t * Qn + q0) * G3;
            const float* gB = g_gi_q + ((size_t)t * Qn + q1) * G3;
            gr00 = __ldg(gA + j0); gz00 = __ldg(gA + Hn + j0); gn00 = __ldg(gA + 2 * Hn + j0);
            gr01 = __ldg(gA + j1); gz01 = __ldg(gA + Hn + j1); gn01 = __ldg(gA + 2 * Hn + j1);
            gr10 = __ldg(gB + j0); gz10 = __ldg(gB + Hn + j0); gn10 = __ldg(gB + 2 * Hn + j0);
            gr11 = __ldg(gB + j1); gz11 = __ldg(gB + Hn + j1); gn11 = __ldg(gB + 2 * Hn + j1);
        }
        __syncthreads();
        u64 ar00 = pk(br0, 0.f), az00 = pk(bz0, 0.f), an00 = pk(bn0, 0.f);
        u64 ar01 = pk(br1, 0.f), az01 = pk(bz1, 0.f), an01 = pk(bn1, 0.f);
        u64 ar10 = pk(br0, 0.f), az10 = pk(bz0, 0.f), an10 = pk(bn0, 0.f);
        u64 ar11 = pk(br1, 0.f), az11 = pk(bz1, 0.f), an11 = pk(bn1, 0.f);
        #pragma unroll 4
        for (int jj = 0; jj < 16; jj++) {
            unsigned off = jj << 4;
            u64 h0a, h0b, h1a, h1b, w01, w23;
            lds2(h0a, h0b, h0A + off);
            lds2(h1a, h1b, h1A + off);
            lds2(w01, w23, wA[0] + off);
            ffma2(ar00, w01, h0a); ffma2(ar00, w23, h0b);
            ffma2(ar10, w01, h1a); ffma2(ar10, w23, h1b);
            lds2(w01, w23, wA[1] + off);
            ffma2(ar01, w01, h0a); ffma2(ar01, w23, h0b);
            ffma2(ar11, w01, h1a); ffma2(ar11, w23, h1b);
            lds2(w01, w23, wA[2] + off);
            ffma2(az00, w01, h0a); ffma2(az00, w23, h0b);
            ffma2(az10, w01, h1a); ffma2(az10, w23, h1b);
            lds2(w01, w23, wA[3] + off);
            ffma2(az01, w01, h0a); ffma2(az01, w23, h0b);
            ffma2(az11, w01, h1a); ffma2(az11, w23, h1b);
            lds2(w01, w23, wA[4] + off);
            ffma2(an00, w01, h0a); ffma2(an00, w23, h0b);
            ffma2(an10, w01, h1a); ffma2(an10, w23, h1b);
            lds2(w01, w23, wA[5] + off);
            ffma2(an01, w01, h0a); ffma2(an01, w23, h0b);
            ffma2(an11, w01, h1a); ffma2(an11, w23, h1b);
        }
        if (kq > 0) {
            float* rp = myred + (kq - 1) * (128 * 13);
            rp[0]  = uns(ar00); rp[1]  = uns(ar01);
            rp[2]  = uns(az00); rp[3]  = uns(az01);
            rp[4]  = uns(an00); rp[5]  = uns(an01);
            rp[6]  = uns(ar10); rp[7]  = uns(ar11);
            rp[8]  = uns(az10); rp[9]  = uns(az11);
            rp[10] = uns(an10); rp[11] = uns(an11);
        }
        __syncthreads();
        if (kq == 0) {
            float s[12];
            s[0] = uns(ar00); s[1] = uns(ar01); s[2] = uns(az00); s[3] = uns(az01);
            s[4] = uns(an00); s[5] = uns(an01); s[6] = uns(ar10); s[7] = uns(ar11);
            s[8] = uns(az10); s[9] = uns(az11); s[10] = uns(an10); s[11] = uns(an11);
            #pragma unroll
            for (int p = 0; p < 3; p++) {
                float* rp = myred + p * (128 * 13);
                #pragma unroll
                for (int v = 0; v < 12; v++) s[v] += rp[v];
            }
            float r, z, n, ho;
            r = sigm(gr00 + s[0]);
            z = sigm(gz00 + s[2]);
            n = tanhf(gn00 + r * s[4]);
            ho = hst[q0 * HSTR + j0];
            hn_[(q0 << 8) + j0] = (1.0f - z) * n + z * ho;
            r = sigm(gr01 + s[1]);
            z = sigm(gz01 + s[3]);
            n = tanhf(gn01 + r * s[5]);
            ho = hst[q0 * HSTR + j1];
            hn_[(q0 << 8) + j1] = (1.0f - z) * n + z * ho;
            r = sigm(gr10 + s[6]);
            z = sigm(gz10 + s[8]);
            n = tanhf(gn10 + r * s[10]);
            ho = hst[q1 * HSTR + j0];
            hn_[(q1 << 8) + j0] = (1.0f - z) * n + z * ho;
            r = sigm(gr11 + s[7]);
            z = sigm(gz11 + s[9]);
            n = tanhf(gn11 + r * s[11]);
            ho = hst[q1 * HSTR + j1];
            hn_[(q1 << 8) + j1] = (1.0f - z) * n + z * ho;
        }
        bar_arrive(fl, cb, fbase + t + 1);
        bar_wait(fl, 32, fbase + t + 1);
    }
}

// ---------------- persistent kernel ----------------
__global__ void __launch_bounds__(NTHR, 1)
fmn_kernel(const int* __restrict__ q_tok, const int* __restrict__ p_tok, const int* __restrict__ n_tok,
           const float* __restrict__ term_emb, const float* __restrict__ term_Wih,
           const float* __restrict__ term_Whh, const float* __restrict__ term_bih,
           const float* __restrict__ term_bhh,
           const float* __restrict__ doc_emb,
           const float* __restrict__ dc_Wih, const float* __restrict__ dc_Whh,
           const float* __restrict__ dc_bih, const float* __restrict__ dc_bhh,
           const float* __restrict__ da_Wih, const float* __restrict__ da_Whh,
           const float* __restrict__ da_bih, const float* __restrict__ da_bhh,
           const float* __restrict__ pos_table, const float* __restrict__ posd_W,
           const float* __restrict__ posd_b,
           const float* __restrict__ qy_Wih, const float* __restrict__ qy_Whh,
           const float* __restrict__ qy_bih, const float* __restrict__ qy_bhh,
           float* __restrict__ out)
{
    __shared__ float ws[24 * 256];
    __shared__ float red[3 * 128 * 13];
    extern __shared__ float dyn[];
    int bid = blockIdx.x;
    int tid = threadIdx.x;
    int half = tid >> 8;                   // 0/1: phase0 virtual half
    unsigned ball = rd_base(g_f_all, bid);

    if (bid < 32) {
        int gid = bid;
        unsigned bp0 = rd_base(g_f_p0c, gid);
        unsigned brr = rd_base(g_f_rc, gid);
        if (gid == 0)
            for (int i = tid; i < DTn * Hn; i += NTHR) g_hc[0][i] = 0.0f;
        transpose_w(gid, dc_Wih, g_wt_c, dyn);
        bar_arrive(g_f_p0c, gid, bp0 + 1); bar_wait(g_f_p0c, NB_DOC, bp0 + 1);
        phase0_gemm(gid * 2 + half, NB_DOC * 2, half, LD * DTn, 1, p_tok, n_tok,
                    doc_emb, g_wt_c, dc_bih, g_gi_c, dyn + half * 2048);
        bar_arrive(g_f_p0c, gid, bp0 + 2); bar_wait(g_f_p0c, NB_DOC, bp0 + 2);
        run_doc(gid, dc_Whh, dc_bhh, g_gi_c, g_hc[0], g_hc[1], g_f_rc, brr, ws, red, dyn);
    } else if (bid < 64) {
        int gid = bid - 32;
        unsigned bp0 = rd_base(g_f_p0a, gid);
        unsigned brr = rd_base(g_f_ra, gid);
        if (gid == 0)
            for (int i = tid; i < DTn * Hn; i += NTHR) g_ha[0][i] = 0.0f;
        transpose_w(gid, da_Wih, g_wt_a, dyn);
        bar_arrive(g_f_p0a, gid, bp0 + 1); bar_wait(g_f_p0a, NB_DOC, bp0 + 1);
        phase0_gemm(gid * 2 + half, NB_DOC * 2, half, LD * DTn, 1, p_tok, n_tok,
                    doc_emb, g_wt_a, da_bih, g_gi_a, dyn + half * 2048);
        bar_arrive(g_f_p0a, gid, bp0 + 2); bar_wait(g_f_p0a, NB_DOC, bp0 + 2);
        run_doc(gid, da_Whh, da_bhh, g_gi_a, g_ha[0], g_ha[1], g_f_ra, brr, ws, red, dyn);
    } else if (bid < 96) {
        int gid = bid - 64;
        unsigned bp0 = rd_base(g_f_p0t, gid);
        unsigned brr = rd_base(g_f_rt, gid);
        if (gid == 0)
            for (int i = tid; i < Qn * Hn; i += NTHR) g_hq[0][i] = 0.0f;
        transpose_w(gid, term_Wih, g_wt_q, dyn);
        bar_arrive(g_f_p0t, gid, bp0 + 1); bar_wait(g_f_p0t, NB_TRM, bp0 + 1);
        phase0_gemm(gid * 2 + half, NB_TRM * 2, half, LQ * Qn, 0, q_tok, (const int*)0,
                    term_emb, g_wt_q, term_bih, g_gi_q, dyn + half * 2048);
        bar_arrive(g_f_p0t, gid, bp0 + 2); bar_wait(g_f_p0t, NB_TRM, bp0 + 2);
        run_term(gid, term_Whh, term_bhh, g_f_rt, brr, ws, red, dyn);
    } else if (bid < 116) {
        int gid = bid - 96 + 32;
        unsigned bp0 = rd_base(g_f_p0c, gid);
        bar_arrive(g_f_p0c, gid, bp0 + 1); bar_wait(g_f_p0c, NB_DOC, bp0 + 1);
        phase0_gemm(gid * 2 + half, NB_DOC * 2, half, LD * DTn, 1, p_tok, n_tok,
                    doc_emb, g_wt_c, dc_bih, g_gi_c, dyn + half * 2048);
        bar_arrive(g_f_p0c, gid, bp0 + 2);
    } else if (bid < 136) {
        int gid = bid - 116 + 32;
        unsigned bp0 = rd_base(g_f_p0a, gid);
        bar_arrive(g_f_p0a, gid, bp0 + 1); bar_wait(g_f_p0a, NB_DOC, bp0 + 1);
        phase0_gemm(gid * 2 + half, NB_DOC * 2, half, LD * DTn, 1, p_tok, n_tok,
                    doc_emb, g_wt_a, da_bih, g_gi_a, dyn + half * 2048);
        bar_arrive(g_f_p0a, gid, bp0 + 2);
    } else {
        int gid = bid - 136 + 32;
        unsigned bp0 = rd_base(g_f_p0t, gid);
        bar_arrive(g_f_p0t, gid, bp0 + 1); bar_wait(g_f_p0t, NB_TRM, bp0 + 1);
        phase0_gemm(gid * 2 + half, NB_TRM * 2, half, LQ * Qn, 0, q_tok, (const int*)0,
                    term_emb, g_wt_q, term_bih, g_gi_q, dyn + half * 2048);
        bar_arrive(g_f_p0t, gid, bp0 + 2);
    }

    bar_arrive(g_f_all, bid, ball + 1); bar_wait(g_f_all, NBLK, ball + 1);

    // ---- phase A: position dense (blocks 0..23; threads 0..255 active) ----
    if (bid < DTn) {
        float* hrow = ws;
        if (tid < 256) hrow[tid] = __ldcg(&g_hc[0][bid * Hn + tid]);
        __syncthreads();
        if (tid < 256) {
            int dset = bid % DSET;
            float pe0 = __ldg(&pos_table[dset * 4 + 0]);
            float pe1 = __ldg(&pos_table[dset * 4 + 1]);
            float pe2 = __ldg(&pos_table[dset * 4 + 2]);
            float pe3 = __ldg(&pos_table[dset * 4 + 3]);
            int j = tid;
            const float* wrow = posd_W + (size_t)j * (Hn + 4);
            unsigned xsa = sptr(hrow);
            u64 acc = pk(0.0f, 0.0f);
            #pragma unroll 4
            for (int ii = 0; ii < 64; ii++) {
                u64 w01, w23, x01, x23;
                ldg2(w01, w23, wrow + (ii << 2));
                lds2(x01, x23, xsa + (ii << 4));
                ffma2(acc, w01, x01);
                ffma2(acc, w23, x23);
            }
            float a = uns(acc);
            a = fmaf(pe0, __ldg(wrow + 256), a);
            a = fmaf(pe1, __ldg(wrow + 257), a);
            a = fmaf(pe2, __ldg(wrow + 258), a);
            a = fmaf(pe3, __ldg(wrow + 259), a);
            a += __ldg(&posd_b[j]);
            g_attc[bid * Hn + j] = a;
        }
    } else if (bid >= 32 && bid < 96) {
        // ---- phase B: attention scores ----
        int q = bid - 32;
        float* eq = ws;
        if (tid < 256) eq[tid] = __ldcg(&g_hq[0][q * Hn + tid]);
        __syncthreads();
        if (tid < DTn) {
            const float4* ap = (const float4*)(g_ha[0] + tid * Hn);
            const float4* e4 = (const float4*)eq;
            float acc = 0.0f;
            #pragma unroll 4
            for (int ii = 0; ii < 64; ii++) {
                float4 a4 = __ldcg(ap + ii);
                float4 x4 = e4[ii];
                acc = fmaf(a4.x, x4.x, acc);
                acc = fmaf(a4.y, x4.y, acc);
                acc = fmaf(a4.z, x4.z, acc);
                acc = fmaf(a4.w, x4.w, acc);
            }
            g_scores[q * DTn + tid] = acc;
        }
    }

    bar_arrive(g_f_all, bid, ball + 2); bar_wait(g_f_all, NBLK, ball + 2);

    // ---- phase C: softmax + memory read + final GRU (blocks 0..63) ----
    if (bid < Qn) {
        int q = bid;
        float* sv = ws;
        float* wv = ws + 32;
        float* qs = ws + 64;
        if (tid < DTn) sv[tid] = __ldcg(&g_scores[q * DTn + tid]);
        __syncthreads();
        if (tid < 2) {
            int off = tid * DSET;
            float mx = -1e30f;
            for (int d2 = 0; d2 < DSET; d2++) mx = fmaxf(mx, sv[off + d2]);
            float s = 0.0f;
            for (int d2 = 0; d2 < DSET; d2++) {
                float e = __expf(sv[off + d2] - mx);
                wv[off + d2] = e;
                s += e;
            }
            float inv = 1.0f / s;
            for (int d2 = 0; d2 < DSET; d2++) wv[off + d2] *= inv;
        }
        __syncthreads();
        if (tid < 256) {
            int j = tid;
            float val = __ldcg(&g_hq[0][q * Hn + j]);
            #pragma unroll
            for (int d2 = 0; d2 < DSET; d2++)
                val = fmaf(wv[d2], __ldcg(&g_attc[d2 * Hn + j]), val);
            #pragma unroll
            for (int d2 = 0; d2 < DSET; d2++)
                val = fmaf(wv[DSET + d2], __ldcg(&g_attc[(DSET + d2) * Hn + j]), val);
            qs[j] = val;
        }
        __syncthreads();
        if (tid < 256) {
            int j = tid;
            u64 dr = pk(0.0f, 0.0f), dz = pk(0.0f, 0.0f), dn = pk(0.0f, 0.0f);
            unsigned qsa = sptr(qs);
            const float* wr = qy_Wih + (size_t)j * Hn;
            const float* wz = qy_Wih + (size_t)(Hn + j) * Hn;
            const float* wn = qy_Wih + (size_t)(2 * Hn + j) * Hn;
            #pragma unroll 4
            for (int ii = 0; ii < 64; ii++) {
                u64 x01, x23, w01, w23;
                lds2(x01, x23, qsa + (ii << 4));
                ldg2(w01, w23, wr + (ii << 2));
                ffma2(dr, w01, x01); ffma2(dr, w23, x23);
                ldg2(w01, w23, wz + (ii << 2));
                ffma2(dz, w01, x01); ffma2(dz, w23, x23);
                ldg2(w01, w23, wn + (ii << 2));
                ffma2(dn, w01, x01); ffma2(dn, w23, x23);
            }
            float r = sigm(uns(dr) + __ldg(&qy_bih[j]) + __ldg(&qy_bhh[j]));
            float z = sigm(uns(dz) + __ldg(&qy_bih[Hn + j]) + __ldg(&qy_bhh[Hn + j]));
            float n = tanhf(uns(dn) + __ldg(&qy_bih[2 * Hn + j]) + r * __ldg(&qy_bhh[2 * Hn + j]));
            out[q * Hn + j] = (1.0f - z) * n;
        }
    }
}

extern "C" void kernel_launch(void* const* d_in, const int* in_sizes, int n_in,
                              void* d_out, int out_size) {
    const int*   q_tok    = (const int*)d_in[0];
    const int*   p_tok    = (const int*)d_in[1];
    const int*   n_tok    = (const int*)d_in[2];
    const float* term_emb = (const float*)d_in[3];
    const float* term_Wih = (const float*)d_in[4];
    const float* term_Whh = (const float*)d_in[5];
    const float* term_bih = (const float*)d_in[6];
    const float* term_bhh = (const float*)d_in[7];
    const float* doc_emb  = (const float*)d_in[8];
    const float* dc_Wih   = (const float*)d_in[9];
    const float* dc_Whh   = (const float*)d_in[10];
    const float* dc_bih   = (const float*)d_in[11];
    const float* dc_bhh   = (const float*)d_in[12];
    const float* da_Wih   = (const float*)d_in[13];
    const float* da_Whh   = (const float*)d_in[14];
    const float* da_bih   = (const float*)d_in[15];
    const float* da_bhh   = (const float*)d_in[16];
    const float* pos_tab  = (const float*)d_in[17];
    const float* posd_W   = (const float*)d_in[18];
    const float* posd_b   = (const float*)d_in[19];
    const float* qy_Wih   = (const float*)d_in[20];
    const float* qy_Whh   = (const float*)d_in[21];
    const float* qy_bih   = (const float*)d_in[22];
    const float* qy_bhh   = (const float*)d_in[23];
    float* out = (float*)d_out;

    const int dyn_bytes = 64 * HSTR * 4;   // 66560: term h stage / transpose buf / 2x phase0 xs
    cudaFuncSetAttribute(fmn_kernel, cudaFuncAttributeMaxDynamicSharedMemorySize, dyn_bytes);
    fmn_kernel<<<NBLK, NTHR, dyn_bytes>>>(q_tok, p_tok, n_tok,
                            term_emb, term_Wih, term_Whh, term_bih, term_bhh,
                            doc_emb, dc_Wih, dc_Whh, dc_bih, dc_bhh,
                            da_Wih, da_Whh, da_bih, da_bhh,
                            pos_tab, posd_W, posd_b,
                            qy_Wih, qy_Whh, qy_bih, qy_bhh,
                            out);
}